// round 1
// baseline (speedup 1.0000x reference)
#include <cuda_runtime.h>
#include <cstdint>
#include <cstddef>

#define NSEQ 512
#define DDIM 128
#define NN   (NSEQ*NSEQ)   // 262144 rows

typedef unsigned long long ull;

// Scratch (device globals: allocation-free).
// g_a[d][r], g_b[d][r] with r = i*512 + k ; g_t[d][r] with r = i*512 + j
static __device__ float g_a[(size_t)DDIM * NN];
static __device__ float g_b[(size_t)DDIM * NN];
static __device__ float g_t[(size_t)DDIM * NN];

// ---------------- packed f32x2 helpers (Blackwell FFMA2) ----------------
__device__ __forceinline__ ull pk2(float a, float b) {
    ull r; asm("mov.b64 %0, {%1, %2};" : "=l"(r) : "f"(a), "f"(b)); return r;
}
__device__ __forceinline__ ull dup2(float a) {
    ull r; asm("mov.b64 %0, {%1, %1};" : "=l"(r) : "f"(a)); return r;
}
__device__ __forceinline__ void fma2(ull& c, ull a, ull b) {
    asm("fma.rn.f32x2 %0, %1, %2, %0;" : "+l"(c) : "l"(a), "l"(b));
}
__device__ __forceinline__ float2 unpk(ull v) {
    float2 r; asm("mov.b64 {%0, %1}, %2;" : "=f"(r.x), "=f"(r.y) : "l"(v)); return r;
}
__device__ __forceinline__ float sigmoidf_(float x) { return 1.0f / (1.0f + __expf(-x)); }

// LayerNorm of one logical row stored as a column: s[(d)*132 + row], d = 0..127.
// One warp per row.
__device__ __forceinline__ void ln_col(float* s, int row, int lane) {
    float x0 = s[(lane      )*132 + row];
    float x1 = s[(lane + 32 )*132 + row];
    float x2 = s[(lane + 64 )*132 + row];
    float x3 = s[(lane + 96 )*132 + row];
    float sum = x0 + x1 + x2 + x3;
    #pragma unroll
    for (int o = 16; o > 0; o >>= 1) sum += __shfl_xor_sync(0xffffffffu, sum, o);
    float mu = sum * (1.0f/128.0f);
    float d0 = x0-mu, d1 = x1-mu, d2 = x2-mu, d3 = x3-mu;
    float v = d0*d0 + d1*d1 + d2*d2 + d3*d3;
    #pragma unroll
    for (int o = 16; o > 0; o >>= 1) v += __shfl_xor_sync(0xffffffffu, v, o);
    float rstd = rsqrtf(v * (1.0f/128.0f) + 1e-5f);
    s[(lane      )*132 + row] = d0 * rstd;
    s[(lane + 32 )*132 + row] = d1 * rstd;
    s[(lane + 64 )*132 + row] = d2 * rstd;
    s[(lane + 96 )*132 + row] = d3 * rstd;
}

// ============================================================================
// Kernel A: LN(pair) -> gate/proj GEMM -> ab = mask * sigmoid(gate) * proj
//           writes a,b channel-major: g_a[ch][r], g_b[ch][r]
// Block: 128 rows (fixed i), 256 threads. Dynamic smem:
//   sP[128k][132row] LN'd pair (transposed), sWg/sWp[128k][68ch], sM[128]
// ============================================================================
__global__ void __launch_bounds__(256) kA(
    const float* __restrict__ pair, const float* __restrict__ mask,
    const float* __restrict__ apw, const float* __restrict__ apb,
    const float* __restrict__ agw, const float* __restrict__ agb)
{
    extern __shared__ float sm[];
    float* sP  = sm;                    // 128*132
    float* sWg = sm + 128*132;          // 128*68 (reused as sOut[64][132])
    float* sWp = sWg + 128*68;          // 128*68
    float* sM  = sWp + 128*68;          // 128

    const int t    = threadIdx.x;
    const int lane = t & 31;
    const int warp = t >> 5;
    const int r0   = blockIdx.x * 128;

    if (t < 128) sM[t] = mask[r0 + t];

    // LN directly from global into transposed smem
    for (int row = warp; row < 128; row += 8) {
        const float* src = pair + (size_t)(r0 + row) * DDIM;
        float x0 = src[lane], x1 = src[lane+32], x2 = src[lane+64], x3 = src[lane+96];
        float s = x0 + x1 + x2 + x3;
        #pragma unroll
        for (int o = 16; o > 0; o >>= 1) s += __shfl_xor_sync(0xffffffffu, s, o);
        float mu = s * (1.0f/128.0f);
        float d0 = x0-mu, d1 = x1-mu, d2 = x2-mu, d3 = x3-mu;
        float v = d0*d0 + d1*d1 + d2*d2 + d3*d3;
        #pragma unroll
        for (int o = 16; o > 0; o >>= 1) v += __shfl_xor_sync(0xffffffffu, v, o);
        float rstd = rsqrtf(v * (1.0f/128.0f) + 1e-5f);
        sP[(lane      )*132 + row] = d0*rstd;
        sP[(lane + 32 )*132 + row] = d1*rstd;
        sP[(lane + 64 )*132 + row] = d2*rstd;
        sP[(lane + 96 )*132 + row] = d3*rstd;
    }

    const int tx = t & 15;   // channel group (4 ch)
    const int ty = t >> 4;   // row group (8 rows)

    for (int ct = 0; ct < 4; ct++) {
        const int ch0 = ct * 64;
        __syncthreads();
        // load 64 gate + 64 proj weight rows, transposed to [k][ch]
        #pragma unroll
        for (int m = 0; m < 8; m++) {
            int q = t + 256*m;
            int c = q >> 5;
            int kb = (q & 31) * 4;
            float4 fg = *(const float4*)(agw + (size_t)(ch0 + c)*DDIM + kb);
            float4 fp = *(const float4*)(apw + (size_t)(ch0 + c)*DDIM + kb);
            sWg[(kb+0)*68 + c] = fg.x; sWg[(kb+1)*68 + c] = fg.y;
            sWg[(kb+2)*68 + c] = fg.z; sWg[(kb+3)*68 + c] = fg.w;
            sWp[(kb+0)*68 + c] = fp.x; sWp[(kb+1)*68 + c] = fp.y;
            sWp[(kb+2)*68 + c] = fp.z; sWp[(kb+3)*68 + c] = fp.w;
        }
        __syncthreads();

        ull cg[8][2], cp[8][2];
        #pragma unroll
        for (int e = 0; e < 8; e++) { cg[e][0]=0; cg[e][1]=0; cp[e][0]=0; cp[e][1]=0; }

        #pragma unroll 4
        for (int k = 0; k < 128; k++) {
            float4 a0 = *(const float4*)&sP[k*132 + ty*8];
            float4 a1 = *(const float4*)&sP[k*132 + ty*8 + 4];
            float4 g4 = *(const float4*)&sWg[k*68 + tx*4];
            float4 p4 = *(const float4*)&sWp[k*68 + tx*4];
            ull g2a = pk2(g4.x, g4.y), g2b = pk2(g4.z, g4.w);
            ull p2a = pk2(p4.x, p4.y), p2b = pk2(p4.z, p4.w);
            float av[8] = {a0.x,a0.y,a0.z,a0.w,a1.x,a1.y,a1.z,a1.w};
            #pragma unroll
            for (int e = 0; e < 8; e++) {
                ull a2 = dup2(av[e]);
                fma2(cg[e][0], a2, g2a);
                fma2(cg[e][1], a2, g2b);
                fma2(cp[e][0], a2, p2a);
                fma2(cp[e][1], a2, p2b);
            }
        }

        float bg0 = __ldg(agb + ch0 + tx*4 + 0);
        float bg1 = __ldg(agb + ch0 + tx*4 + 1);
        float bg2 = __ldg(agb + ch0 + tx*4 + 2);
        float bg3 = __ldg(agb + ch0 + tx*4 + 3);
        float bp0 = __ldg(apb + ch0 + tx*4 + 0);
        float bp1 = __ldg(apb + ch0 + tx*4 + 1);
        float bp2 = __ldg(apb + ch0 + tx*4 + 2);
        float bp3 = __ldg(apb + ch0 + tx*4 + 3);

        __syncthreads();   // done reading sWg; reuse as sOut
        #pragma unroll
        for (int e = 0; e < 8; e++) {
            float mv = sM[ty*8 + e];
            float2 gA = unpk(cg[e][0]), gB = unpk(cg[e][1]);
            float2 pA = unpk(cp[e][0]), pB = unpk(cp[e][1]);
            sWg[(tx*4+0)*132 + ty*8 + e] = mv * sigmoidf_(gA.x + bg0) * (pA.x + bp0);
            sWg[(tx*4+1)*132 + ty*8 + e] = mv * sigmoidf_(gA.y + bg1) * (pA.y + bp1);
            sWg[(tx*4+2)*132 + ty*8 + e] = mv * sigmoidf_(gB.x + bg2) * (pB.x + bp2);
            sWg[(tx*4+3)*132 + ty*8 + e] = mv * sigmoidf_(gB.y + bg3) * (pB.y + bp3);
        }
        __syncthreads();
        float* dstbase = (ch0 < 128) ? (g_a + (size_t)ch0 * NN)
                                     : (g_b + (size_t)(ch0 - 128) * NN);
        #pragma unroll
        for (int m = 0; m < 8; m++) {
            int q = t + 256*m;
            int c = q >> 5;
            int r4 = (q & 31) * 4;
            float4 v = *(const float4*)&sWg[c*132 + r4];
            *(float4*)(dstbase + (size_t)c*NN + r0 + r4) = v;
        }
    }
}

// ============================================================================
// Kernel B: 128 batched NT SGEMMs: C_d = A_d * B_d^T  (512x512x512)
// Tile 128x128, Kc=16, 256 threads, 8x8 micro-tile with f32x2 FMAs.
// ============================================================================
__global__ void __launch_bounds__(256, 2) kB()
{
    __shared__ __align__(16) float sA[16*132];
    __shared__ __align__(16) float sB[16*132];

    const int t  = threadIdx.x;
    const int d  = blockIdx.z;
    const int i0 = blockIdx.x * 128;
    const int j0 = blockIdx.y * 128;

    const float* __restrict__ Ab = g_a + (size_t)d*NN + (size_t)i0*NSEQ;
    const float* __restrict__ Bb = g_b + (size_t)d*NN + (size_t)j0*NSEQ;

    const int tx = t & 15;     // j group (8 cols)
    const int ty = t >> 4;     // i group (8 rows)

    const int rowL = t >> 2;          // 0..63
    const int kqL  = (t & 3) * 4;     // 0,4,8,12

    float4 ra0 = *(const float4*)(Ab + (size_t)rowL*NSEQ + kqL);
    float4 ra1 = *(const float4*)(Ab + (size_t)(rowL+64)*NSEQ + kqL);
    float4 rb0 = *(const float4*)(Bb + (size_t)rowL*NSEQ + kqL);
    float4 rb1 = *(const float4*)(Bb + (size_t)(rowL+64)*NSEQ + kqL);

    ull acc[8][4];
    #pragma unroll
    for (int r = 0; r < 8; r++)
        #pragma unroll
        for (int c = 0; c < 4; c++) acc[r][c] = 0;

    for (int kc = 0; kc < NSEQ; kc += 16) {
        // regs -> smem (transposed [k][row])
        sA[(kqL+0)*132 + rowL] = ra0.x; sA[(kqL+1)*132 + rowL] = ra0.y;
        sA[(kqL+2)*132 + rowL] = ra0.z; sA[(kqL+3)*132 + rowL] = ra0.w;
        sA[(kqL+0)*132 + rowL+64] = ra1.x; sA[(kqL+1)*132 + rowL+64] = ra1.y;
        sA[(kqL+2)*132 + rowL+64] = ra1.z; sA[(kqL+3)*132 + rowL+64] = ra1.w;
        sB[(kqL+0)*132 + rowL] = rb0.x; sB[(kqL+1)*132 + rowL] = rb0.y;
        sB[(kqL+2)*132 + rowL] = rb0.z; sB[(kqL+3)*132 + rowL] = rb0.w;
        sB[(kqL+0)*132 + rowL+64] = rb1.x; sB[(kqL+1)*132 + rowL+64] = rb1.y;
        sB[(kqL+2)*132 + rowL+64] = rb1.z; sB[(kqL+3)*132 + rowL+64] = rb1.w;
        __syncthreads();

        if (kc + 16 < NSEQ) {
            const float* An = Ab + kc + 16 + kqL;
            const float* Bn = Bb + kc + 16 + kqL;
            ra0 = *(const float4*)(An + (size_t)rowL*NSEQ);
            ra1 = *(const float4*)(An + (size_t)(rowL+64)*NSEQ);
            rb0 = *(const float4*)(Bn + (size_t)rowL*NSEQ);
            rb1 = *(const float4*)(Bn + (size_t)(rowL+64)*NSEQ);
        }

        #pragma unroll
        for (int k = 0; k < 16; k++) {
            float4 a0 = *(const float4*)&sA[k*132 + ty*8];
            float4 a1 = *(const float4*)&sA[k*132 + ty*8 + 4];
            float4 b0 = *(const float4*)&sB[k*132 + tx*8];
            float4 b1 = *(const float4*)&sB[k*132 + tx*8 + 4];
            ull bb0 = pk2(b0.x, b0.y), bb1 = pk2(b0.z, b0.w);
            ull bb2 = pk2(b1.x, b1.y), bb3 = pk2(b1.z, b1.w);
            float av[8] = {a0.x,a0.y,a0.z,a0.w,a1.x,a1.y,a1.z,a1.w};
            #pragma unroll
            for (int r = 0; r < 8; r++) {
                ull a2 = dup2(av[r]);
                fma2(acc[r][0], a2, bb0);
                fma2(acc[r][1], a2, bb1);
                fma2(acc[r][2], a2, bb2);
                fma2(acc[r][3], a2, bb3);
            }
        }
        __syncthreads();
    }

    float* C = g_t + (size_t)d*NN + (size_t)(i0 + ty*8)*NSEQ + (j0 + tx*8);
    #pragma unroll
    for (int r = 0; r < 8; r++) {
        float2 v0 = unpk(acc[r][0]), v1 = unpk(acc[r][1]);
        float2 v2 = unpk(acc[r][2]), v3 = unpk(acc[r][3]);
        float4 o0 = make_float4(v0.x, v0.y, v1.x, v1.y);
        float4 o1 = make_float4(v2.x, v2.y, v3.x, v3.y);
        *(float4*)(C + (size_t)r*NSEQ)     = o0;
        *(float4*)(C + (size_t)r*NSEQ + 4) = o1;
    }
}

// ============================================================================
// Kernel C: out = sigmoid(LN(pair)@ogw^T + ogb) * (LN(tri)@opw^T + opb)
// Block: 128 rows (r = i*512 + j), 256 threads.
// ============================================================================
__global__ void __launch_bounds__(256) kC(
    const float* __restrict__ pair,
    const float* __restrict__ opw, const float* __restrict__ opb,
    const float* __restrict__ ogw, const float* __restrict__ ogb,
    float* __restrict__ out)
{
    extern __shared__ float sm[];
    float* sP  = sm;               // 128*132  pair LN, [d][row]
    float* sT  = sm + 128*132;     // 128*132  tri LN,  [d][row]
    float* sWg = sT + 128*132;     // 128*68
    float* sWp = sWg + 128*68;     // 128*68

    const int t    = threadIdx.x;
    const int lane = t & 31;
    const int warp = t >> 5;
    const int r0   = blockIdx.x * 128;

    // pair tile -> transposed smem
    #pragma unroll
    for (int m = 0; m < 16; m++) {
        int q = t + 256*m;
        int row = q >> 5;
        int db = (q & 31) * 4;
        float4 f = *(const float4*)(pair + (size_t)(r0 + row)*DDIM + db);
        sP[(db+0)*132 + row] = f.x;
        sP[(db+1)*132 + row] = f.y;
        sP[(db+2)*132 + row] = f.z;
        sP[(db+3)*132 + row] = f.w;
    }
    // tri tile: already [d][r] layout
    #pragma unroll
    for (int m = 0; m < 16; m++) {
        int q = t + 256*m;
        int dd = q >> 5;
        int r4 = (q & 31) * 4;
        float4 f = *(const float4*)(g_t + (size_t)dd*NN + r0 + r4);
        *(float4*)&sT[dd*132 + r4] = f;
    }
    __syncthreads();
    for (int row = warp; row < 128; row += 8) {
        ln_col(sP, row, lane);
        ln_col(sT, row, lane);
    }

    const int tx = t & 15;
    const int ty = t >> 4;

    for (int ot = 0; ot < 2; ot++) {
        const int o0 = ot * 64;
        __syncthreads();
        #pragma unroll
        for (int m = 0; m < 8; m++) {
            int q = t + 256*m;
            int c = q >> 5;
            int db = (q & 31) * 4;
            float4 fg = *(const float4*)(ogw + (size_t)(o0 + c)*DDIM + db);
            float4 fp = *(const float4*)(opw + (size_t)(o0 + c)*DDIM + db);
            sWg[(db+0)*68 + c] = fg.x; sWg[(db+1)*68 + c] = fg.y;
            sWg[(db+2)*68 + c] = fg.z; sWg[(db+3)*68 + c] = fg.w;
            sWp[(db+0)*68 + c] = fp.x; sWp[(db+1)*68 + c] = fp.y;
            sWp[(db+2)*68 + c] = fp.z; sWp[(db+3)*68 + c] = fp.w;
        }
        __syncthreads();

        ull cg[8][2], cp[8][2];
        #pragma unroll
        for (int e = 0; e < 8; e++) { cg[e][0]=0; cg[e][1]=0; cp[e][0]=0; cp[e][1]=0; }

        #pragma unroll 4
        for (int k = 0; k < 128; k++) {
            float4 q0 = *(const float4*)&sP[k*132 + ty*8];
            float4 q1 = *(const float4*)&sP[k*132 + ty*8 + 4];
            float4 u0 = *(const float4*)&sT[k*132 + ty*8];
            float4 u1 = *(const float4*)&sT[k*132 + ty*8 + 4];
            float4 g4 = *(const float4*)&sWg[k*68 + tx*4];
            float4 p4 = *(const float4*)&sWp[k*68 + tx*4];
            ull g2a = pk2(g4.x, g4.y), g2b = pk2(g4.z, g4.w);
            ull p2a = pk2(p4.x, p4.y), p2b = pk2(p4.z, p4.w);
            float pv[8] = {q0.x,q0.y,q0.z,q0.w,q1.x,q1.y,q1.z,q1.w};
            float tv[8] = {u0.x,u0.y,u0.z,u0.w,u1.x,u1.y,u1.z,u1.w};
            #pragma unroll
            for (int e = 0; e < 8; e++) {
                ull a2 = dup2(pv[e]);
                fma2(cg[e][0], a2, g2a);
                fma2(cg[e][1], a2, g2b);
                ull b2 = dup2(tv[e]);
                fma2(cp[e][0], b2, p2a);
                fma2(cp[e][1], b2, p2b);
            }
        }

        float bg0 = __ldg(ogb + o0 + tx*4 + 0);
        float bg1 = __ldg(ogb + o0 + tx*4 + 1);
        float bg2 = __ldg(ogb + o0 + tx*4 + 2);
        float bg3 = __ldg(ogb + o0 + tx*4 + 3);
        float bp0 = __ldg(opb + o0 + tx*4 + 0);
        float bp1 = __ldg(opb + o0 + tx*4 + 1);
        float bp2 = __ldg(opb + o0 + tx*4 + 2);
        float bp3 = __ldg(opb + o0 + tx*4 + 3);

        #pragma unroll
        for (int e = 0; e < 8; e++) {
            float2 gA = unpk(cg[e][0]), gB = unpk(cg[e][1]);
            float2 pA = unpk(cp[e][0]), pB = unpk(cp[e][1]);
            float4 r;
            r.x = sigmoidf_(gA.x + bg0) * (pA.x + bp0);
            r.y = sigmoidf_(gA.y + bg1) * (pA.y + bp1);
            r.z = sigmoidf_(gB.x + bg2) * (pB.x + bp2);
            r.w = sigmoidf_(gB.y + bg3) * (pB.y + bp3);
            *(float4*)(out + (size_t)(r0 + ty*8 + e)*DDIM + o0 + tx*4) = r;
        }
    }
}

// ============================================================================
extern "C" void kernel_launch(void* const* d_in, const int* in_sizes, int n_in,
                              void* d_out, int out_size)
{
    const float* pair = (const float*)d_in[0];
    const float* mask = (const float*)d_in[1];
    const float* apw  = (const float*)d_in[2];   // ab_proj_w [256,128]
    const float* apb  = (const float*)d_in[3];
    const float* agw  = (const float*)d_in[4];   // ab_gate_w [256,128]
    const float* agb  = (const float*)d_in[5];
    const float* opw  = (const float*)d_in[6];   // out_proj_w [128,128]
    const float* opb  = (const float*)d_in[7];
    const float* ogw  = (const float*)d_in[8];   // out_gate_w [128,128]
    const float* ogb  = (const float*)d_in[9];
    float* out = (float*)d_out;

    const size_t smA = (size_t)(128*132 + 2*128*68 + 128) * sizeof(float);   // ~137.7 KB
    const size_t smC = (size_t)(2*128*132 + 2*128*68) * sizeof(float);       // ~204.8 KB
    cudaFuncSetAttribute(kA, cudaFuncAttributeMaxDynamicSharedMemorySize, (int)smA);
    cudaFuncSetAttribute(kC, cudaFuncAttributeMaxDynamicSharedMemorySize, (int)smC);

    kA<<<NN/128, 256, smA>>>(pair, mask, apw, apb, agw, agb);
    kB<<<dim3(4, 4, DDIM), 256>>>();
    kC<<<NN/128, 256, smC>>>(pair, opw, opb, ogw, ogb, out);
}

// round 3
// speedup vs baseline: 1.2129x; 1.2129x over previous
#include <cuda_runtime.h>
#include <cuda_bf16.h>
#include <cstdint>
#include <cstddef>

#define NSEQ 512
#define DDIM 128
#define NN   (NSEQ*NSEQ)

typedef unsigned long long ull;

// Scratch: a,b as bf16 hi/lo, channel-major [d][i][k]; tri fp32 [d][i][j]
static __device__ __nv_bfloat16 g_ah[(size_t)DDIM * NN];
static __device__ __nv_bfloat16 g_al[(size_t)DDIM * NN];
static __device__ __nv_bfloat16 g_bh[(size_t)DDIM * NN];
static __device__ __nv_bfloat16 g_bl[(size_t)DDIM * NN];
static __device__ float g_t[(size_t)DDIM * NN];

// ---------------- packed f32x2 helpers ----------------
__device__ __forceinline__ ull pk2(float a, float b) {
    ull r; asm("mov.b64 %0, {%1, %2};" : "=l"(r) : "f"(a), "f"(b)); return r;
}
__device__ __forceinline__ ull dup2(float a) {
    ull r; asm("mov.b64 %0, {%1, %1};" : "=l"(r) : "f"(a)); return r;
}
__device__ __forceinline__ void fma2(ull& c, ull a, ull b) {
    asm("fma.rn.f32x2 %0, %1, %2, %0;" : "+l"(c) : "l"(a), "l"(b));
}
__device__ __forceinline__ float2 unpk(ull v) {
    float2 r; asm("mov.b64 {%0, %1}, %2;" : "=f"(r.x), "=f"(r.y) : "l"(v)); return r;
}
__device__ __forceinline__ float sigmoidf_(float x) { return 1.0f / (1.0f + __expf(-x)); }

__device__ __forceinline__ uint32_t smem_u32(const void* p) {
    uint32_t a;
    asm("{ .reg .u64 t; cvta.to.shared.u64 t, %1; cvt.u32.u64 %0, t; }" : "=r"(a) : "l"(p));
    return a;
}
#define SW128(o) ((o) ^ (((o) >> 3) & 0x70))

#define CP_ASYNC16(dst, src) \
    asm volatile("cp.async.cg.shared.global [%0], [%1], 16;" :: "r"(dst), "l"(src) : "memory")
#define CP_COMMIT() asm volatile("cp.async.commit_group;" ::: "memory")
#define CP_WAIT(n)  asm volatile("cp.async.wait_group %0;" :: "n"(n) : "memory")

__device__ __forceinline__ void ldm4(uint32_t addr, uint32_t r[4]) {
    asm volatile("ldmatrix.sync.aligned.m8n8.x4.shared.b16 {%0,%1,%2,%3}, [%4];"
        : "=r"(r[0]), "=r"(r[1]), "=r"(r[2]), "=r"(r[3]) : "r"(addr));
}
__device__ __forceinline__ void mma16816(float c[4], const uint32_t a[4],
                                         uint32_t b0, uint32_t b1) {
    asm volatile(
        "mma.sync.aligned.m16n8k16.row.col.f32.bf16.bf16.f32 "
        "{%0,%1,%2,%3}, {%4,%5,%6,%7}, {%8,%9}, {%0,%1,%2,%3};"
        : "+f"(c[0]), "+f"(c[1]), "+f"(c[2]), "+f"(c[3])
        : "r"(a[0]), "r"(a[1]), "r"(a[2]), "r"(a[3]), "r"(b0), "r"(b1));
}

// LayerNorm of one logical row stored as a column: s[d*132 + row]
__device__ __forceinline__ void ln_col(float* s, int row, int lane) {
    float x0 = s[(lane      )*132 + row];
    float x1 = s[(lane + 32 )*132 + row];
    float x2 = s[(lane + 64 )*132 + row];
    float x3 = s[(lane + 96 )*132 + row];
    float sum = x0 + x1 + x2 + x3;
    #pragma unroll
    for (int o = 16; o > 0; o >>= 1) sum += __shfl_xor_sync(0xffffffffu, sum, o);
    float mu = sum * (1.0f/128.0f);
    float d0 = x0-mu, d1 = x1-mu, d2 = x2-mu, d3 = x3-mu;
    float v = d0*d0 + d1*d1 + d2*d2 + d3*d3;
    #pragma unroll
    for (int o = 16; o > 0; o >>= 1) v += __shfl_xor_sync(0xffffffffu, v, o);
    float rstd = rsqrtf(v * (1.0f/128.0f) + 1e-5f);
    s[(lane      )*132 + row] = d0 * rstd;
    s[(lane + 32 )*132 + row] = d1 * rstd;
    s[(lane + 64 )*132 + row] = d2 * rstd;
    s[(lane + 96 )*132 + row] = d3 * rstd;
}

// ============================================================================
// Kernel A: LN(pair) -> gate/proj GEMM -> ab = mask*sigmoid(gate)*proj
//           writes a,b channel-major as bf16 hi/lo
// ============================================================================
__global__ void __launch_bounds__(256) kA(
    const float* __restrict__ pair, const float* __restrict__ mask,
    const float* __restrict__ apw, const float* __restrict__ apb,
    const float* __restrict__ agw, const float* __restrict__ agb)
{
    extern __shared__ float sm[];
    float* sP  = sm;                    // 128*132
    float* sWg = sm + 128*132;          // 128*68 (reused as sOut)
    float* sWp = sWg + 128*68;          // 128*68
    float* sM  = sWp + 128*68;          // 128

    const int t    = threadIdx.x;
    const int lane = t & 31;
    const int warp = t >> 5;
    const int r0   = blockIdx.x * 128;

    if (t < 128) sM[t] = mask[r0 + t];

    for (int row = warp; row < 128; row += 8) {
        const float* src = pair + (size_t)(r0 + row) * DDIM;
        float x0 = src[lane], x1 = src[lane+32], x2 = src[lane+64], x3 = src[lane+96];
        float s = x0 + x1 + x2 + x3;
        #pragma unroll
        for (int o = 16; o > 0; o >>= 1) s += __shfl_xor_sync(0xffffffffu, s, o);
        float mu = s * (1.0f/128.0f);
        float d0 = x0-mu, d1 = x1-mu, d2 = x2-mu, d3 = x3-mu;
        float v = d0*d0 + d1*d1 + d2*d2 + d3*d3;
        #pragma unroll
        for (int o = 16; o > 0; o >>= 1) v += __shfl_xor_sync(0xffffffffu, v, o);
        float rstd = rsqrtf(v * (1.0f/128.0f) + 1e-5f);
        sP[(lane      )*132 + row] = d0*rstd;
        sP[(lane + 32 )*132 + row] = d1*rstd;
        sP[(lane + 64 )*132 + row] = d2*rstd;
        sP[(lane + 96 )*132 + row] = d3*rstd;
    }

    const int tx = t & 15;
    const int ty = t >> 4;

    for (int ct = 0; ct < 4; ct++) {
        const int ch0 = ct * 64;
        __syncthreads();
        #pragma unroll
        for (int m = 0; m < 8; m++) {
            int q = t + 256*m;
            int c = q >> 5;
            int kb = (q & 31) * 4;
            float4 fg = *(const float4*)(agw + (size_t)(ch0 + c)*DDIM + kb);
            float4 fp = *(const float4*)(apw + (size_t)(ch0 + c)*DDIM + kb);
            sWg[(kb+0)*68 + c] = fg.x; sWg[(kb+1)*68 + c] = fg.y;
            sWg[(kb+2)*68 + c] = fg.z; sWg[(kb+3)*68 + c] = fg.w;
            sWp[(kb+0)*68 + c] = fp.x; sWp[(kb+1)*68 + c] = fp.y;
            sWp[(kb+2)*68 + c] = fp.z; sWp[(kb+3)*68 + c] = fp.w;
        }
        __syncthreads();

        ull cg[8][2], cp[8][2];
        #pragma unroll
        for (int e = 0; e < 8; e++) { cg[e][0]=0; cg[e][1]=0; cp[e][0]=0; cp[e][1]=0; }

        #pragma unroll 4
        for (int k = 0; k < 128; k++) {
            float4 a0 = *(const float4*)&sP[k*132 + ty*8];
            float4 a1 = *(const float4*)&sP[k*132 + ty*8 + 4];
            float4 g4 = *(const float4*)&sWg[k*68 + tx*4];
            float4 p4 = *(const float4*)&sWp[k*68 + tx*4];
            ull g2a = pk2(g4.x, g4.y), g2b = pk2(g4.z, g4.w);
            ull p2a = pk2(p4.x, p4.y), p2b = pk2(p4.z, p4.w);
            float av[8] = {a0.x,a0.y,a0.z,a0.w,a1.x,a1.y,a1.z,a1.w};
            #pragma unroll
            for (int e = 0; e < 8; e++) {
                ull a2 = dup2(av[e]);
                fma2(cg[e][0], a2, g2a);
                fma2(cg[e][1], a2, g2b);
                fma2(cp[e][0], a2, p2a);
                fma2(cp[e][1], a2, p2b);
            }
        }

        float bg0 = __ldg(agb + ch0 + tx*4 + 0);
        float bg1 = __ldg(agb + ch0 + tx*4 + 1);
        float bg2 = __ldg(agb + ch0 + tx*4 + 2);
        float bg3 = __ldg(agb + ch0 + tx*4 + 3);
        float bp0 = __ldg(apb + ch0 + tx*4 + 0);
        float bp1 = __ldg(apb + ch0 + tx*4 + 1);
        float bp2 = __ldg(apb + ch0 + tx*4 + 2);
        float bp3 = __ldg(apb + ch0 + tx*4 + 3);

        __syncthreads();
        #pragma unroll
        for (int e = 0; e < 8; e++) {
            float mv = sM[ty*8 + e];
            float2 gA = unpk(cg[e][0]), gB = unpk(cg[e][1]);
            float2 pA = unpk(cp[e][0]), pB = unpk(cp[e][1]);
            sWg[(tx*4+0)*132 + ty*8 + e] = mv * sigmoidf_(gA.x + bg0) * (pA.x + bp0);
            sWg[(tx*4+1)*132 + ty*8 + e] = mv * sigmoidf_(gA.y + bg1) * (pA.y + bp1);
            sWg[(tx*4+2)*132 + ty*8 + e] = mv * sigmoidf_(gB.x + bg2) * (pB.x + bp2);
            sWg[(tx*4+3)*132 + ty*8 + e] = mv * sigmoidf_(gB.y + bg3) * (pB.y + bp3);
        }
        __syncthreads();

        __nv_bfloat16* dstH = (ch0 < 128) ? (g_ah + (size_t)ch0 * NN)
                                          : (g_bh + (size_t)(ch0 - 128) * NN);
        __nv_bfloat16* dstL = (ch0 < 128) ? (g_al + (size_t)ch0 * NN)
                                          : (g_bl + (size_t)(ch0 - 128) * NN);
        #pragma unroll
        for (int m = 0; m < 4; m++) {
            int q = t + 256*m;
            int c = q >> 4;
            int r8 = (q & 15) * 8;
            float4 v0 = *(const float4*)&sWg[c*132 + r8];
            float4 v1 = *(const float4*)&sWg[c*132 + r8 + 4];
            float vv[8] = {v0.x,v0.y,v0.z,v0.w,v1.x,v1.y,v1.z,v1.w};
            union { __nv_bfloat16 b[8]; uint4 u; } H, L;
            #pragma unroll
            for (int e = 0; e < 8; e++) {
                __nv_bfloat16 h = __float2bfloat16_rn(vv[e]);
                H.b[e] = h;
                L.b[e] = __float2bfloat16_rn(vv[e] - __bfloat162float(h));
            }
            size_t off = (size_t)c * NN + r0 + r8;
            *(uint4*)(dstH + off) = H.u;
            *(uint4*)(dstL + off) = L.u;
        }
    }
}

// ============================================================================
// Kernel B: 128 batched NT GEMMs via HMMA bf16x3 split.
// CTA: 128x128 tile, KC=64, double-buffered cp.async (2 x 64KB stages).
// 8 warps (2m x 4n), each 64x32 with m16n8k16.
// ============================================================================
__global__ void __launch_bounds__(256) kB()
{
    extern __shared__ char smc[];
    const uint32_t sbase = smem_u32(smc);

    const int t    = threadIdx.x;
    const int lane = t & 31;
    const int wid  = t >> 5;
    const int d    = blockIdx.z;
    const int i0   = blockIdx.x * 128;
    const int j0   = blockIdx.y * 128;

    const int wm = wid & 1;       // 0..1
    const int wn = wid >> 1;      // 0..3
    const int m0 = wm * 64;
    const int n0 = wn * 32;

    const __nv_bfloat16* srcs[4] = {
        g_ah + (size_t)d*NN + (size_t)i0*NSEQ,
        g_al + (size_t)d*NN + (size_t)i0*NSEQ,
        g_bh + (size_t)d*NN + (size_t)j0*NSEQ,
        g_bl + (size_t)d*NN + (size_t)j0*NSEQ };

    // cp.async per-thread segments
    const int segRow = t >> 1;                 // base pattern not used; see loop
    (void)segRow;

    // issue one chunk (4 tiles of 128x64 bf16, SW128 swizzled)
    auto issue = [&](int stage, int kc) {
        uint32_t sb = sbase + stage * 65536;
        #pragma unroll
        for (int T = 0; T < 4; T++) {
            const __nv_bfloat16* base = srcs[T];
            #pragma unroll
            for (int q = 0; q < 4; q++) {
                int seg = t + 256*q;
                int row = seg >> 3;
                int s   = seg & 7;
                uint32_t dst = sb + T*16384 + SW128((uint32_t)(row*128 + s*16));
                CP_ASYNC16(dst, base + (size_t)row*NSEQ + kc + s*8);
            }
        }
        CP_COMMIT();
    };

    float acc[4][4][4];
    #pragma unroll
    for (int m = 0; m < 4; m++)
        #pragma unroll
        for (int n = 0; n < 4; n++)
            #pragma unroll
            for (int e = 0; e < 4; e++) acc[m][n][e] = 0.0f;

    // precomputed fragment address components
    const int aRow = lane & 15;            // + m0 + f*16
    const int aK   = (lane >> 4) * 16;     // byte offset within k16 (two 8-col halves)
    const int bRow = (lane & 7) + ((lane >> 4) << 3);   // + n0 + c*16
    const int bK   = ((lane >> 3) & 1) * 16;

    issue(0, 0);

    for (int ch = 0; ch < 8; ch++) {
        const int stage = ch & 1;
        if (ch < 7) { issue(stage ^ 1, (ch + 1) * 64); CP_WAIT(1); }
        else        { CP_WAIT(0); }
        __syncthreads();

        const uint32_t sb  = sbase + stage * 65536;
        const uint32_t sAh = sb;
        const uint32_t sAl = sb + 16384;
        const uint32_t sBh = sb + 32768;
        const uint32_t sBl = sb + 49152;

        #pragma unroll
        for (int kk = 0; kk < 4; kk++) {
            const uint32_t kOffA = (uint32_t)(kk*32) + aK;
            const uint32_t kOffB = (uint32_t)(kk*32) + bK;

            uint32_t bh[2][4], bl[2][4];
            #pragma unroll
            for (int c = 0; c < 2; c++) {
                uint32_t off = (uint32_t)((n0 + c*16 + bRow) * 128) + kOffB;
                ldm4(sBh + SW128(off), bh[c]);
            }
            uint32_t ah[4][4];
            #pragma unroll
            for (int f = 0; f < 4; f++) {
                uint32_t off = (uint32_t)((m0 + f*16 + aRow) * 128) + kOffA;
                ldm4(sAh + SW128(off), ah[f]);
            }
            #pragma unroll
            for (int m = 0; m < 4; m++)
                #pragma unroll
                for (int n = 0; n < 4; n++)
                    mma16816(acc[m][n], ah[m], bh[n>>1][(n&1)*2], bh[n>>1][(n&1)*2+1]);

            #pragma unroll
            for (int c = 0; c < 2; c++) {
                uint32_t off = (uint32_t)((n0 + c*16 + bRow) * 128) + kOffB;
                ldm4(sBl + SW128(off), bl[c]);
            }
            #pragma unroll
            for (int m = 0; m < 4; m++)
                #pragma unroll
                for (int n = 0; n < 4; n++)
                    mma16816(acc[m][n], ah[m], bl[n>>1][(n&1)*2], bl[n>>1][(n&1)*2+1]);

            uint32_t al[4][4];
            #pragma unroll
            for (int f = 0; f < 4; f++) {
                uint32_t off = (uint32_t)((m0 + f*16 + aRow) * 128) + kOffA;
                ldm4(sAl + SW128(off), al[f]);
            }
            #pragma unroll
            for (int m = 0; m < 4; m++)
                #pragma unroll
                for (int n = 0; n < 4; n++)
                    mma16816(acc[m][n], al[m], bh[n>>1][(n&1)*2], bh[n>>1][(n&1)*2+1]);
        }
        __syncthreads();
    }

    // epilogue: direct float2 stores
    float* base = g_t + (size_t)d*NN;
    #pragma unroll
    for (int m = 0; m < 4; m++) {
        int r1 = i0 + m0 + m*16 + (lane >> 2);
        #pragma unroll
        for (int n = 0; n < 4; n++) {
            int c = j0 + n0 + n*8 + (lane & 3)*2;
            float2 lo = make_float2(acc[m][n][0], acc[m][n][1]);
            float2 hi = make_float2(acc[m][n][2], acc[m][n][3]);
            *(float2*)(base + (size_t)r1*NSEQ + c)       = lo;
            *(float2*)(base + (size_t)(r1+8)*NSEQ + c)   = hi;
        }
    }
}

// ============================================================================
// Kernel C: out = sigmoid(LN(pair)@ogw^T + ogb) * (LN(tri)@opw^T + opb)
// ============================================================================
__global__ void __launch_bounds__(256) kC(
    const float* __restrict__ pair,
    const float* __restrict__ opw, const float* __restrict__ opb,
    const float* __restrict__ ogw, const float* __restrict__ ogb,
    float* __restrict__ out)
{
    extern __shared__ float sm[];
    float* sP  = sm;               // 128*132
    float* sT  = sm + 128*132;     // 128*132
    float* sWg = sT + 128*132;     // 128*68
    float* sWp = sWg + 128*68;     // 128*68

    const int t    = threadIdx.x;
    const int lane = t & 31;
    const int warp = t >> 5;
    const int r0   = blockIdx.x * 128;

    #pragma unroll
    for (int m = 0; m < 16; m++) {
        int q = t + 256*m;
        int row = q >> 5;
        int db = (q & 31) * 4;
        float4 f = *(const float4*)(pair + (size_t)(r0 + row)*DDIM + db);
        sP[(db+0)*132 + row] = f.x;
        sP[(db+1)*132 + row] = f.y;
        sP[(db+2)*132 + row] = f.z;
        sP[(db+3)*132 + row] = f.w;
    }
    #pragma unroll
    for (int m = 0; m < 16; m++) {
        int q = t + 256*m;
        int dd = q >> 5;
        int r4 = (q & 31) * 4;
        float4 f = *(const float4*)(g_t + (size_t)dd*NN + r0 + r4);
        *(float4*)&sT[dd*132 + r4] = f;
    }
    __syncthreads();
    for (int row = warp; row < 128; row += 8) {
        ln_col(sP, row, lane);
        ln_col(sT, row, lane);
    }

    const int tx = t & 15;
    const int ty = t >> 4;

    for (int ot = 0; ot < 2; ot++) {
        const int o0 = ot * 64;
        __syncthreads();
        #pragma unroll
        for (int m = 0; m < 8; m++) {
            int q = t + 256*m;
            int c = q >> 5;
            int db = (q & 31) * 4;
            float4 fg = *(const float4*)(ogw + (size_t)(o0 + c)*DDIM + db);
            float4 fp = *(const float4*)(opw + (size_t)(o0 + c)*DDIM + db);
            sWg[(db+0)*68 + c] = fg.x; sWg[(db+1)*68 + c] = fg.y;
            sWg[(db+2)*68 + c] = fg.z; sWg[(db+3)*68 + c] = fg.w;
            sWp[(db+0)*68 + c] = fp.x; sWp[(db+1)*68 + c] = fp.y;
            sWp[(db+2)*68 + c] = fp.z; sWp[(db+3)*68 + c] = fp.w;
        }
        __syncthreads();

        ull cg[8][2], cp[8][2];
        #pragma unroll
        for (int e = 0; e < 8; e++) { cg[e][0]=0; cg[e][1]=0; cp[e][0]=0; cp[e][1]=0; }

        #pragma unroll 4
        for (int k = 0; k < 128; k++) {
            float4 q0 = *(const float4*)&sP[k*132 + ty*8];
            float4 q1 = *(const float4*)&sP[k*132 + ty*8 + 4];
            float4 u0 = *(const float4*)&sT[k*132 + ty*8];
            float4 u1 = *(const float4*)&sT[k*132 + ty*8 + 4];
            float4 g4 = *(const float4*)&sWg[k*68 + tx*4];
            float4 p4 = *(const float4*)&sWp[k*68 + tx*4];
            ull g2a = pk2(g4.x, g4.y), g2b = pk2(g4.z, g4.w);
            ull p2a = pk2(p4.x, p4.y), p2b = pk2(p4.z, p4.w);
            float pv[8] = {q0.x,q0.y,q0.z,q0.w,q1.x,q1.y,q1.z,q1.w};
            float tv[8] = {u0.x,u0.y,u0.z,u0.w,u1.x,u1.y,u1.z,u1.w};
            #pragma unroll
            for (int e = 0; e < 8; e++) {
                ull a2 = dup2(pv[e]);
                fma2(cg[e][0], a2, g2a);
                fma2(cg[e][1], a2, g2b);
                ull b2 = dup2(tv[e]);
                fma2(cp[e][0], b2, p2a);
                fma2(cp[e][1], b2, p2b);
            }
        }

        float bg0 = __ldg(ogb + o0 + tx*4 + 0);
        float bg1 = __ldg(ogb + o0 + tx*4 + 1);
        float bg2 = __ldg(ogb + o0 + tx*4 + 2);
        float bg3 = __ldg(ogb + o0 + tx*4 + 3);
        float bp0 = __ldg(opb + o0 + tx*4 + 0);
        float bp1 = __ldg(opb + o0 + tx*4 + 1);
        float bp2 = __ldg(opb + o0 + tx*4 + 2);
        float bp3 = __ldg(opb + o0 + tx*4 + 3);

        #pragma unroll
        for (int e = 0; e < 8; e++) {
            float2 gA = unpk(cg[e][0]), gB = unpk(cg[e][1]);
            float2 pA = unpk(cp[e][0]), pB = unpk(cp[e][1]);
            float4 r;
            r.x = sigmoidf_(gA.x + bg0) * (pA.x + bp0);
            r.y = sigmoidf_(gA.y + bg1) * (pA.y + bp1);
            r.z = sigmoidf_(gB.x + bg2) * (pB.x + bp2);
            r.w = sigmoidf_(gB.y + bg3) * (pB.y + bp3);
            *(float4*)(out + (size_t)(r0 + ty*8 + e)*DDIM + o0 + tx*4) = r;
        }
    }
}

// ============================================================================
extern "C" void kernel_launch(void* const* d_in, const int* in_sizes, int n_in,
                              void* d_out, int out_size)
{
    const float* pair = (const float*)d_in[0];
    const float* mask = (const float*)d_in[1];
    const float* apw  = (const float*)d_in[2];
    const float* apb  = (const float*)d_in[3];
    const float* agw  = (const float*)d_in[4];
    const float* agb  = (const float*)d_in[5];
    const float* opw  = (const float*)d_in[6];
    const float* opb  = (const float*)d_in[7];
    const float* ogw  = (const float*)d_in[8];
    const float* ogb  = (const float*)d_in[9];
    float* out = (float*)d_out;

    const size_t smA = (size_t)(128*132 + 2*128*68 + 128) * sizeof(float);
    const size_t smB = 131072;   // 2 stages x 64KB
    const size_t smC = (size_t)(2*128*132 + 2*128*68) * sizeof(float);
    cudaFuncSetAttribute(kA, cudaFuncAttributeMaxDynamicSharedMemorySize, (int)smA);
    cudaFuncSetAttribute(kB, cudaFuncAttributeMaxDynamicSharedMemorySize, (int)smB);
    cudaFuncSetAttribute(kC, cudaFuncAttributeMaxDynamicSharedMemorySize, (int)smC);

    kA<<<NN/128, 256, smA>>>(pair, mask, apw, apb, agw, agb);
    kB<<<dim3(4, 4, DDIM), 256, smB>>>();
    kC<<<NN/128, 256, smC>>>(pair, opw, opb, ogw, ogb, out);
}

// round 4
// speedup vs baseline: 1.8748x; 1.5457x over previous
#include <cuda_runtime.h>
#include <cuda_bf16.h>
#include <cstdint>
#include <cstddef>

#define NSEQ 512
#define DDIM 128
#define NN   (NSEQ*NSEQ)

typedef unsigned long long ull;

// Scratch: a,b as bf16 hi/lo, channel-major [d][i][k]; tri fp32 [d][i][j]
static __device__ __nv_bfloat16 g_ah[(size_t)DDIM * NN];
static __device__ __nv_bfloat16 g_al[(size_t)DDIM * NN];
static __device__ __nv_bfloat16 g_bh[(size_t)DDIM * NN];
static __device__ __nv_bfloat16 g_bl[(size_t)DDIM * NN];
static __device__ float g_t[(size_t)DDIM * NN];

// Pre-split weights (bf16 hi/lo), row-major [ch][k]
static __device__ __nv_bfloat16 g_wgh[256*128], g_wgl[256*128];   // ab_gate
static __device__ __nv_bfloat16 g_wph[256*128], g_wpl[256*128];   // ab_proj
static __device__ __nv_bfloat16 g_ogh[128*128], g_ogl[128*128];   // out_gate
static __device__ __nv_bfloat16 g_oph[128*128], g_opl[128*128];   // out_proj

__device__ __forceinline__ float sigmoidf_(float x) { return 1.0f / (1.0f + __expf(-x)); }

__device__ __forceinline__ uint32_t smem_u32(const void* p) {
    uint32_t a;
    asm("{ .reg .u64 t; cvta.to.shared.u64 t, %1; cvt.u32.u64 %0, t; }" : "=r"(a) : "l"(p));
    return a;
}
#define SW128(o) ((o) ^ (((o) >> 3) & 0x70))

#define CP_ASYNC16(dst, src) \
    asm volatile("cp.async.cg.shared.global [%0], [%1], 16;" :: "r"(dst), "l"(src) : "memory")
#define CP_COMMIT() asm volatile("cp.async.commit_group;" ::: "memory")
#define CP_WAIT(n)  asm volatile("cp.async.wait_group %0;" :: "n"(n) : "memory")

__device__ __forceinline__ void ldm4(uint32_t addr, uint32_t r[4]) {
    asm volatile("ldmatrix.sync.aligned.m8n8.x4.shared.b16 {%0,%1,%2,%3}, [%4];"
        : "=r"(r[0]), "=r"(r[1]), "=r"(r[2]), "=r"(r[3]) : "r"(addr));
}
__device__ __forceinline__ void mma16816(float c[4], const uint32_t a[4],
                                         uint32_t b0, uint32_t b1) {
    asm volatile(
        "mma.sync.aligned.m16n8k16.row.col.f32.bf16.bf16.f32 "
        "{%0,%1,%2,%3}, {%4,%5,%6,%7}, {%8,%9}, {%0,%1,%2,%3};"
        : "+f"(c[0]), "+f"(c[1]), "+f"(c[2]), "+f"(c[3])
        : "r"(a[0]), "r"(a[1]), "r"(a[2]), "r"(a[3]), "r"(b0), "r"(b1));
}

// LayerNorm of one logical row stored as a column: s[d*132 + row]
__device__ __forceinline__ void ln_col(float* s, int row, int lane) {
    float x0 = s[(lane      )*132 + row];
    float x1 = s[(lane + 32 )*132 + row];
    float x2 = s[(lane + 64 )*132 + row];
    float x3 = s[(lane + 96 )*132 + row];
    float sum = x0 + x1 + x2 + x3;
    #pragma unroll
    for (int o = 16; o > 0; o >>= 1) sum += __shfl_xor_sync(0xffffffffu, sum, o);
    float mu = sum * (1.0f/128.0f);
    float d0 = x0-mu, d1 = x1-mu, d2 = x2-mu, d3 = x3-mu;
    float v = d0*d0 + d1*d1 + d2*d2 + d3*d3;
    #pragma unroll
    for (int o = 16; o > 0; o >>= 1) v += __shfl_xor_sync(0xffffffffu, v, o);
    float rstd = rsqrtf(v * (1.0f/128.0f) + 1e-5f);
    s[(lane      )*132 + row] = d0 * rstd;
    s[(lane + 32 )*132 + row] = d1 * rstd;
    s[(lane + 64 )*132 + row] = d2 * rstd;
    s[(lane + 96 )*132 + row] = d3 * rstd;
}

// ============================================================================
// Prep: split weight matrices to bf16 hi/lo
// ============================================================================
__global__ void __launch_bounds__(256) kW(
    const float* __restrict__ agw, const float* __restrict__ apw,
    const float* __restrict__ ogw, const float* __restrict__ opw)
{
    int i = blockIdx.x * 256 + threadIdx.x;
    if (i < 256*128) {
        float g = agw[i];
        __nv_bfloat16 gh = __float2bfloat16_rn(g);
        g_wgh[i] = gh; g_wgl[i] = __float2bfloat16_rn(g - __bfloat162float(gh));
        float p = apw[i];
        __nv_bfloat16 ph = __float2bfloat16_rn(p);
        g_wph[i] = ph; g_wpl[i] = __float2bfloat16_rn(p - __bfloat162float(ph));
    }
    if (i < 128*128) {
        float g = ogw[i];
        __nv_bfloat16 gh = __float2bfloat16_rn(g);
        g_ogh[i] = gh; g_ogl[i] = __float2bfloat16_rn(g - __bfloat162float(gh));
        float p = opw[i];
        __nv_bfloat16 ph = __float2bfloat16_rn(p);
        g_oph[i] = ph; g_opl[i] = __float2bfloat16_rn(p - __bfloat162float(ph));
    }
}

// ============================================================================
// Kernel A (HMMA): LN(pair) -> gate/proj bf16x3 GEMM -> ab = mask*sig(g)*p
//                  writes a,b channel-major as bf16 hi/lo
// smem layout (bytes):
//   0      : A hi  (2 halves x 16384)           32KB
//   32768  : A lo                               32KB
//   65536  : W  (4 arrays gh/gl/ph/pl x 16384)  64KB   per-array: half*8192 + SW128(ch*128+(k&63)*2)
//   131072 : stage hi (64ch x 128row bf16)      16KB
//   147456 : stage lo                           16KB
//   163840 : mask float[128]                    512B
// ============================================================================
__global__ void __launch_bounds__(256) kA(
    const float* __restrict__ pair, const float* __restrict__ mask,
    const float* __restrict__ apb, const float* __restrict__ agb)
{
    extern __shared__ char smc[];
    const uint32_t sbase = smem_u32(smc);
    const uint32_t uAh = sbase;
    const uint32_t uAl = sbase + 32768;
    const uint32_t uW  = sbase + 65536;
    float* sM = (float*)(smc + 163840);
    __nv_bfloat16* stgH = (__nv_bfloat16*)(smc + 131072);
    __nv_bfloat16* stgL = (__nv_bfloat16*)(smc + 147456);

    const int t    = threadIdx.x;
    const int lane = t & 31;
    const int wid  = t >> 5;
    const int r0   = blockIdx.x * 128;

    if (t < 128) sM[t] = mask[r0 + t];

    // LN + bf16 split -> A tiles
    for (int row = wid; row < 128; row += 8) {
        const float* src = pair + (size_t)(r0 + row) * DDIM;
        float x[4] = { src[lane], src[lane+32], src[lane+64], src[lane+96] };
        float s = x[0] + x[1] + x[2] + x[3];
        #pragma unroll
        for (int o = 16; o > 0; o >>= 1) s += __shfl_xor_sync(0xffffffffu, s, o);
        float mu = s * (1.0f/128.0f);
        float d0 = x[0]-mu, d1 = x[1]-mu, d2 = x[2]-mu, d3 = x[3]-mu;
        float v = d0*d0 + d1*d1 + d2*d2 + d3*d3;
        #pragma unroll
        for (int o = 16; o > 0; o >>= 1) v += __shfl_xor_sync(0xffffffffu, v, o);
        float rstd = rsqrtf(v * (1.0f/128.0f) + 1e-5f);
        float dd[4] = { d0*rstd, d1*rstd, d2*rstd, d3*rstd };
        #pragma unroll
        for (int j = 0; j < 4; j++) {
            __nv_bfloat16 h = __float2bfloat16_rn(dd[j]);
            __nv_bfloat16 l = __float2bfloat16_rn(dd[j] - __bfloat162float(h));
            uint32_t off = (uint32_t)(j >= 2) * 16384u
                         + SW128((uint32_t)(row*128 + (lane + 32*(j&1))*2));
            *(__nv_bfloat16*)(smc + off)         = h;
            *(__nv_bfloat16*)(smc + 32768 + off) = l;
        }
    }

    const int aRow = lane & 15;
    const int aK   = (lane >> 4) * 16;
    const int bRow = (lane & 7) + ((lane >> 4) << 3);
    const int bK   = ((lane >> 3) & 1) * 16;
    const int m0   = (wid & 3) * 32;
    const int n0   = (wid >> 2) * 32;

    for (int ct = 0; ct < 4; ct++) {
        const int ch0 = ct * 64;
        __syncthreads();
        // load weight chunk: 4 arrays x 64ch x 128k bf16
        const __nv_bfloat16* warr[4] = { g_wgh, g_wgl, g_wph, g_wpl };
        #pragma unroll
        for (int arr = 0; arr < 4; arr++) {
            #pragma unroll
            for (int q = 0; q < 4; q++) {
                int seg = t + 256*q;          // 0..1023
                int ch  = seg >> 4;
                int s8  = seg & 15;           // 16B segment (8 bf16)
                uint4 v = *(const uint4*)(warr[arr] + (size_t)(ch0 + ch)*128 + s8*8);
                uint32_t dst = 65536 + arr*16384 + ((s8 >= 8) ? 8192u : 0u)
                             + SW128((uint32_t)(ch*128 + (s8 & 7)*16));
                *(uint4*)(smc + dst) = v;
            }
        }
        __syncthreads();

        float accg[2][4][4], accp[2][4][4];
        #pragma unroll
        for (int m = 0; m < 2; m++)
            #pragma unroll
            for (int n = 0; n < 4; n++)
                #pragma unroll
                for (int e = 0; e < 4; e++) { accg[m][n][e] = 0.f; accp[m][n][e] = 0.f; }

        #pragma unroll
        for (int kk = 0; kk < 8; kk++) {
            const uint32_t halfA = (uint32_t)(kk >> 2) * 16384u;
            const uint32_t halfW = (uint32_t)(kk >> 2) * 8192u;
            const uint32_t k32   = (uint32_t)(kk & 3) * 32u;

            uint32_t ah[2][4], al[2][4];
            #pragma unroll
            for (int f = 0; f < 2; f++) {
                uint32_t off = SW128((uint32_t)((m0 + f*16 + aRow)*128) + k32 + aK);
                ldm4(uAh + halfA + off, ah[f]);
                ldm4(uAl + halfA + off, al[f]);
            }
            uint32_t gh[2][4], gl[2][4], ph[2][4], pl[2][4];
            #pragma unroll
            for (int c = 0; c < 2; c++) {
                uint32_t off = SW128((uint32_t)((n0 + c*16 + bRow)*128) + k32 + bK);
                ldm4(uW +     0 + halfW + off, gh[c]);
                ldm4(uW + 16384 + halfW + off, gl[c]);
                ldm4(uW + 32768 + halfW + off, ph[c]);
                ldm4(uW + 49152 + halfW + off, pl[c]);
            }
            #pragma unroll
            for (int m = 0; m < 2; m++)
                #pragma unroll
                for (int n = 0; n < 4; n++) {
                    int ci = n >> 1, bi = (n & 1) * 2;
                    mma16816(accg[m][n], ah[m], gh[ci][bi], gh[ci][bi+1]);
                    mma16816(accg[m][n], ah[m], gl[ci][bi], gl[ci][bi+1]);
                    mma16816(accg[m][n], al[m], gh[ci][bi], gh[ci][bi+1]);
                    mma16816(accp[m][n], ah[m], ph[ci][bi], ph[ci][bi+1]);
                    mma16816(accp[m][n], ah[m], pl[ci][bi], pl[ci][bi+1]);
                    mma16816(accp[m][n], al[m], ph[ci][bi], ph[ci][bi+1]);
                }
        }

        // epilogue -> stage (ch-major)
        #pragma unroll
        for (int m = 0; m < 2; m++) {
            int row0 = m0 + m*16 + (lane >> 2);
            #pragma unroll
            for (int n = 0; n < 4; n++) {
                int c0 = n0 + n*8 + (lane & 3)*2;
                float gb0 = __ldg(agb + ch0 + c0), gb1 = __ldg(agb + ch0 + c0 + 1);
                float pb0 = __ldg(apb + ch0 + c0), pb1 = __ldg(apb + ch0 + c0 + 1);
                float mv0 = sM[row0], mv1 = sM[row0 + 8];
                float vals[4];
                vals[0] = mv0 * sigmoidf_(accg[m][n][0] + gb0) * (accp[m][n][0] + pb0);
                vals[1] = mv0 * sigmoidf_(accg[m][n][1] + gb1) * (accp[m][n][1] + pb1);
                vals[2] = mv1 * sigmoidf_(accg[m][n][2] + gb0) * (accp[m][n][2] + pb0);
                vals[3] = mv1 * sigmoidf_(accg[m][n][3] + gb1) * (accp[m][n][3] + pb1);
                #pragma unroll
                for (int e = 0; e < 4; e++) {
                    int cc = c0 + (e & 1);
                    int rr = row0 + (e >> 1) * 8;
                    __nv_bfloat16 h = __float2bfloat16_rn(vals[e]);
                    stgH[cc*128 + rr] = h;
                    stgL[cc*128 + rr] = __float2bfloat16_rn(vals[e] - __bfloat162float(h));
                }
            }
        }
        __syncthreads();

        __nv_bfloat16* dstH = (ch0 < 128) ? (g_ah + (size_t)ch0 * NN)
                                          : (g_bh + (size_t)(ch0 - 128) * NN);
        __nv_bfloat16* dstL = (ch0 < 128) ? (g_al + (size_t)ch0 * NN)
                                          : (g_bl + (size_t)(ch0 - 128) * NN);
        #pragma unroll
        for (int q = 0; q < 4; q++) {
            int seg = t + 256*q;          // 0..1023
            int ch  = seg >> 4;
            int r8  = (seg & 15) * 8;
            uint4 vh = *(const uint4*)(stgH + ch*128 + r8);
            uint4 vl = *(const uint4*)(stgL + ch*128 + r8);
            size_t off = (size_t)ch * NN + r0 + r8;
            *(uint4*)(dstH + off) = vh;
            *(uint4*)(dstL + off) = vl;
        }
    }
}

// ============================================================================
// Kernel B: 128 batched NT GEMMs via HMMA bf16x3 split (unchanged from R3).
// ============================================================================
__global__ void __launch_bounds__(256) kB()
{
    extern __shared__ char smc[];
    const uint32_t sbase = smem_u32(smc);

    const int t    = threadIdx.x;
    const int lane = t & 31;
    const int wid  = t >> 5;
    const int d    = blockIdx.z;
    const int i0   = blockIdx.x * 128;
    const int j0   = blockIdx.y * 128;

    const int wm = wid & 1;
    const int wn = wid >> 1;
    const int m0 = wm * 64;
    const int n0 = wn * 32;

    const __nv_bfloat16* srcs[4] = {
        g_ah + (size_t)d*NN + (size_t)i0*NSEQ,
        g_al + (size_t)d*NN + (size_t)i0*NSEQ,
        g_bh + (size_t)d*NN + (size_t)j0*NSEQ,
        g_bl + (size_t)d*NN + (size_t)j0*NSEQ };

    auto issue = [&](int stage, int kc) {
        uint32_t sb = sbase + stage * 65536;
        #pragma unroll
        for (int T = 0; T < 4; T++) {
            const __nv_bfloat16* base = srcs[T];
            #pragma unroll
            for (int q = 0; q < 4; q++) {
                int seg = t + 256*q;
                int row = seg >> 3;
                int s   = seg & 7;
                uint32_t dst = sb + T*16384 + SW128((uint32_t)(row*128 + s*16));
                CP_ASYNC16(dst, base + (size_t)row*NSEQ + kc + s*8);
            }
        }
        CP_COMMIT();
    };

    float acc[4][4][4];
    #pragma unroll
    for (int m = 0; m < 4; m++)
        #pragma unroll
        for (int n = 0; n < 4; n++)
            #pragma unroll
            for (int e = 0; e < 4; e++) acc[m][n][e] = 0.0f;

    const int aRow = lane & 15;
    const int aK   = (lane >> 4) * 16;
    const int bRow = (lane & 7) + ((lane >> 4) << 3);
    const int bK   = ((lane >> 3) & 1) * 16;

    issue(0, 0);

    for (int ch = 0; ch < 8; ch++) {
        const int stage = ch & 1;
        if (ch < 7) { issue(stage ^ 1, (ch + 1) * 64); CP_WAIT(1); }
        else        { CP_WAIT(0); }
        __syncthreads();

        const uint32_t sb  = sbase + stage * 65536;
        const uint32_t sAh = sb;
        const uint32_t sAl = sb + 16384;
        const uint32_t sBh = sb + 32768;
        const uint32_t sBl = sb + 49152;

        #pragma unroll
        for (int kk = 0; kk < 4; kk++) {
            const uint32_t kOffA = (uint32_t)(kk*32) + aK;
            const uint32_t kOffB = (uint32_t)(kk*32) + bK;

            uint32_t bh[2][4], bl[2][4];
            #pragma unroll
            for (int c = 0; c < 2; c++) {
                uint32_t off = (uint32_t)((n0 + c*16 + bRow) * 128) + kOffB;
                ldm4(sBh + SW128(off), bh[c]);
            }
            uint32_t ah[4][4];
            #pragma unroll
            for (int f = 0; f < 4; f++) {
                uint32_t off = (uint32_t)((m0 + f*16 + aRow) * 128) + kOffA;
                ldm4(sAh + SW128(off), ah[f]);
            }
            #pragma unroll
            for (int m = 0; m < 4; m++)
                #pragma unroll
                for (int n = 0; n < 4; n++)
                    mma16816(acc[m][n], ah[m], bh[n>>1][(n&1)*2], bh[n>>1][(n&1)*2+1]);

            #pragma unroll
            for (int c = 0; c < 2; c++) {
                uint32_t off = (uint32_t)((n0 + c*16 + bRow) * 128) + kOffB;
                ldm4(sBl + SW128(off), bl[c]);
            }
            #pragma unroll
            for (int m = 0; m < 4; m++)
                #pragma unroll
                for (int n = 0; n < 4; n++)
                    mma16816(acc[m][n], ah[m], bl[n>>1][(n&1)*2], bl[n>>1][(n&1)*2+1]);

            uint32_t al[4][4];
            #pragma unroll
            for (int f = 0; f < 4; f++) {
                uint32_t off = (uint32_t)((m0 + f*16 + aRow) * 128) + kOffA;
                ldm4(sAl + SW128(off), al[f]);
            }
            #pragma unroll
            for (int m = 0; m < 4; m++)
                #pragma unroll
                for (int n = 0; n < 4; n++)
                    mma16816(acc[m][n], al[m], bh[n>>1][(n&1)*2], bh[n>>1][(n&1)*2+1]);
        }
        __syncthreads();
    }

    float* base = g_t + (size_t)d*NN;
    #pragma unroll
    for (int m = 0; m < 4; m++) {
        int r1 = i0 + m0 + m*16 + (lane >> 2);
        #pragma unroll
        for (int n = 0; n < 4; n++) {
            int c = j0 + n0 + n*8 + (lane & 3)*2;
            float2 lo = make_float2(acc[m][n][0], acc[m][n][1]);
            float2 hi = make_float2(acc[m][n][2], acc[m][n][3]);
            *(float2*)(base + (size_t)r1*NSEQ + c)       = lo;
            *(float2*)(base + (size_t)(r1+8)*NSEQ + c)   = hi;
        }
    }
}

// ============================================================================
// Kernel C (HMMA): out = sig(LN(pair)@ogw^T + ogb) * (LN(tri)@opw^T + opb)
// smem:
//   0      : A1 hi/lo (pair LN)  64KB   (hi: half*16384; lo at +32768)
//   65536  : A2 hi/lo (tri LN)   64KB
//   131072 : sTmp fp32 128x132 (67.6KB) -- reused as W (64KB) during compute
// ============================================================================
__global__ void __launch_bounds__(256) kC(
    const float* __restrict__ pair,
    const float* __restrict__ opb, const float* __restrict__ ogb,
    float* __restrict__ out)
{
    extern __shared__ char smc[];
    const uint32_t sbase = smem_u32(smc);
    const uint32_t uA1 = sbase;
    const uint32_t uA2 = sbase + 65536;
    const uint32_t uW  = sbase + 131072;
    float* sTmp = (float*)(smc + 131072);

    const int t    = threadIdx.x;
    const int lane = t & 31;
    const int wid  = t >> 5;
    const int r0   = blockIdx.x * 128;

    // pair LN -> A1 tiles (register path)
    for (int row = wid; row < 128; row += 8) {
        const float* src = pair + (size_t)(r0 + row) * DDIM;
        float x[4] = { src[lane], src[lane+32], src[lane+64], src[lane+96] };
        float s = x[0] + x[1] + x[2] + x[3];
        #pragma unroll
        for (int o = 16; o > 0; o >>= 1) s += __shfl_xor_sync(0xffffffffu, s, o);
        float mu = s * (1.0f/128.0f);
        float d0 = x[0]-mu, d1 = x[1]-mu, d2 = x[2]-mu, d3 = x[3]-mu;
        float v = d0*d0 + d1*d1 + d2*d2 + d3*d3;
        #pragma unroll
        for (int o = 16; o > 0; o >>= 1) v += __shfl_xor_sync(0xffffffffu, v, o);
        float rstd = rsqrtf(v * (1.0f/128.0f) + 1e-5f);
        float dd[4] = { d0*rstd, d1*rstd, d2*rstd, d3*rstd };
        #pragma unroll
        for (int j = 0; j < 4; j++) {
            __nv_bfloat16 h = __float2bfloat16_rn(dd[j]);
            __nv_bfloat16 l = __float2bfloat16_rn(dd[j] - __bfloat162float(h));
            uint32_t off = (uint32_t)(j >= 2) * 16384u
                         + SW128((uint32_t)(row*128 + (lane + 32*(j&1))*2));
            *(__nv_bfloat16*)(smc + off)         = h;
            *(__nv_bfloat16*)(smc + 32768 + off) = l;
        }
    }

    // tri -> sTmp [d][132+r], LN, transpose -> A2 tiles
    #pragma unroll
    for (int m = 0; m < 16; m++) {
        int q = t + 256*m;
        int dd = q >> 5;
        int r4 = (q & 31) * 4;
        float4 f = *(const float4*)(g_t + (size_t)dd*NN + r0 + r4);
        *(float4*)&sTmp[dd*132 + r4] = f;
    }
    __syncthreads();
    for (int row = wid; row < 128; row += 8) ln_col(sTmp, row, lane);
    __syncthreads();
    for (int row = wid; row < 128; row += 8) {
        #pragma unroll
        for (int j = 0; j < 4; j++) {
            int k = lane + 32*j;
            float v = sTmp[k*132 + row];
            __nv_bfloat16 h = __float2bfloat16_rn(v);
            __nv_bfloat16 l = __float2bfloat16_rn(v - __bfloat162float(h));
            uint32_t off = (uint32_t)(j >= 2) * 16384u
                         + SW128((uint32_t)(row*128 + (lane + 32*(j&1))*2));
            *(__nv_bfloat16*)(smc + 65536 + off)         = h;
            *(__nv_bfloat16*)(smc + 65536 + 32768 + off) = l;
        }
    }

    const int aRow = lane & 15;
    const int aK   = (lane >> 4) * 16;
    const int bRow = (lane & 7) + ((lane >> 4) << 3);
    const int bK   = ((lane >> 3) & 1) * 16;
    const int m0   = (wid & 3) * 32;
    const int n0   = (wid >> 2) * 32;

    for (int ot = 0; ot < 2; ot++) {
        const int o0 = ot * 64;
        __syncthreads();   // sTmp free / previous chunk done
        const __nv_bfloat16* warr[4] = { g_ogh, g_ogl, g_oph, g_opl };
        #pragma unroll
        for (int arr = 0; arr < 4; arr++) {
            #pragma unroll
            for (int q = 0; q < 4; q++) {
                int seg = t + 256*q;
                int ch  = seg >> 4;
                int s8  = seg & 15;
                uint4 v = *(const uint4*)(warr[arr] + (size_t)(o0 + ch)*128 + s8*8);
                uint32_t dst = 131072 + arr*16384 + ((s8 >= 8) ? 8192u : 0u)
                             + SW128((uint32_t)(ch*128 + (s8 & 7)*16));
                *(uint4*)(smc + dst) = v;
            }
        }
        __syncthreads();

        float accg[2][4][4], accp[2][4][4];
        #pragma unroll
        for (int m = 0; m < 2; m++)
            #pragma unroll
            for (int n = 0; n < 4; n++)
                #pragma unroll
                for (int e = 0; e < 4; e++) { accg[m][n][e] = 0.f; accp[m][n][e] = 0.f; }

        #pragma unroll
        for (int kk = 0; kk < 8; kk++) {
            const uint32_t halfA = (uint32_t)(kk >> 2) * 16384u;
            const uint32_t halfW = (uint32_t)(kk >> 2) * 8192u;
            const uint32_t k32   = (uint32_t)(kk & 3) * 32u;

            uint32_t a1h[2][4], a1l[2][4], a2h[2][4], a2l[2][4];
            #pragma unroll
            for (int f = 0; f < 2; f++) {
                uint32_t off = SW128((uint32_t)((m0 + f*16 + aRow)*128) + k32 + aK);
                ldm4(uA1 +         halfA + off, a1h[f]);
                ldm4(uA1 + 32768 + halfA + off, a1l[f]);
                ldm4(uA2 +         halfA + off, a2h[f]);
                ldm4(uA2 + 32768 + halfA + off, a2l[f]);
            }
            uint32_t gh[2][4], gl[2][4], ph[2][4], pl[2][4];
            #pragma unroll
            for (int c = 0; c < 2; c++) {
                uint32_t off = SW128((uint32_t)((n0 + c*16 + bRow)*128) + k32 + bK);
                ldm4(uW +     0 + halfW + off, gh[c]);
                ldm4(uW + 16384 + halfW + off, gl[c]);
                ldm4(uW + 32768 + halfW + off, ph[c]);
                ldm4(uW + 49152 + halfW + off, pl[c]);
            }
            #pragma unroll
            for (int m = 0; m < 2; m++)
                #pragma unroll
                for (int n = 0; n < 4; n++) {
                    int ci = n >> 1, bi = (n & 1) * 2;
                    mma16816(accg[m][n], a1h[m], gh[ci][bi], gh[ci][bi+1]);
                    mma16816(accg[m][n], a1h[m], gl[ci][bi], gl[ci][bi+1]);
                    mma16816(accg[m][n], a1l[m], gh[ci][bi], gh[ci][bi+1]);
                    mma16816(accp[m][n], a2h[m], ph[ci][bi], ph[ci][bi+1]);
                    mma16816(accp[m][n], a2h[m], pl[ci][bi], pl[ci][bi+1]);
                    mma16816(accp[m][n], a2l[m], ph[ci][bi], ph[ci][bi+1]);
                }
        }

        // epilogue: direct float2 stores
        #pragma unroll
        for (int m = 0; m < 2; m++) {
            int row0 = m0 + m*16 + (lane >> 2);
            #pragma unroll
            for (int n = 0; n < 4; n++) {
                int c0 = n0 + n*8 + (lane & 3)*2;
                float gb0 = __ldg(ogb + o0 + c0), gb1 = __ldg(ogb + o0 + c0 + 1);
                float pb0 = __ldg(opb + o0 + c0), pb1 = __ldg(opb + o0 + c0 + 1);
                float2 v0, v1;
                v0.x = sigmoidf_(accg[m][n][0] + gb0) * (accp[m][n][0] + pb0);
                v0.y = sigmoidf_(accg[m][n][1] + gb1) * (accp[m][n][1] + pb1);
                v1.x = sigmoidf_(accg[m][n][2] + gb0) * (accp[m][n][2] + pb0);
                v1.y = sigmoidf_(accg[m][n][3] + gb1) * (accp[m][n][3] + pb1);
                *(float2*)(out + (size_t)(r0 + row0)*DDIM + o0 + c0)     = v0;
                *(float2*)(out + (size_t)(r0 + row0 + 8)*DDIM + o0 + c0) = v1;
            }
        }
    }
}

// ============================================================================
extern "C" void kernel_launch(void* const* d_in, const int* in_sizes, int n_in,
                              void* d_out, int out_size)
{
    const float* pair = (const float*)d_in[0];
    const float* mask = (const float*)d_in[1];
    const float* apw  = (const float*)d_in[2];
    const float* apb  = (const float*)d_in[3];
    const float* agw  = (const float*)d_in[4];
    const float* agb  = (const float*)d_in[5];
    const float* opw  = (const float*)d_in[6];
    const float* opb  = (const float*)d_in[7];
    const float* ogw  = (const float*)d_in[8];
    const float* ogb  = (const float*)d_in[9];
    float* out = (float*)d_out;

    const size_t smA = 164352;          // 160.5 KB
    const size_t smB = 131072;          // 128 KB
    const size_t smC = 131072 + 67584;  // 194 KB
    cudaFuncSetAttribute(kA, cudaFuncAttributeMaxDynamicSharedMemorySize, (int)smA);
    cudaFuncSetAttribute(kB, cudaFuncAttributeMaxDynamicSharedMemorySize, (int)smB);
    cudaFuncSetAttribute(kC, cudaFuncAttributeMaxDynamicSharedMemorySize, (int)smC);

    kW<<<128, 256>>>(agw, apw, ogw, opw);
    kA<<<NN/128, 256, smA>>>(pair, mask, apb, agb);
    kB<<<dim3(4, 4, DDIM), 256, smB>>>();
    kC<<<NN/128, 256, smC>>>(pair, opb, ogb, out);
}

// round 5
// speedup vs baseline: 2.3428x; 1.2496x over previous
#include <cuda_runtime.h>
#include <cuda_bf16.h>
#include <cstdint>
#include <cstddef>

#define NSEQ 512
#define DDIM 128
#define NN   (NSEQ*NSEQ)

typedef unsigned long long ull;

// Scratch: a,b as bf16 hi/lo, channel-major [d][i][k]; tri fp32 [d][i][j]
static __device__ __nv_bfloat16 g_ah[(size_t)DDIM * NN];
static __device__ __nv_bfloat16 g_al[(size_t)DDIM * NN];
static __device__ __nv_bfloat16 g_bh[(size_t)DDIM * NN];
static __device__ __nv_bfloat16 g_bl[(size_t)DDIM * NN];
static __device__ float g_t[(size_t)DDIM * NN];

// Pre-split weights (bf16 hi/lo), row-major [ch][k]
static __device__ __nv_bfloat16 g_wgh[256*128], g_wgl[256*128];
static __device__ __nv_bfloat16 g_wph[256*128], g_wpl[256*128];
static __device__ __nv_bfloat16 g_ogh[128*128], g_ogl[128*128];
static __device__ __nv_bfloat16 g_oph[128*128], g_opl[128*128];

__device__ __forceinline__ float sigmoidf_(float x) { return 1.0f / (1.0f + __expf(-x)); }

__device__ __forceinline__ uint32_t smem_u32(const void* p) {
    uint32_t a;
    asm("{ .reg .u64 t; cvta.to.shared.u64 t, %1; cvt.u32.u64 %0, t; }" : "=r"(a) : "l"(p));
    return a;
}
#define SW128(o) ((o) ^ (((o) >> 3) & 0x70))

#define CP_ASYNC16(dst, src) \
    asm volatile("cp.async.cg.shared.global [%0], [%1], 16;" :: "r"(dst), "l"(src) : "memory")
#define CP_COMMIT() asm volatile("cp.async.commit_group;" ::: "memory")
#define CP_WAIT(n)  asm volatile("cp.async.wait_group %0;" :: "n"(n) : "memory")

__device__ __forceinline__ void ldm4(uint32_t addr, uint32_t r[4]) {
    asm volatile("ldmatrix.sync.aligned.m8n8.x4.shared.b16 {%0,%1,%2,%3}, [%4];"
        : "=r"(r[0]), "=r"(r[1]), "=r"(r[2]), "=r"(r[3]) : "r"(addr));
}
__device__ __forceinline__ void mma16816(float c[4], const uint32_t a[4],
                                         uint32_t b0, uint32_t b1) {
    asm volatile(
        "mma.sync.aligned.m16n8k16.row.col.f32.bf16.bf16.f32 "
        "{%0,%1,%2,%3}, {%4,%5,%6,%7}, {%8,%9}, {%0,%1,%2,%3};"
        : "+f"(c[0]), "+f"(c[1]), "+f"(c[2]), "+f"(c[3])
        : "r"(a[0]), "r"(a[1]), "r"(a[2]), "r"(a[3]), "r"(b0), "r"(b1));
}

// LayerNorm of one logical row stored as a column: s[d*132 + row]
__device__ __forceinline__ void ln_col(float* s, int row, int lane) {
    float x0 = s[(lane      )*132 + row];
    float x1 = s[(lane + 32 )*132 + row];
    float x2 = s[(lane + 64 )*132 + row];
    float x3 = s[(lane + 96 )*132 + row];
    float sum = x0 + x1 + x2 + x3;
    #pragma unroll
    for (int o = 16; o > 0; o >>= 1) sum += __shfl_xor_sync(0xffffffffu, sum, o);
    float mu = sum * (1.0f/128.0f);
    float d0 = x0-mu, d1 = x1-mu, d2 = x2-mu, d3 = x3-mu;
    float v = d0*d0 + d1*d1 + d2*d2 + d3*d3;
    #pragma unroll
    for (int o = 16; o > 0; o >>= 1) v += __shfl_xor_sync(0xffffffffu, v, o);
    float rstd = rsqrtf(v * (1.0f/128.0f) + 1e-5f);
    s[(lane      )*132 + row] = d0 * rstd;
    s[(lane + 32 )*132 + row] = d1 * rstd;
    s[(lane + 64 )*132 + row] = d2 * rstd;
    s[(lane + 96 )*132 + row] = d3 * rstd;
}

// ============================================================================
__global__ void __launch_bounds__(256) kW(
    const float* __restrict__ agw, const float* __restrict__ apw,
    const float* __restrict__ ogw, const float* __restrict__ opw)
{
    int i = blockIdx.x * 256 + threadIdx.x;
    if (i < 256*128) {
        float g = agw[i];
        __nv_bfloat16 gh = __float2bfloat16_rn(g);
        g_wgh[i] = gh; g_wgl[i] = __float2bfloat16_rn(g - __bfloat162float(gh));
        float p = apw[i];
        __nv_bfloat16 ph = __float2bfloat16_rn(p);
        g_wph[i] = ph; g_wpl[i] = __float2bfloat16_rn(p - __bfloat162float(ph));
    }
    if (i < 128*128) {
        float g = ogw[i];
        __nv_bfloat16 gh = __float2bfloat16_rn(g);
        g_ogh[i] = gh; g_ogl[i] = __float2bfloat16_rn(g - __bfloat162float(gh));
        float p = opw[i];
        __nv_bfloat16 ph = __float2bfloat16_rn(p);
        g_oph[i] = ph; g_opl[i] = __float2bfloat16_rn(p - __bfloat162float(ph));
    }
}

// ============================================================================
// Kernel A (HMMA, 512 thr): LN(pair) -> gate/proj bf16x3 -> ab channel-major
// smem: A hi 32K | A lo 32K | W 64K | stage hi 16K | stage lo 16K | mask
// ============================================================================
__global__ void __launch_bounds__(512) kA(
    const float* __restrict__ pair, const float* __restrict__ mask,
    const float* __restrict__ apb, const float* __restrict__ agb)
{
    extern __shared__ char smc[];
    const uint32_t sbase = smem_u32(smc);
    const uint32_t uAh = sbase;
    const uint32_t uAl = sbase + 32768;
    const uint32_t uW  = sbase + 65536;
    float* sM = (float*)(smc + 163840);
    __nv_bfloat16* stgH = (__nv_bfloat16*)(smc + 131072);
    __nv_bfloat16* stgL = (__nv_bfloat16*)(smc + 147456);

    const int t    = threadIdx.x;
    const int lane = t & 31;
    const int wid  = t >> 5;
    const int r0   = blockIdx.x * 128;

    if (t < 128) sM[t] = mask[r0 + t];

    // LN + bf16 split -> A tiles
    for (int row = wid; row < 128; row += 16) {
        const float* src = pair + (size_t)(r0 + row) * DDIM;
        float x[4] = { src[lane], src[lane+32], src[lane+64], src[lane+96] };
        float s = x[0] + x[1] + x[2] + x[3];
        #pragma unroll
        for (int o = 16; o > 0; o >>= 1) s += __shfl_xor_sync(0xffffffffu, s, o);
        float mu = s * (1.0f/128.0f);
        float d0 = x[0]-mu, d1 = x[1]-mu, d2 = x[2]-mu, d3 = x[3]-mu;
        float v = d0*d0 + d1*d1 + d2*d2 + d3*d3;
        #pragma unroll
        for (int o = 16; o > 0; o >>= 1) v += __shfl_xor_sync(0xffffffffu, v, o);
        float rstd = rsqrtf(v * (1.0f/128.0f) + 1e-5f);
        float dd[4] = { d0*rstd, d1*rstd, d2*rstd, d3*rstd };
        #pragma unroll
        for (int j = 0; j < 4; j++) {
            __nv_bfloat16 h = __float2bfloat16_rn(dd[j]);
            __nv_bfloat16 l = __float2bfloat16_rn(dd[j] - __bfloat162float(h));
            uint32_t off = (uint32_t)(j >= 2) * 16384u
                         + SW128((uint32_t)(row*128 + (lane + 32*(j&1))*2));
            *(__nv_bfloat16*)(smc + off)         = h;
            *(__nv_bfloat16*)(smc + 32768 + off) = l;
        }
    }

    const int aRow = lane & 15;
    const int aK   = (lane >> 4) * 16;
    const int bRow = (lane & 7) + ((lane >> 4) << 3);
    const int bK   = ((lane >> 3) & 1) * 16;
    const int m0   = (wid & 3) * 32;
    const int n0   = (wid >> 2) * 16;

    for (int ct = 0; ct < 4; ct++) {
        const int ch0 = ct * 64;
        __syncthreads();
        const __nv_bfloat16* warr[4] = { g_wgh, g_wgl, g_wph, g_wpl };
        #pragma unroll
        for (int arr = 0; arr < 4; arr++) {
            #pragma unroll
            for (int q = 0; q < 2; q++) {
                int seg = t + 512*q;
                int ch  = seg >> 4;
                int s8  = seg & 15;
                uint4 v = *(const uint4*)(warr[arr] + (size_t)(ch0 + ch)*128 + s8*8);
                uint32_t dst = 65536 + arr*16384 + ((s8 >= 8) ? 8192u : 0u)
                             + SW128((uint32_t)(ch*128 + (s8 & 7)*16));
                *(uint4*)(smc + dst) = v;
            }
        }
        __syncthreads();

        float accg[2][2][4], accp[2][2][4];
        #pragma unroll
        for (int m = 0; m < 2; m++)
            #pragma unroll
            for (int n = 0; n < 2; n++)
                #pragma unroll
                for (int e = 0; e < 4; e++) { accg[m][n][e] = 0.f; accp[m][n][e] = 0.f; }

        #pragma unroll
        for (int kk = 0; kk < 8; kk++) {
            const uint32_t halfA = (uint32_t)(kk >> 2) * 16384u;
            const uint32_t halfW = (uint32_t)(kk >> 2) * 8192u;
            const uint32_t k32   = (uint32_t)(kk & 3) * 32u;

            uint32_t ah[2][4], al[2][4];
            #pragma unroll
            for (int f = 0; f < 2; f++) {
                uint32_t off = SW128((uint32_t)((m0 + f*16 + aRow)*128) + k32 + aK);
                ldm4(uAh + halfA + off, ah[f]);
                ldm4(uAl + halfA + off, al[f]);
            }
            uint32_t gh[4], gl[4], ph[4], pl[4];
            {
                uint32_t off = SW128((uint32_t)((n0 + bRow)*128) + k32 + bK);
                ldm4(uW +     0 + halfW + off, gh);
                ldm4(uW + 16384 + halfW + off, gl);
                ldm4(uW + 32768 + halfW + off, ph);
                ldm4(uW + 49152 + halfW + off, pl);
            }
            #pragma unroll
            for (int m = 0; m < 2; m++)
                #pragma unroll
                for (int n = 0; n < 2; n++) {
                    int bi = n * 2;
                    mma16816(accg[m][n], ah[m], gh[bi], gh[bi+1]);
                    mma16816(accg[m][n], ah[m], gl[bi], gl[bi+1]);
                    mma16816(accg[m][n], al[m], gh[bi], gh[bi+1]);
                    mma16816(accp[m][n], ah[m], ph[bi], ph[bi+1]);
                    mma16816(accp[m][n], ah[m], pl[bi], pl[bi+1]);
                    mma16816(accp[m][n], al[m], ph[bi], ph[bi+1]);
                }
        }

        #pragma unroll
        for (int m = 0; m < 2; m++) {
            int row0 = m0 + m*16 + (lane >> 2);
            #pragma unroll
            for (int n = 0; n < 2; n++) {
                int c0 = n0 + n*8 + (lane & 3)*2;
                float gb0 = __ldg(agb + ch0 + c0), gb1 = __ldg(agb + ch0 + c0 + 1);
                float pb0 = __ldg(apb + ch0 + c0), pb1 = __ldg(apb + ch0 + c0 + 1);
                float mv0 = sM[row0], mv1 = sM[row0 + 8];
                float vals[4];
                vals[0] = mv0 * sigmoidf_(accg[m][n][0] + gb0) * (accp[m][n][0] + pb0);
                vals[1] = mv0 * sigmoidf_(accg[m][n][1] + gb1) * (accp[m][n][1] + pb1);
                vals[2] = mv1 * sigmoidf_(accg[m][n][2] + gb0) * (accp[m][n][2] + pb0);
                vals[3] = mv1 * sigmoidf_(accg[m][n][3] + gb1) * (accp[m][n][3] + pb1);
                #pragma unroll
                for (int e = 0; e < 4; e++) {
                    int cc = c0 + (e & 1);
                    int rr = row0 + (e >> 1) * 8;
                    __nv_bfloat16 h = __float2bfloat16_rn(vals[e]);
                    stgH[cc*128 + rr] = h;
                    stgL[cc*128 + rr] = __float2bfloat16_rn(vals[e] - __bfloat162float(h));
                }
            }
        }
        __syncthreads();

        __nv_bfloat16* dstH = (ch0 < 128) ? (g_ah + (size_t)ch0 * NN)
                                          : (g_bh + (size_t)(ch0 - 128) * NN);
        __nv_bfloat16* dstL = (ch0 < 128) ? (g_al + (size_t)ch0 * NN)
                                          : (g_bl + (size_t)(ch0 - 128) * NN);
        #pragma unroll
        for (int q = 0; q < 2; q++) {
            int seg = t + 512*q;
            int ch  = seg >> 4;
            int r8  = (seg & 15) * 8;
            uint4 vh = *(const uint4*)(stgH + ch*128 + r8);
            uint4 vl = *(const uint4*)(stgL + ch*128 + r8);
            size_t off = (size_t)ch * NN + r0 + r8;
            *(uint4*)(dstH + off) = vh;
            *(uint4*)(dstL + off) = vl;
        }
    }
}

// ============================================================================
// Kernel B (512 thr): 128 batched NT GEMMs via HMMA bf16x3.
// 16 warps 4m x 4n, warp tile 32x32.
// ============================================================================
__global__ void __launch_bounds__(512) kB()
{
    extern __shared__ char smc[];
    const uint32_t sbase = smem_u32(smc);

    const int t    = threadIdx.x;
    const int lane = t & 31;
    const int wid  = t >> 5;
    const int d    = blockIdx.z;
    const int i0   = blockIdx.x * 128;
    const int j0   = blockIdx.y * 128;

    const int m0 = (wid & 3) * 32;
    const int n0 = (wid >> 2) * 32;

    const __nv_bfloat16* srcs[4] = {
        g_ah + (size_t)d*NN + (size_t)i0*NSEQ,
        g_al + (size_t)d*NN + (size_t)i0*NSEQ,
        g_bh + (size_t)d*NN + (size_t)j0*NSEQ,
        g_bl + (size_t)d*NN + (size_t)j0*NSEQ };

    auto issue = [&](int stage, int kc) {
        uint32_t sb = sbase + stage * 65536;
        #pragma unroll
        for (int T = 0; T < 4; T++) {
            const __nv_bfloat16* base = srcs[T];
            #pragma unroll
            for (int q = 0; q < 2; q++) {
                int seg = t + 512*q;
                int row = seg >> 3;
                int s   = seg & 7;
                uint32_t dst = sb + T*16384 + SW128((uint32_t)(row*128 + s*16));
                CP_ASYNC16(dst, base + (size_t)row*NSEQ + kc + s*8);
            }
        }
        CP_COMMIT();
    };

    float acc[2][4][4];
    #pragma unroll
    for (int m = 0; m < 2; m++)
        #pragma unroll
        for (int n = 0; n < 4; n++)
            #pragma unroll
            for (int e = 0; e < 4; e++) acc[m][n][e] = 0.0f;

    const int aRow = lane & 15;
    const int aK   = (lane >> 4) * 16;
    const int bRow = (lane & 7) + ((lane >> 4) << 3);
    const int bK   = ((lane >> 3) & 1) * 16;

    issue(0, 0);

    for (int ch = 0; ch < 8; ch++) {
        const int stage = ch & 1;
        if (ch < 7) { issue(stage ^ 1, (ch + 1) * 64); CP_WAIT(1); }
        else        { CP_WAIT(0); }
        __syncthreads();

        const uint32_t sb  = sbase + stage * 65536;
        const uint32_t sAh = sb;
        const uint32_t sAl = sb + 16384;
        const uint32_t sBh = sb + 32768;
        const uint32_t sBl = sb + 49152;

        #pragma unroll
        for (int kk = 0; kk < 4; kk++) {
            const uint32_t kOffA = (uint32_t)(kk*32) + aK;
            const uint32_t kOffB = (uint32_t)(kk*32) + bK;

            uint32_t bh[2][4], bl[2][4];
            #pragma unroll
            for (int c = 0; c < 2; c++) {
                uint32_t off = (uint32_t)((n0 + c*16 + bRow) * 128) + kOffB;
                ldm4(sBh + SW128(off), bh[c]);
                ldm4(sBl + SW128(off), bl[c]);
            }
            uint32_t ah[2][4], al[2][4];
            #pragma unroll
            for (int f = 0; f < 2; f++) {
                uint32_t off = (uint32_t)((m0 + f*16 + aRow) * 128) + kOffA;
                ldm4(sAh + SW128(off), ah[f]);
                ldm4(sAl + SW128(off), al[f]);
            }
            #pragma unroll
            for (int m = 0; m < 2; m++)
                #pragma unroll
                for (int n = 0; n < 4; n++) {
                    int ci = n >> 1, bi = (n & 1) * 2;
                    mma16816(acc[m][n], ah[m], bh[ci][bi], bh[ci][bi+1]);
                    mma16816(acc[m][n], ah[m], bl[ci][bi], bl[ci][bi+1]);
                    mma16816(acc[m][n], al[m], bh[ci][bi], bh[ci][bi+1]);
                }
        }
        __syncthreads();
    }

    float* base = g_t + (size_t)d*NN;
    #pragma unroll
    for (int m = 0; m < 2; m++) {
        int r1 = i0 + m0 + m*16 + (lane >> 2);
        #pragma unroll
        for (int n = 0; n < 4; n++) {
            int c = j0 + n0 + n*8 + (lane & 3)*2;
            float2 lo = make_float2(acc[m][n][0], acc[m][n][1]);
            float2 hi = make_float2(acc[m][n][2], acc[m][n][3]);
            *(float2*)(base + (size_t)r1*NSEQ + c)       = lo;
            *(float2*)(base + (size_t)(r1+8)*NSEQ + c)   = hi;
        }
    }
}

// ============================================================================
// Kernel C (HMMA, 512 thr): out = sig(LN(pair)@ogw^T+ogb)*(LN(tri)@opw^T+opb)
// smem: A1 hi/lo 64K | A2 hi/lo 64K | sTmp fp32 (67.6K) reused as W (64K)
// ============================================================================
__global__ void __launch_bounds__(512) kC(
    const float* __restrict__ pair,
    const float* __restrict__ opb, const float* __restrict__ ogb,
    float* __restrict__ out)
{
    extern __shared__ char smc[];
    const uint32_t sbase = smem_u32(smc);
    const uint32_t uA1 = sbase;
    const uint32_t uA2 = sbase + 65536;
    const uint32_t uW  = sbase + 131072;
    float* sTmp = (float*)(smc + 131072);

    const int t    = threadIdx.x;
    const int lane = t & 31;
    const int wid  = t >> 5;
    const int r0   = blockIdx.x * 128;

    for (int row = wid; row < 128; row += 16) {
        const float* src = pair + (size_t)(r0 + row) * DDIM;
        float x[4] = { src[lane], src[lane+32], src[lane+64], src[lane+96] };
        float s = x[0] + x[1] + x[2] + x[3];
        #pragma unroll
        for (int o = 16; o > 0; o >>= 1) s += __shfl_xor_sync(0xffffffffu, s, o);
        float mu = s * (1.0f/128.0f);
        float d0 = x[0]-mu, d1 = x[1]-mu, d2 = x[2]-mu, d3 = x[3]-mu;
        float v = d0*d0 + d1*d1 + d2*d2 + d3*d3;
        #pragma unroll
        for (int o = 16; o > 0; o >>= 1) v += __shfl_xor_sync(0xffffffffu, v, o);
        float rstd = rsqrtf(v * (1.0f/128.0f) + 1e-5f);
        float dd[4] = { d0*rstd, d1*rstd, d2*rstd, d3*rstd };
        #pragma unroll
        for (int j = 0; j < 4; j++) {
            __nv_bfloat16 h = __float2bfloat16_rn(dd[j]);
            __nv_bfloat16 l = __float2bfloat16_rn(dd[j] - __bfloat162float(h));
            uint32_t off = (uint32_t)(j >= 2) * 16384u
                         + SW128((uint32_t)(row*128 + (lane + 32*(j&1))*2));
            *(__nv_bfloat16*)(smc + off)         = h;
            *(__nv_bfloat16*)(smc + 32768 + off) = l;
        }
    }

    #pragma unroll
    for (int m = 0; m < 8; m++) {
        int q = t + 512*m;
        int dd = q >> 5;
        int r4 = (q & 31) * 4;
        float4 f = *(const float4*)(g_t + (size_t)dd*NN + r0 + r4);
        *(float4*)&sTmp[dd*132 + r4] = f;
    }
    __syncthreads();
    for (int row = wid; row < 128; row += 16) ln_col(sTmp, row, lane);
    __syncthreads();
    for (int row = wid; row < 128; row += 16) {
        #pragma unroll
        for (int j = 0; j < 4; j++) {
            int k = lane + 32*j;
            float v = sTmp[k*132 + row];
            __nv_bfloat16 h = __float2bfloat16_rn(v);
            __nv_bfloat16 l = __float2bfloat16_rn(v - __bfloat162float(h));
            uint32_t off = (uint32_t)(j >= 2) * 16384u
                         + SW128((uint32_t)(row*128 + (lane + 32*(j&1))*2));
            *(__nv_bfloat16*)(smc + 65536 + off)         = h;
            *(__nv_bfloat16*)(smc + 65536 + 32768 + off) = l;
        }
    }

    const int aRow = lane & 15;
    const int aK   = (lane >> 4) * 16;
    const int bRow = (lane & 7) + ((lane >> 4) << 3);
    const int bK   = ((lane >> 3) & 1) * 16;
    const int m0   = (wid & 3) * 32;
    const int n0   = (wid >> 2) * 16;

    for (int ot = 0; ot < 2; ot++) {
        const int o0 = ot * 64;
        __syncthreads();
        const __nv_bfloat16* warr[4] = { g_ogh, g_ogl, g_oph, g_opl };
        #pragma unroll
        for (int arr = 0; arr < 4; arr++) {
            #pragma unroll
            for (int q = 0; q < 2; q++) {
                int seg = t + 512*q;
                int ch  = seg >> 4;
                int s8  = seg & 15;
                uint4 v = *(const uint4*)(warr[arr] + (size_t)(o0 + ch)*128 + s8*8);
                uint32_t dst = 131072 + arr*16384 + ((s8 >= 8) ? 8192u : 0u)
                             + SW128((uint32_t)(ch*128 + (s8 & 7)*16));
                *(uint4*)(smc + dst) = v;
            }
        }
        __syncthreads();

        float accg[2][2][4], accp[2][2][4];
        #pragma unroll
        for (int m = 0; m < 2; m++)
            #pragma unroll
            for (int n = 0; n < 2; n++)
                #pragma unroll
                for (int e = 0; e < 4; e++) { accg[m][n][e] = 0.f; accp[m][n][e] = 0.f; }

        #pragma unroll
        for (int kk = 0; kk < 8; kk++) {
            const uint32_t halfA = (uint32_t)(kk >> 2) * 16384u;
            const uint32_t halfW = (uint32_t)(kk >> 2) * 8192u;
            const uint32_t k32   = (uint32_t)(kk & 3) * 32u;

            uint32_t a1h[2][4], a1l[2][4], a2h[2][4], a2l[2][4];
            #pragma unroll
            for (int f = 0; f < 2; f++) {
                uint32_t off = SW128((uint32_t)((m0 + f*16 + aRow)*128) + k32 + aK);
                ldm4(uA1 +         halfA + off, a1h[f]);
                ldm4(uA1 + 32768 + halfA + off, a1l[f]);
                ldm4(uA2 +         halfA + off, a2h[f]);
                ldm4(uA2 + 32768 + halfA + off, a2l[f]);
            }
            uint32_t gh[4], gl[4], ph[4], pl[4];
            {
                uint32_t off = SW128((uint32_t)((n0 + bRow)*128) + k32 + bK);
                ldm4(uW +     0 + halfW + off, gh);
                ldm4(uW + 16384 + halfW + off, gl);
                ldm4(uW + 32768 + halfW + off, ph);
                ldm4(uW + 49152 + halfW + off, pl);
            }
            #pragma unroll
            for (int m = 0; m < 2; m++)
                #pragma unroll
                for (int n = 0; n < 2; n++) {
                    int bi = n * 2;
                    mma16816(accg[m][n], a1h[m], gh[bi], gh[bi+1]);
                    mma16816(accg[m][n], a1h[m], gl[bi], gl[bi+1]);
                    mma16816(accg[m][n], a1l[m], gh[bi], gh[bi+1]);
                    mma16816(accp[m][n], a2h[m], ph[bi], ph[bi+1]);
                    mma16816(accp[m][n], a2h[m], pl[bi], pl[bi+1]);
                    mma16816(accp[m][n], a2l[m], ph[bi], ph[bi+1]);
                }
        }

        #pragma unroll
        for (int m = 0; m < 2; m++) {
            int row0 = m0 + m*16 + (lane >> 2);
            #pragma unroll
            for (int n = 0; n < 2; n++) {
                int c0 = n0 + n*8 + (lane & 3)*2;
                float gb0 = __ldg(ogb + o0 + c0), gb1 = __ldg(ogb + o0 + c0 + 1);
                float pb0 = __ldg(opb + o0 + c0), pb1 = __ldg(opb + o0 + c0 + 1);
                float2 v0, v1;
                v0.x = sigmoidf_(accg[m][n][0] + gb0) * (accp[m][n][0] + pb0);
                v0.y = sigmoidf_(accg[m][n][1] + gb1) * (accp[m][n][1] + pb1);
                v1.x = sigmoidf_(accg[m][n][2] + gb0) * (accp[m][n][2] + pb0);
                v1.y = sigmoidf_(accg[m][n][3] + gb1) * (accp[m][n][3] + pb1);
                *(float2*)(out + (size_t)(r0 + row0)*DDIM + o0 + c0)     = v0;
                *(float2*)(out + (size_t)(r0 + row0 + 8)*DDIM + o0 + c0) = v1;
            }
        }
    }
}

// ============================================================================
extern "C" void kernel_launch(void* const* d_in, const int* in_sizes, int n_in,
                              void* d_out, int out_size)
{
    const float* pair = (const float*)d_in[0];
    const float* mask = (const float*)d_in[1];
    const float* apw  = (const float*)d_in[2];
    const float* apb  = (const float*)d_in[3];
    const float* agw  = (const float*)d_in[4];
    const float* agb  = (const float*)d_in[5];
    const float* opw  = (const float*)d_in[6];
    const float* opb  = (const float*)d_in[7];
    const float* ogw  = (const float*)d_in[8];
    const float* ogb  = (const float*)d_in[9];
    float* out = (float*)d_out;

    const size_t smA = 164352;
    const size_t smB = 131072;
    const size_t smC = 131072 + 67584;
    cudaFuncSetAttribute(kA, cudaFuncAttributeMaxDynamicSharedMemorySize, (int)smA);
    cudaFuncSetAttribute(kB, cudaFuncAttributeMaxDynamicSharedMemorySize, (int)smB);
    cudaFuncSetAttribute(kC, cudaFuncAttributeMaxDynamicSharedMemorySize, (int)smC);

    kW<<<128, 256>>>(agw, apw, ogw, opw);
    kA<<<NN/128, 512, smA>>>(pair, mask, apb, agb);
    kB<<<dim3(4, 4, DDIM), 512, smB>>>();
    kC<<<NN/128, 512, smC>>>(pair, opb, ogb, out);
}

// round 6
// speedup vs baseline: 2.3879x; 1.0193x over previous
#include <cuda_runtime.h>
#include <cuda_bf16.h>
#include <cstdint>
#include <cstddef>

#define NSEQ 512
#define DDIM 128
#define NN   (NSEQ*NSEQ)

typedef unsigned long long ull;

// Scratch: a,b as bf16 hi/lo, channel-major [d][i][k]; tri fp32 [d][i][j]
static __device__ __nv_bfloat16 g_ah[(size_t)DDIM * NN];
static __device__ __nv_bfloat16 g_al[(size_t)DDIM * NN];
static __device__ __nv_bfloat16 g_bh[(size_t)DDIM * NN];
static __device__ __nv_bfloat16 g_bl[(size_t)DDIM * NN];
static __device__ float g_t[(size_t)DDIM * NN];

// Pre-split weights (bf16 hi/lo), row-major [ch][k]
static __device__ __nv_bfloat16 g_wgh[256*128], g_wgl[256*128];
static __device__ __nv_bfloat16 g_wph[256*128], g_wpl[256*128];
static __device__ __nv_bfloat16 g_ogh[128*128], g_ogl[128*128];
static __device__ __nv_bfloat16 g_oph[128*128], g_opl[128*128];

__device__ __forceinline__ float sigmoidf_(float x) { return 1.0f / (1.0f + __expf(-x)); }

__device__ __forceinline__ uint32_t smem_u32(const void* p) {
    uint32_t a;
    asm("{ .reg .u64 t; cvta.to.shared.u64 t, %1; cvt.u32.u64 %0, t; }" : "=r"(a) : "l"(p));
    return a;
}
#define SW128(o) ((o) ^ (((o) >> 3) & 0x70))
#define SW64(o)  ((o) ^ (((o) >> 3) & 0x30))

#define CP_ASYNC16(dst, src) \
    asm volatile("cp.async.cg.shared.global [%0], [%1], 16;" :: "r"(dst), "l"(src) : "memory")
#define CP_COMMIT() asm volatile("cp.async.commit_group;" ::: "memory")
#define CP_WAIT(n)  asm volatile("cp.async.wait_group %0;" :: "n"(n) : "memory")

__device__ __forceinline__ void ldm4(uint32_t addr, uint32_t r[4]) {
    asm volatile("ldmatrix.sync.aligned.m8n8.x4.shared.b16 {%0,%1,%2,%3}, [%4];"
        : "=r"(r[0]), "=r"(r[1]), "=r"(r[2]), "=r"(r[3]) : "r"(addr));
}
__device__ __forceinline__ void mma16816(float c[4], const uint32_t a[4],
                                         uint32_t b0, uint32_t b1) {
    asm volatile(
        "mma.sync.aligned.m16n8k16.row.col.f32.bf16.bf16.f32 "
        "{%0,%1,%2,%3}, {%4,%5,%6,%7}, {%8,%9}, {%0,%1,%2,%3};"
        : "+f"(c[0]), "+f"(c[1]), "+f"(c[2]), "+f"(c[3])
        : "r"(a[0]), "r"(a[1]), "r"(a[2]), "r"(a[3]), "r"(b0), "r"(b1));
}

// LayerNorm of one logical row stored as a column: s[d*132 + row]
__device__ __forceinline__ void ln_col(float* s, int row, int lane) {
    float x0 = s[(lane      )*132 + row];
    float x1 = s[(lane + 32 )*132 + row];
    float x2 = s[(lane + 64 )*132 + row];
    float x3 = s[(lane + 96 )*132 + row];
    float sum = x0 + x1 + x2 + x3;
    #pragma unroll
    for (int o = 16; o > 0; o >>= 1) sum += __shfl_xor_sync(0xffffffffu, sum, o);
    float mu = sum * (1.0f/128.0f);
    float d0 = x0-mu, d1 = x1-mu, d2 = x2-mu, d3 = x3-mu;
    float v = d0*d0 + d1*d1 + d2*d2 + d3*d3;
    #pragma unroll
    for (int o = 16; o > 0; o >>= 1) v += __shfl_xor_sync(0xffffffffu, v, o);
    float rstd = rsqrtf(v * (1.0f/128.0f) + 1e-5f);
    s[(lane      )*132 + row] = d0 * rstd;
    s[(lane + 32 )*132 + row] = d1 * rstd;
    s[(lane + 64 )*132 + row] = d2 * rstd;
    s[(lane + 96 )*132 + row] = d3 * rstd;
}

// ============================================================================
__global__ void __launch_bounds__(256) kW(
    const float* __restrict__ agw, const float* __restrict__ apw,
    const float* __restrict__ ogw, const float* __restrict__ opw)
{
    int i = blockIdx.x * 256 + threadIdx.x;
    if (i < 256*128) {
        float g = agw[i];
        __nv_bfloat16 gh = __float2bfloat16_rn(g);
        g_wgh[i] = gh; g_wgl[i] = __float2bfloat16_rn(g - __bfloat162float(gh));
        float p = apw[i];
        __nv_bfloat16 ph = __float2bfloat16_rn(p);
        g_wph[i] = ph; g_wpl[i] = __float2bfloat16_rn(p - __bfloat162float(ph));
    }
    if (i < 128*128) {
        float g = ogw[i];
        __nv_bfloat16 gh = __float2bfloat16_rn(g);
        g_ogh[i] = gh; g_ogl[i] = __float2bfloat16_rn(g - __bfloat162float(gh));
        float p = opw[i];
        __nv_bfloat16 ph = __float2bfloat16_rn(p);
        g_oph[i] = ph; g_opl[i] = __float2bfloat16_rn(p - __bfloat162float(ph));
    }
}

// ============================================================================
// Kernel A (HMMA, 256 thr, 64-row blocks, ~112KB smem -> 2 CTAs/SM)
// smem: Ahi 16K | Alo 16K | W 64K | stgH 8K | stgL 8K | mask 256B
// ============================================================================
__global__ void __launch_bounds__(256, 2) kA(
    const float* __restrict__ pair, const float* __restrict__ mask,
    const float* __restrict__ apb, const float* __restrict__ agb)
{
    extern __shared__ char smc[];
    const uint32_t sbase = smem_u32(smc);
    const uint32_t uAh = sbase;
    const uint32_t uAl = sbase + 16384;
    const uint32_t uW  = sbase + 32768;
    __nv_bfloat16* stgH = (__nv_bfloat16*)(smc + 98304);
    __nv_bfloat16* stgL = (__nv_bfloat16*)(smc + 106496);
    float* sM = (float*)(smc + 114688);

    const int t    = threadIdx.x;
    const int lane = t & 31;
    const int wid  = t >> 5;
    const int r0   = blockIdx.x * 64;

    if (t < 64) sM[t] = mask[r0 + t];

    // LN + bf16 split -> A tiles (64 rows x 128k, halves of 8KB)
    for (int row = wid; row < 64; row += 8) {
        const float* src = pair + (size_t)(r0 + row) * DDIM;
        float x[4] = { src[lane], src[lane+32], src[lane+64], src[lane+96] };
        float s = x[0] + x[1] + x[2] + x[3];
        #pragma unroll
        for (int o = 16; o > 0; o >>= 1) s += __shfl_xor_sync(0xffffffffu, s, o);
        float mu = s * (1.0f/128.0f);
        float d0 = x[0]-mu, d1 = x[1]-mu, d2 = x[2]-mu, d3 = x[3]-mu;
        float v = d0*d0 + d1*d1 + d2*d2 + d3*d3;
        #pragma unroll
        for (int o = 16; o > 0; o >>= 1) v += __shfl_xor_sync(0xffffffffu, v, o);
        float rstd = rsqrtf(v * (1.0f/128.0f) + 1e-5f);
        float dd[4] = { d0*rstd, d1*rstd, d2*rstd, d3*rstd };
        #pragma unroll
        for (int j = 0; j < 4; j++) {
            __nv_bfloat16 h = __float2bfloat16_rn(dd[j]);
            __nv_bfloat16 l = __float2bfloat16_rn(dd[j] - __bfloat162float(h));
            uint32_t off = (uint32_t)(j >= 2) * 8192u
                         + SW128((uint32_t)(row*128 + (lane + 32*(j&1))*2));
            *(__nv_bfloat16*)(smc + off)         = h;
            *(__nv_bfloat16*)(smc + 16384 + off) = l;
        }
    }

    const int aRow = lane & 15;
    const int aK   = (lane >> 4) * 16;
    const int bRow = (lane & 7) + ((lane >> 4) << 3);
    const int bK   = ((lane >> 3) & 1) * 16;
    const int m0   = (wid & 1) * 32;
    const int n0   = (wid >> 1) * 16;

    for (int ct = 0; ct < 4; ct++) {
        const int ch0 = ct * 64;
        __syncthreads();
        const __nv_bfloat16* warr[4] = { g_wgh, g_wgl, g_wph, g_wpl };
        #pragma unroll
        for (int arr = 0; arr < 4; arr++) {
            #pragma unroll
            for (int q = 0; q < 4; q++) {
                int seg = t + 256*q;          // 0..1023
                int ch  = seg >> 4;
                int s8  = seg & 15;
                uint4 v = *(const uint4*)(warr[arr] + (size_t)(ch0 + ch)*128 + s8*8);
                uint32_t dst = 32768 + arr*16384 + ((s8 >= 8) ? 8192u : 0u)
                             + SW128((uint32_t)(ch*128 + (s8 & 7)*16));
                *(uint4*)(smc + dst) = v;
            }
        }
        __syncthreads();

        float accg[2][2][4], accp[2][2][4];
        #pragma unroll
        for (int m = 0; m < 2; m++)
            #pragma unroll
            for (int n = 0; n < 2; n++)
                #pragma unroll
                for (int e = 0; e < 4; e++) { accg[m][n][e] = 0.f; accp[m][n][e] = 0.f; }

        #pragma unroll
        for (int kk = 0; kk < 8; kk++) {
            const uint32_t halfA = (uint32_t)(kk >> 2) * 8192u;
            const uint32_t halfW = (uint32_t)(kk >> 2) * 8192u;
            const uint32_t k32   = (uint32_t)(kk & 3) * 32u;

            uint32_t ah[2][4], al[2][4];
            #pragma unroll
            for (int f = 0; f < 2; f++) {
                uint32_t off = SW128((uint32_t)((m0 + f*16 + aRow)*128) + k32 + aK);
                ldm4(uAh + halfA + off, ah[f]);
                ldm4(uAl + halfA + off, al[f]);
            }
            uint32_t gh[4], gl[4], ph[4], pl[4];
            {
                uint32_t off = SW128((uint32_t)((n0 + bRow)*128) + k32 + bK);
                ldm4(uW +     0 + halfW + off, gh);
                ldm4(uW + 16384 + halfW + off, gl);
                ldm4(uW + 32768 + halfW + off, ph);
                ldm4(uW + 49152 + halfW + off, pl);
            }
            #pragma unroll
            for (int m = 0; m < 2; m++)
                #pragma unroll
                for (int n = 0; n < 2; n++) {
                    int bi = n * 2;
                    mma16816(accg[m][n], ah[m], gh[bi], gh[bi+1]);
                    mma16816(accg[m][n], ah[m], gl[bi], gl[bi+1]);
                    mma16816(accg[m][n], al[m], gh[bi], gh[bi+1]);
                    mma16816(accp[m][n], ah[m], ph[bi], ph[bi+1]);
                    mma16816(accp[m][n], ah[m], pl[bi], pl[bi+1]);
                    mma16816(accp[m][n], al[m], ph[bi], ph[bi+1]);
                }
        }

        #pragma unroll
        for (int m = 0; m < 2; m++) {
            int row0 = m0 + m*16 + (lane >> 2);    // 0..63
            #pragma unroll
            for (int n = 0; n < 2; n++) {
                int c0 = n0 + n*8 + (lane & 3)*2;  // 0..63
                float gb0 = __ldg(agb + ch0 + c0), gb1 = __ldg(agb + ch0 + c0 + 1);
                float pb0 = __ldg(apb + ch0 + c0), pb1 = __ldg(apb + ch0 + c0 + 1);
                float mv0 = sM[row0], mv1 = sM[row0 + 8];
                float vals[4];
                vals[0] = mv0 * sigmoidf_(accg[m][n][0] + gb0) * (accp[m][n][0] + pb0);
                vals[1] = mv0 * sigmoidf_(accg[m][n][1] + gb1) * (accp[m][n][1] + pb1);
                vals[2] = mv1 * sigmoidf_(accg[m][n][2] + gb0) * (accp[m][n][2] + pb0);
                vals[3] = mv1 * sigmoidf_(accg[m][n][3] + gb1) * (accp[m][n][3] + pb1);
                #pragma unroll
                for (int e = 0; e < 4; e++) {
                    int cc = c0 + (e & 1);
                    int rr = row0 + (e >> 1) * 8;
                    __nv_bfloat16 h = __float2bfloat16_rn(vals[e]);
                    stgH[cc*64 + rr] = h;
                    stgL[cc*64 + rr] = __float2bfloat16_rn(vals[e] - __bfloat162float(h));
                }
            }
        }
        __syncthreads();

        __nv_bfloat16* dstH = (ch0 < 128) ? (g_ah + (size_t)ch0 * NN)
                                          : (g_bh + (size_t)(ch0 - 128) * NN);
        __nv_bfloat16* dstL = (ch0 < 128) ? (g_al + (size_t)ch0 * NN)
                                          : (g_bl + (size_t)(ch0 - 128) * NN);
        #pragma unroll
        for (int q = 0; q < 2; q++) {
            int seg = t + 256*q;          // 0..511
            int ch  = seg >> 3;           // 0..63
            int r8  = (seg & 7) * 8;      // 0..56
            uint4 vh = *(const uint4*)(stgH + ch*64 + r8);
            uint4 vl = *(const uint4*)(stgL + ch*64 + r8);
            size_t off = (size_t)ch * NN + r0 + r8;
            *(uint4*)(dstH + off) = vh;
            *(uint4*)(dstL + off) = vl;
        }
    }
}

// ============================================================================
// Kernel B (256 thr, K-chunk 32, SW64 tiles, 64KB smem -> 2 CTAs/SM)
// 8 warps 2m x 4n, warp tile 64x32.
// ============================================================================
__global__ void __launch_bounds__(256, 2) kB()
{
    extern __shared__ char smc[];
    const uint32_t sbase = smem_u32(smc);

    const int t    = threadIdx.x;
    const int lane = t & 31;
    const int wid  = t >> 5;
    const int d    = blockIdx.z;
    const int i0   = blockIdx.x * 128;
    const int j0   = blockIdx.y * 128;

    const int m0 = (wid & 1) * 64;
    const int n0 = (wid >> 1) * 32;

    const __nv_bfloat16* srcs[4] = {
        g_ah + (size_t)d*NN + (size_t)i0*NSEQ,
        g_al + (size_t)d*NN + (size_t)i0*NSEQ,
        g_bh + (size_t)d*NN + (size_t)j0*NSEQ,
        g_bl + (size_t)d*NN + (size_t)j0*NSEQ };

    // stage = 4 tiles of 128row x 32col bf16 (64B rows, SW64), 8KB each
    auto issue = [&](int stage, int kc) {
        uint32_t sb = sbase + stage * 32768;
        #pragma unroll
        for (int T = 0; T < 4; T++) {
            const __nv_bfloat16* base = srcs[T];
            #pragma unroll
            for (int q = 0; q < 2; q++) {
                int seg = t + 256*q;          // 0..511
                int row = seg >> 2;           // 0..127
                int s   = seg & 3;            // 16B seg
                uint32_t dst = sb + T*8192 + SW64((uint32_t)(row*64 + s*16));
                CP_ASYNC16(dst, base + (size_t)row*NSEQ + kc + s*8);
            }
        }
        CP_COMMIT();
    };

    float acc[4][4][4];
    #pragma unroll
    for (int m = 0; m < 4; m++)
        #pragma unroll
        for (int n = 0; n < 4; n++)
            #pragma unroll
            for (int e = 0; e < 4; e++) acc[m][n][e] = 0.0f;

    const int aRow = lane & 15;
    const int aK   = (lane >> 4) * 16;
    const int bRow = (lane & 7) + ((lane >> 4) << 3);
    const int bK   = ((lane >> 3) & 1) * 16;

    issue(0, 0);

    for (int ch = 0; ch < 16; ch++) {
        const int stage = ch & 1;
        if (ch < 15) { issue(stage ^ 1, (ch + 1) * 32); CP_WAIT(1); }
        else         { CP_WAIT(0); }
        __syncthreads();

        const uint32_t sb  = sbase + stage * 32768;
        const uint32_t sAh = sb;
        const uint32_t sAl = sb + 8192;
        const uint32_t sBh = sb + 16384;
        const uint32_t sBl = sb + 24576;

        #pragma unroll
        for (int kk = 0; kk < 2; kk++) {
            const uint32_t kOffA = (uint32_t)(kk*32) + aK;
            const uint32_t kOffB = (uint32_t)(kk*32) + bK;

            uint32_t bh[2][4], bl[2][4];
            #pragma unroll
            for (int c = 0; c < 2; c++) {
                uint32_t off = (uint32_t)((n0 + c*16 + bRow) * 64) + kOffB;
                ldm4(sBh + SW64(off), bh[c]);
            }
            uint32_t ah[4][4];
            #pragma unroll
            for (int f = 0; f < 4; f++) {
                uint32_t off = (uint32_t)((m0 + f*16 + aRow) * 64) + kOffA;
                ldm4(sAh + SW64(off), ah[f]);
            }
            #pragma unroll
            for (int m = 0; m < 4; m++)
                #pragma unroll
                for (int n = 0; n < 4; n++)
                    mma16816(acc[m][n], ah[m], bh[n>>1][(n&1)*2], bh[n>>1][(n&1)*2+1]);

            #pragma unroll
            for (int c = 0; c < 2; c++) {
                uint32_t off = (uint32_t)((n0 + c*16 + bRow) * 64) + kOffB;
                ldm4(sBl + SW64(off), bl[c]);
            }
            #pragma unroll
            for (int m = 0; m < 4; m++)
                #pragma unroll
                for (int n = 0; n < 4; n++)
                    mma16816(acc[m][n], ah[m], bl[n>>1][(n&1)*2], bl[n>>1][(n&1)*2+1]);

            uint32_t al[4][4];
            #pragma unroll
            for (int f = 0; f < 4; f++) {
                uint32_t off = (uint32_t)((m0 + f*16 + aRow) * 64) + kOffA;
                ldm4(sAl + SW64(off), al[f]);
            }
            #pragma unroll
            for (int m = 0; m < 4; m++)
                #pragma unroll
                for (int n = 0; n < 4; n++)
                    mma16816(acc[m][n], al[m], bh[n>>1][(n&1)*2], bh[n>>1][(n&1)*2+1]);
        }
        __syncthreads();
    }

    float* base = g_t + (size_t)d*NN;
    #pragma unroll
    for (int m = 0; m < 4; m++) {
        int r1 = i0 + m0 + m*16 + (lane >> 2);
        #pragma unroll
        for (int n = 0; n < 4; n++) {
            int c = j0 + n0 + n*8 + (lane & 3)*2;
            float2 lo = make_float2(acc[m][n][0], acc[m][n][1]);
            float2 hi = make_float2(acc[m][n][2], acc[m][n][3]);
            *(float2*)(base + (size_t)r1*NSEQ + c)       = lo;
            *(float2*)(base + (size_t)(r1+8)*NSEQ + c)   = hi;
        }
    }
}

// ============================================================================
// Kernel C (HMMA, 512 thr) — unchanged from R5
// ============================================================================
__global__ void __launch_bounds__(512) kC(
    const float* __restrict__ pair,
    const float* __restrict__ opb, const float* __restrict__ ogb,
    float* __restrict__ out)
{
    extern __shared__ char smc[];
    const uint32_t sbase = smem_u32(smc);
    const uint32_t uA1 = sbase;
    const uint32_t uA2 = sbase + 65536;
    const uint32_t uW  = sbase + 131072;
    float* sTmp = (float*)(smc + 131072);

    const int t    = threadIdx.x;
    const int lane = t & 31;
    const int wid  = t >> 5;
    const int r0   = blockIdx.x * 128;

    for (int row = wid; row < 128; row += 16) {
        const float* src = pair + (size_t)(r0 + row) * DDIM;
        float x[4] = { src[lane], src[lane+32], src[lane+64], src[lane+96] };
        float s = x[0] + x[1] + x[2] + x[3];
        #pragma unroll
        for (int o = 16; o > 0; o >>= 1) s += __shfl_xor_sync(0xffffffffu, s, o);
        float mu = s * (1.0f/128.0f);
        float d0 = x[0]-mu, d1 = x[1]-mu, d2 = x[2]-mu, d3 = x[3]-mu;
        float v = d0*d0 + d1*d1 + d2*d2 + d3*d3;
        #pragma unroll
        for (int o = 16; o > 0; o >>= 1) v += __shfl_xor_sync(0xffffffffu, v, o);
        float rstd = rsqrtf(v * (1.0f/128.0f) + 1e-5f);
        float dd[4] = { d0*rstd, d1*rstd, d2*rstd, d3*rstd };
        #pragma unroll
        for (int j = 0; j < 4; j++) {
            __nv_bfloat16 h = __float2bfloat16_rn(dd[j]);
            __nv_bfloat16 l = __float2bfloat16_rn(dd[j] - __bfloat162float(h));
            uint32_t off = (uint32_t)(j >= 2) * 16384u
                         + SW128((uint32_t)(row*128 + (lane + 32*(j&1))*2));
            *(__nv_bfloat16*)(smc + off)         = h;
            *(__nv_bfloat16*)(smc + 32768 + off) = l;
        }
    }

    #pragma unroll
    for (int m = 0; m < 8; m++) {
        int q = t + 512*m;
        int dd = q >> 5;
        int r4 = (q & 31) * 4;
        float4 f = *(const float4*)(g_t + (size_t)dd*NN + r0 + r4);
        *(float4*)&sTmp[dd*132 + r4] = f;
    }
    __syncthreads();
    for (int row = wid; row < 128; row += 16) ln_col(sTmp, row, lane);
    __syncthreads();
    for (int row = wid; row < 128; row += 16) {
        #pragma unroll
        for (int j = 0; j < 4; j++) {
            int k = lane + 32*j;
            float v = sTmp[k*132 + row];
            __nv_bfloat16 h = __float2bfloat16_rn(v);
            __nv_bfloat16 l = __float2bfloat16_rn(v - __bfloat162float(h));
            uint32_t off = (uint32_t)(j >= 2) * 16384u
                         + SW128((uint32_t)(row*128 + (lane + 32*(j&1))*2));
            *(__nv_bfloat16*)(smc + 65536 + off)         = h;
            *(__nv_bfloat16*)(smc + 65536 + 32768 + off) = l;
        }
    }

    const int aRow = lane & 15;
    const int aK   = (lane >> 4) * 16;
    const int bRow = (lane & 7) + ((lane >> 4) << 3);
    const int bK   = ((lane >> 3) & 1) * 16;
    const int m0   = (wid & 3) * 32;
    const int n0   = (wid >> 2) * 16;

    for (int ot = 0; ot < 2; ot++) {
        const int o0 = ot * 64;
        __syncthreads();
        const __nv_bfloat16* warr[4] = { g_ogh, g_ogl, g_oph, g_opl };
        #pragma unroll
        for (int arr = 0; arr < 4; arr++) {
            #pragma unroll
            for (int q = 0; q < 2; q++) {
                int seg = t + 512*q;
                int ch  = seg >> 4;
                int s8  = seg & 15;
                uint4 v = *(const uint4*)(warr[arr] + (size_t)(o0 + ch)*128 + s8*8);
                uint32_t dst = 131072 + arr*16384 + ((s8 >= 8) ? 8192u : 0u)
                             + SW128((uint32_t)(ch*128 + (s8 & 7)*16));
                *(uint4*)(smc + dst) = v;
            }
        }
        __syncthreads();

        float accg[2][2][4], accp[2][2][4];
        #pragma unroll
        for (int m = 0; m < 2; m++)
            #pragma unroll
            for (int n = 0; n < 2; n++)
                #pragma unroll
                for (int e = 0; e < 4; e++) { accg[m][n][e] = 0.f; accp[m][n][e] = 0.f; }

        #pragma unroll
        for (int kk = 0; kk < 8; kk++) {
            const uint32_t halfA = (uint32_t)(kk >> 2) * 16384u;
            const uint32_t halfW = (uint32_t)(kk >> 2) * 8192u;
            const uint32_t k32   = (uint32_t)(kk & 3) * 32u;

            uint32_t a1h[2][4], a1l[2][4], a2h[2][4], a2l[2][4];
            #pragma unroll
            for (int f = 0; f < 2; f++) {
                uint32_t off = SW128((uint32_t)((m0 + f*16 + aRow)*128) + k32 + aK);
                ldm4(uA1 +         halfA + off, a1h[f]);
                ldm4(uA1 + 32768 + halfA + off, a1l[f]);
                ldm4(uA2 +         halfA + off, a2h[f]);
                ldm4(uA2 + 32768 + halfA + off, a2l[f]);
            }
            uint32_t gh[4], gl[4], ph[4], pl[4];
            {
                uint32_t off = SW128((uint32_t)((n0 + bRow)*128) + k32 + bK);
                ldm4(uW +     0 + halfW + off, gh);
                ldm4(uW + 16384 + halfW + off, gl);
                ldm4(uW + 32768 + halfW + off, ph);
                ldm4(uW + 49152 + halfW + off, pl);
            }
            #pragma unroll
            for (int m = 0; m < 2; m++)
                #pragma unroll
                for (int n = 0; n < 2; n++) {
                    int bi = n * 2;
                    mma16816(accg[m][n], a1h[m], gh[bi], gh[bi+1]);
                    mma16816(accg[m][n], a1h[m], gl[bi], gl[bi+1]);
                    mma16816(accg[m][n], a1l[m], gh[bi], gh[bi+1]);
                    mma16816(accp[m][n], a2h[m], ph[bi], ph[bi+1]);
                    mma16816(accp[m][n], a2h[m], pl[bi], pl[bi+1]);
                    mma16816(accp[m][n], a2l[m], ph[bi], ph[bi+1]);
                }
        }

        #pragma unroll
        for (int m = 0; m < 2; m++) {
            int row0 = m0 + m*16 + (lane >> 2);
            #pragma unroll
            for (int n = 0; n < 2; n++) {
                int c0 = n0 + n*8 + (lane & 3)*2;
                float gb0 = __ldg(ogb + o0 + c0), gb1 = __ldg(ogb + o0 + c0 + 1);
                float pb0 = __ldg(opb + o0 + c0), pb1 = __ldg(opb + o0 + c0 + 1);
                float2 v0, v1;
                v0.x = sigmoidf_(accg[m][n][0] + gb0) * (accp[m][n][0] + pb0);
                v0.y = sigmoidf_(accg[m][n][1] + gb1) * (accp[m][n][1] + pb1);
                v1.x = sigmoidf_(accg[m][n][2] + gb0) * (accp[m][n][2] + pb0);
                v1.y = sigmoidf_(accg[m][n][3] + gb1) * (accp[m][n][3] + pb1);
                *(float2*)(out + (size_t)(r0 + row0)*DDIM + o0 + c0)     = v0;
                *(float2*)(out + (size_t)(r0 + row0 + 8)*DDIM + o0 + c0) = v1;
            }
        }
    }
}

// ============================================================================
extern "C" void kernel_launch(void* const* d_in, const int* in_sizes, int n_in,
                              void* d_out, int out_size)
{
    const float* pair = (const float*)d_in[0];
    const float* mask = (const float*)d_in[1];
    const float* apw  = (const float*)d_in[2];
    const float* apb  = (const float*)d_in[3];
    const float* agw  = (const float*)d_in[4];
    const float* agb  = (const float*)d_in[5];
    const float* opw  = (const float*)d_in[6];
    const float* opb  = (const float*)d_in[7];
    const float* ogw  = (const float*)d_in[8];
    const float* ogb  = (const float*)d_in[9];
    float* out = (float*)d_out;

    const size_t smA = 114944;          // ~112.25 KB -> 2 CTAs/SM
    const size_t smB = 65536;           // 64 KB -> 2 CTAs/SM
    const size_t smC = 131072 + 67584;  // 194 KB
    cudaFuncSetAttribute(kA, cudaFuncAttributeMaxDynamicSharedMemorySize, (int)smA);
    cudaFuncSetAttribute(kB, cudaFuncAttributeMaxDynamicSharedMemorySize, (int)smB);
    cudaFuncSetAttribute(kC, cudaFuncAttributeMaxDynamicSharedMemorySize, (int)smC);

    kW<<<128, 256>>>(agw, apw, ogw, opw);
    kA<<<NN/64, 256, smA>>>(pair, mask, apb, agb);
    kB<<<dim3(4, 4, DDIM), 256, smB>>>();
    kC<<<NN/128, 512, smC>>>(pair, opb, ogb, out);
}

// round 7
// speedup vs baseline: 3.8451x; 1.6102x over previous
#include <cuda_runtime.h>
#include <cuda_fp16.h>
#include <cstdint>
#include <cstddef>

#define NSEQ 512
#define DDIM 128
#define NN   (NSEQ*NSEQ)

// Scratch: a,b fp16 channel-major [d][i][k]; tri fp32 [d][i][j]
static __device__ __half g_af[(size_t)DDIM * NN];
static __device__ __half g_bf[(size_t)DDIM * NN];
static __device__ float  g_t[(size_t)DDIM * NN];

// Pre-converted weights (fp16), row-major [ch][k]
static __device__ __half g_wg[256*128];               // ab_gate  (1-term)
static __device__ __half g_wp[256*128];               // ab_proj  (1-term)
static __device__ __half g_og[128*128];               // out_gate (1-term)
static __device__ __half g_oph[128*128], g_opl[128*128]; // out_proj (hi/lo)

__device__ __forceinline__ float sigmoidf_(float x) { return 1.0f / (1.0f + __expf(-x)); }

__device__ __forceinline__ uint32_t smem_u32(const void* p) {
    uint32_t a;
    asm("{ .reg .u64 t; cvta.to.shared.u64 t, %1; cvt.u32.u64 %0, t; }" : "=r"(a) : "l"(p));
    return a;
}
#define SW128(o) ((o) ^ (((o) >> 3) & 0x70))

#define CP_ASYNC16(dst, src) \
    asm volatile("cp.async.cg.shared.global [%0], [%1], 16;" :: "r"(dst), "l"(src) : "memory")
#define CP_COMMIT() asm volatile("cp.async.commit_group;" ::: "memory")
#define CP_WAIT(n)  asm volatile("cp.async.wait_group %0;" :: "n"(n) : "memory")

__device__ __forceinline__ void ldm4(uint32_t addr, uint32_t r[4]) {
    asm volatile("ldmatrix.sync.aligned.m8n8.x4.shared.b16 {%0,%1,%2,%3}, [%4];"
        : "=r"(r[0]), "=r"(r[1]), "=r"(r[2]), "=r"(r[3]) : "r"(addr));
}
__device__ __forceinline__ void mma16816(float c[4], const uint32_t a[4],
                                         uint32_t b0, uint32_t b1) {
    asm volatile(
        "mma.sync.aligned.m16n8k16.row.col.f32.f16.f16.f32 "
        "{%0,%1,%2,%3}, {%4,%5,%6,%7}, {%8,%9}, {%0,%1,%2,%3};"
        : "+f"(c[0]), "+f"(c[1]), "+f"(c[2]), "+f"(c[3])
        : "r"(a[0]), "r"(a[1]), "r"(a[2]), "r"(a[3]), "r"(b0), "r"(b1));
}

// LayerNorm of one logical row stored as a column: s[d*132 + row]
__device__ __forceinline__ void ln_col(float* s, int row, int lane) {
    float x0 = s[(lane      )*132 + row];
    float x1 = s[(lane + 32 )*132 + row];
    float x2 = s[(lane + 64 )*132 + row];
    float x3 = s[(lane + 96 )*132 + row];
    float sum = x0 + x1 + x2 + x3;
    #pragma unroll
    for (int o = 16; o > 0; o >>= 1) sum += __shfl_xor_sync(0xffffffffu, sum, o);
    float mu = sum * (1.0f/128.0f);
    float d0 = x0-mu, d1 = x1-mu, d2 = x2-mu, d3 = x3-mu;
    float v = d0*d0 + d1*d1 + d2*d2 + d3*d3;
    #pragma unroll
    for (int o = 16; o > 0; o >>= 1) v += __shfl_xor_sync(0xffffffffu, v, o);
    float rstd = rsqrtf(v * (1.0f/128.0f) + 1e-5f);
    s[(lane      )*132 + row] = d0 * rstd;
    s[(lane + 32 )*132 + row] = d1 * rstd;
    s[(lane + 64 )*132 + row] = d2 * rstd;
    s[(lane + 96 )*132 + row] = d3 * rstd;
}

// ============================================================================
__global__ void __launch_bounds__(256) kW(
    const float* __restrict__ agw, const float* __restrict__ apw,
    const float* __restrict__ ogw, const float* __restrict__ opw)
{
    int i = blockIdx.x * 256 + threadIdx.x;
    if (i < 256*128) {
        g_wg[i] = __float2half_rn(agw[i]);
        g_wp[i] = __float2half_rn(apw[i]);
    }
    if (i < 128*128) {
        g_og[i] = __float2half_rn(ogw[i]);
        float p = opw[i];
        __half ph = __float2half_rn(p);
        g_oph[i] = ph;
        g_opl[i] = __float2half_rn(p - __half2float(ph));
    }
}

// ============================================================================
// Kernel A (fp16 1-term): LN(pair) -> gate/proj GEMM -> ab -> fp16 ch-major
// smem: A 32K | Wg 16K | Wp 16K | stage 16K | mask 512B  (~80.5KB, 2 CTA/SM)
// 256 thr, 8 warps 2m x 4n, warp tile 64 x 16.
// ============================================================================
__global__ void __launch_bounds__(256, 2) kA(
    const float* __restrict__ pair, const float* __restrict__ mask,
    const float* __restrict__ apb, const float* __restrict__ agb)
{
    extern __shared__ char smc[];
    const uint32_t sbase = smem_u32(smc);
    const uint32_t uA  = sbase;
    const uint32_t uWg = sbase + 32768;
    const uint32_t uWp = sbase + 49152;
    __half* stgF = (__half*)(smc + 65536);
    float*  sM   = (float*)(smc + 81920);

    const int t    = threadIdx.x;
    const int lane = t & 31;
    const int wid  = t >> 5;
    const int r0   = blockIdx.x * 128;

    if (t < 128) sM[t] = mask[r0 + t];

    // LN -> fp16 A tiles (two 64-k halves of 16KB, SW128 within 128B rows)
    for (int row = wid; row < 128; row += 8) {
        const float* src = pair + (size_t)(r0 + row) * DDIM;
        float x[4] = { src[lane], src[lane+32], src[lane+64], src[lane+96] };
        float s = x[0] + x[1] + x[2] + x[3];
        #pragma unroll
        for (int o = 16; o > 0; o >>= 1) s += __shfl_xor_sync(0xffffffffu, s, o);
        float mu = s * (1.0f/128.0f);
        float d0 = x[0]-mu, d1 = x[1]-mu, d2 = x[2]-mu, d3 = x[3]-mu;
        float v = d0*d0 + d1*d1 + d2*d2 + d3*d3;
        #pragma unroll
        for (int o = 16; o > 0; o >>= 1) v += __shfl_xor_sync(0xffffffffu, v, o);
        float rstd = rsqrtf(v * (1.0f/128.0f) + 1e-5f);
        float dd[4] = { d0*rstd, d1*rstd, d2*rstd, d3*rstd };
        #pragma unroll
        for (int j = 0; j < 4; j++) {
            uint32_t off = (uint32_t)(j >= 2) * 16384u
                         + SW128((uint32_t)(row*128 + (lane + 32*(j&1))*2));
            *(__half*)(smc + off) = __float2half_rn(dd[j]);
        }
    }

    const int aRow = lane & 15;
    const int aK   = (lane >> 4) * 16;
    const int bRow = (lane & 7) + ((lane >> 4) << 3);
    const int bK   = ((lane >> 3) & 1) * 16;
    const int m0   = (wid & 1) * 64;
    const int n0   = (wid >> 1) * 16;

    for (int ct = 0; ct < 4; ct++) {
        const int ch0 = ct * 64;
        __syncthreads();
        // load 64ch x 128k fp16 of Wg and Wp
        #pragma unroll
        for (int q = 0; q < 4; q++) {
            int seg = t + 256*q;          // 0..1023
            int ch  = seg >> 4;
            int s8  = seg & 15;
            uint32_t dst = ((s8 >= 8) ? 8192u : 0u) + SW128((uint32_t)(ch*128 + (s8 & 7)*16));
            *(uint4*)(smc + 32768 + dst) = *(const uint4*)(g_wg + (size_t)(ch0 + ch)*128 + s8*8);
            *(uint4*)(smc + 49152 + dst) = *(const uint4*)(g_wp + (size_t)(ch0 + ch)*128 + s8*8);
        }
        __syncthreads();

        float accg[4][2][4], accp[4][2][4];
        #pragma unroll
        for (int m = 0; m < 4; m++)
            #pragma unroll
            for (int n = 0; n < 2; n++)
                #pragma unroll
                for (int e = 0; e < 4; e++) { accg[m][n][e] = 0.f; accp[m][n][e] = 0.f; }

        #pragma unroll
        for (int kk = 0; kk < 8; kk++) {
            const uint32_t halfA = (uint32_t)(kk >> 2) * 16384u;
            const uint32_t halfW = (uint32_t)(kk >> 2) * 8192u;
            const uint32_t k32   = (uint32_t)(kk & 3) * 32u;

            uint32_t ah[4][4];
            #pragma unroll
            for (int f = 0; f < 4; f++) {
                uint32_t off = SW128((uint32_t)((m0 + f*16 + aRow)*128) + k32 + aK);
                ldm4(uA + halfA + off, ah[f]);
            }
            uint32_t gh[4], ph[4];
            {
                uint32_t off = SW128((uint32_t)((n0 + bRow)*128) + k32 + bK);
                ldm4(uWg + halfW + off, gh);
                ldm4(uWp + halfW + off, ph);
            }
            #pragma unroll
            for (int m = 0; m < 4; m++)
                #pragma unroll
                for (int n = 0; n < 2; n++) {
                    mma16816(accg[m][n], ah[m], gh[n*2], gh[n*2+1]);
                    mma16816(accp[m][n], ah[m], ph[n*2], ph[n*2+1]);
                }
        }

        #pragma unroll
        for (int m = 0; m < 4; m++) {
            int row0 = m0 + m*16 + (lane >> 2);
            #pragma unroll
            for (int n = 0; n < 2; n++) {
                int c0 = n0 + n*8 + (lane & 3)*2;
                float gb0 = __ldg(agb + ch0 + c0), gb1 = __ldg(agb + ch0 + c0 + 1);
                float pb0 = __ldg(apb + ch0 + c0), pb1 = __ldg(apb + ch0 + c0 + 1);
                float mv0 = sM[row0], mv1 = sM[row0 + 8];
                float vals[4];
                vals[0] = mv0 * sigmoidf_(accg[m][n][0] + gb0) * (accp[m][n][0] + pb0);
                vals[1] = mv0 * sigmoidf_(accg[m][n][1] + gb1) * (accp[m][n][1] + pb1);
                vals[2] = mv1 * sigmoidf_(accg[m][n][2] + gb0) * (accp[m][n][2] + pb0);
                vals[3] = mv1 * sigmoidf_(accg[m][n][3] + gb1) * (accp[m][n][3] + pb1);
                #pragma unroll
                for (int e = 0; e < 4; e++) {
                    int cc = c0 + (e & 1);
                    int rr = row0 + (e >> 1) * 8;
                    stgF[cc*128 + rr] = __float2half_rn(vals[e]);
                }
            }
        }
        __syncthreads();

        __half* dst = (ch0 < 128) ? (g_af + (size_t)ch0 * NN)
                                  : (g_bf + (size_t)(ch0 - 128) * NN);
        #pragma unroll
        for (int q = 0; q < 4; q++) {
            int seg = t + 256*q;          // 0..1023
            int ch  = seg >> 4;
            int r8  = (seg & 15) * 8;
            *(uint4*)(dst + (size_t)ch * NN + r0 + r8) = *(const uint4*)(stgF + ch*128 + r8);
        }
    }
}

// ============================================================================
// Kernel B (fp16 1-term): 128 batched NT GEMMs.
// K-chunk 64, 2 stages x 32KB (A 16K + B 16K) -> 64KB, 2 CTA/SM.
// 8 warps 2m x 4n, warp tile 64 x 32.
// ============================================================================
__global__ void __launch_bounds__(256, 2) kB()
{
    extern __shared__ char smc[];
    const uint32_t sbase = smem_u32(smc);

    const int t    = threadIdx.x;
    const int lane = t & 31;
    const int wid  = t >> 5;
    const int d    = blockIdx.z;
    const int i0   = blockIdx.x * 128;
    const int j0   = blockIdx.y * 128;

    const int m0 = (wid & 1) * 64;
    const int n0 = (wid >> 1) * 32;

    const __half* srcA = g_af + (size_t)d*NN + (size_t)i0*NSEQ;
    const __half* srcB = g_bf + (size_t)d*NN + (size_t)j0*NSEQ;

    auto issue = [&](int stage, int kc) {
        uint32_t sb = sbase + stage * 32768;
        #pragma unroll
        for (int q = 0; q < 4; q++) {
            int seg = t + 256*q;          // 0..1023
            int row = seg >> 3;
            int s   = seg & 7;
            uint32_t off = SW128((uint32_t)(row*128 + s*16));
            CP_ASYNC16(sb + off,         srcA + (size_t)row*NSEQ + kc + s*8);
            CP_ASYNC16(sb + 16384 + off, srcB + (size_t)row*NSEQ + kc + s*8);
        }
        CP_COMMIT();
    };

    float acc[4][4][4];
    #pragma unroll
    for (int m = 0; m < 4; m++)
        #pragma unroll
        for (int n = 0; n < 4; n++)
            #pragma unroll
            for (int e = 0; e < 4; e++) acc[m][n][e] = 0.0f;

    const int aRow = lane & 15;
    const int aK   = (lane >> 4) * 16;
    const int bRow = (lane & 7) + ((lane >> 4) << 3);
    const int bK   = ((lane >> 3) & 1) * 16;

    issue(0, 0);

    for (int ch = 0; ch < 8; ch++) {
        const int stage = ch & 1;
        if (ch < 7) { issue(stage ^ 1, (ch + 1) * 64); CP_WAIT(1); }
        else        { CP_WAIT(0); }
        __syncthreads();

        const uint32_t sA = sbase + stage * 32768;
        const uint32_t sB = sA + 16384;

        #pragma unroll
        for (int kk = 0; kk < 4; kk++) {
            const uint32_t kOffA = (uint32_t)(kk*32) + aK;
            const uint32_t kOffB = (uint32_t)(kk*32) + bK;

            uint32_t bh[2][4];
            #pragma unroll
            for (int c = 0; c < 2; c++) {
                uint32_t off = (uint32_t)((n0 + c*16 + bRow) * 128) + kOffB;
                ldm4(sB + SW128(off), bh[c]);
            }
            uint32_t ah[4][4];
            #pragma unroll
            for (int f = 0; f < 4; f++) {
                uint32_t off = (uint32_t)((m0 + f*16 + aRow) * 128) + kOffA;
                ldm4(sA + SW128(off), ah[f]);
            }
            #pragma unroll
            for (int m = 0; m < 4; m++)
                #pragma unroll
                for (int n = 0; n < 4; n++)
                    mma16816(acc[m][n], ah[m], bh[n>>1][(n&1)*2], bh[n>>1][(n&1)*2+1]);
        }
        __syncthreads();
    }

    float* base = g_t + (size_t)d*NN;
    #pragma unroll
    for (int m = 0; m < 4; m++) {
        int r1 = i0 + m0 + m*16 + (lane >> 2);
        #pragma unroll
        for (int n = 0; n < 4; n++) {
            int c = j0 + n0 + n*8 + (lane & 3)*2;
            float2 lo = make_float2(acc[m][n][0], acc[m][n][1]);
            float2 hi = make_float2(acc[m][n][2], acc[m][n][3]);
            *(float2*)(base + (size_t)r1*NSEQ + c)       = lo;
            *(float2*)(base + (size_t)(r1+8)*NSEQ + c)   = hi;
        }
    }
}

// ============================================================================
// Kernel C (fp16; gate 1-term, proj 3-term): 512 thr.
// smem: A1 32K | A2h 32K | A2l 32K | W 48K (og/oph/opl) overlapped by sTmp 66K
// ============================================================================
__global__ void __launch_bounds__(512) kC(
    const float* __restrict__ pair,
    const float* __restrict__ opb, const float* __restrict__ ogb,
    float* __restrict__ out)
{
    extern __shared__ char smc[];
    const uint32_t sbase = smem_u32(smc);
    const uint32_t uA1  = sbase;
    const uint32_t uA2h = sbase + 32768;
    const uint32_t uA2l = sbase + 65536;
    const uint32_t uW   = sbase + 98304;
    float* sTmp = (float*)(smc + 98304);

    const int t    = threadIdx.x;
    const int lane = t & 31;
    const int wid  = t >> 5;
    const int r0   = blockIdx.x * 128;

    // pair LN -> A1 fp16 (single)
    for (int row = wid; row < 128; row += 16) {
        const float* src = pair + (size_t)(r0 + row) * DDIM;
        float x[4] = { src[lane], src[lane+32], src[lane+64], src[lane+96] };
        float s = x[0] + x[1] + x[2] + x[3];
        #pragma unroll
        for (int o = 16; o > 0; o >>= 1) s += __shfl_xor_sync(0xffffffffu, s, o);
        float mu = s * (1.0f/128.0f);
        float d0 = x[0]-mu, d1 = x[1]-mu, d2 = x[2]-mu, d3 = x[3]-mu;
        float v = d0*d0 + d1*d1 + d2*d2 + d3*d3;
        #pragma unroll
        for (int o = 16; o > 0; o >>= 1) v += __shfl_xor_sync(0xffffffffu, v, o);
        float rstd = rsqrtf(v * (1.0f/128.0f) + 1e-5f);
        float dd[4] = { d0*rstd, d1*rstd, d2*rstd, d3*rstd };
        #pragma unroll
        for (int j = 0; j < 4; j++) {
            uint32_t off = (uint32_t)(j >= 2) * 16384u
                         + SW128((uint32_t)(row*128 + (lane + 32*(j&1))*2));
            *(__half*)(smc + off) = __float2half_rn(dd[j]);
        }
    }

    // tri -> sTmp [d][132+r], LN over d, transpose -> A2 hi/lo
    #pragma unroll
    for (int m = 0; m < 8; m++) {
        int q = t + 512*m;
        int dd = q >> 5;
        int r4 = (q & 31) * 4;
        float4 f = *(const float4*)(g_t + (size_t)dd*NN + r0 + r4);
        *(float4*)&sTmp[dd*132 + r4] = f;
    }
    __syncthreads();
    for (int row = wid; row < 128; row += 16) ln_col(sTmp, row, lane);
    __syncthreads();
    for (int row = wid; row < 128; row += 16) {
        #pragma unroll
        for (int j = 0; j < 4; j++) {
            int k = lane + 32*j;
            float v = sTmp[k*132 + row];
            __half h = __float2half_rn(v);
            __half l = __float2half_rn(v - __half2float(h));
            uint32_t off = (uint32_t)(j >= 2) * 16384u
                         + SW128((uint32_t)(row*128 + (lane + 32*(j&1))*2));
            *(__half*)(smc + 32768 + off) = h;
            *(__half*)(smc + 65536 + off) = l;
        }
    }

    const int aRow = lane & 15;
    const int aK   = (lane >> 4) * 16;
    const int bRow = (lane & 7) + ((lane >> 4) << 3);
    const int bK   = ((lane >> 3) & 1) * 16;
    const int m0   = (wid & 3) * 32;
    const int n0   = (wid >> 2) * 16;

    for (int ot = 0; ot < 2; ot++) {
        const int o0 = ot * 64;
        __syncthreads();  // sTmp free / previous chunk done
        #pragma unroll
        for (int q = 0; q < 2; q++) {
            int seg = t + 512*q;          // 0..1023
            int ch  = seg >> 4;
            int s8  = seg & 15;
            uint32_t dst = ((s8 >= 8) ? 8192u : 0u) + SW128((uint32_t)(ch*128 + (s8 & 7)*16));
            *(uint4*)(smc +  98304 + dst) = *(const uint4*)(g_og  + (size_t)(o0 + ch)*128 + s8*8);
            *(uint4*)(smc + 114688 + dst) = *(const uint4*)(g_oph + (size_t)(o0 + ch)*128 + s8*8);
            *(uint4*)(smc + 131072 + dst) = *(const uint4*)(g_opl + (size_t)(o0 + ch)*128 + s8*8);
        }
        __syncthreads();

        float accg[2][2][4], accp[2][2][4];
        #pragma unroll
        for (int m = 0; m < 2; m++)
            #pragma unroll
            for (int n = 0; n < 2; n++)
                #pragma unroll
                for (int e = 0; e < 4; e++) { accg[m][n][e] = 0.f; accp[m][n][e] = 0.f; }

        #pragma unroll
        for (int kk = 0; kk < 8; kk++) {
            const uint32_t halfA = (uint32_t)(kk >> 2) * 16384u;
            const uint32_t halfW = (uint32_t)(kk >> 2) * 8192u;
            const uint32_t k32   = (uint32_t)(kk & 3) * 32u;

            uint32_t a1[2][4], a2h[2][4], a2l[2][4];
            #pragma unroll
            for (int f = 0; f < 2; f++) {
                uint32_t off = SW128((uint32_t)((m0 + f*16 + aRow)*128) + k32 + aK);
                ldm4(uA1  + halfA + off, a1[f]);
                ldm4(uA2h + halfA + off, a2h[f]);
                ldm4(uA2l + halfA + off, a2l[f]);
            }
            uint32_t og[4], ph[4], pl[4];
            {
                uint32_t off = SW128((uint32_t)((n0 + bRow)*128) + k32 + bK);
                ldm4(uW +     0 + halfW + off, og);
                ldm4(uW + 16384 + halfW + off, ph);
                ldm4(uW + 32768 + halfW + off, pl);
            }
            #pragma unroll
            for (int m = 0; m < 2; m++)
                #pragma unroll
                for (int n = 0; n < 2; n++) {
                    int bi = n * 2;
                    mma16816(accg[m][n], a1[m],  og[bi], og[bi+1]);
                    mma16816(accp[m][n], a2h[m], ph[bi], ph[bi+1]);
                    mma16816(accp[m][n], a2h[m], pl[bi], pl[bi+1]);
                    mma16816(accp[m][n], a2l[m], ph[bi], ph[bi+1]);
                }
        }

        #pragma unroll
        for (int m = 0; m < 2; m++) {
            int row0 = m0 + m*16 + (lane >> 2);
            #pragma unroll
            for (int n = 0; n < 2; n++) {
                int c0 = n0 + n*8 + (lane & 3)*2;
                float gb0 = __ldg(ogb + o0 + c0), gb1 = __ldg(ogb + o0 + c0 + 1);
                float pb0 = __ldg(opb + o0 + c0), pb1 = __ldg(opb + o0 + c0 + 1);
                float2 v0, v1;
                v0.x = sigmoidf_(accg[m][n][0] + gb0) * (accp[m][n][0] + pb0);
                v0.y = sigmoidf_(accg[m][n][1] + gb1) * (accp[m][n][1] + pb1);
                v1.x = sigmoidf_(accg[m][n][2] + gb0) * (accp[m][n][2] + pb0);
                v1.y = sigmoidf_(accg[m][n][3] + gb1) * (accp[m][n][3] + pb1);
                *(float2*)(out + (size_t)(r0 + row0)*DDIM + o0 + c0)     = v0;
                *(float2*)(out + (size_t)(r0 + row0 + 8)*DDIM + o0 + c0) = v1;
            }
        }
    }
}

// ============================================================================
extern "C" void kernel_launch(void* const* d_in, const int* in_sizes, int n_in,
                              void* d_out, int out_size)
{
    const float* pair = (const float*)d_in[0];
    const float* mask = (const float*)d_in[1];
    const float* apw  = (const float*)d_in[2];
    const float* apb  = (const float*)d_in[3];
    const float* agw  = (const float*)d_in[4];
    const float* agb  = (const float*)d_in[5];
    const float* opw  = (const float*)d_in[6];
    const float* opb  = (const float*)d_in[7];
    const float* ogw  = (const float*)d_in[8];
    const float* ogb  = (const float*)d_in[9];
    float* out = (float*)d_out;

    const size_t smA = 82432;    // 80.5 KB  -> 2 CTA/SM
    const size_t smB = 65536;    // 64 KB    -> 2 CTA/SM
    const size_t smC = 165888;   // 162 KB
    cudaFuncSetAttribute(kA, cudaFuncAttributeMaxDynamicSharedMemorySize, (int)smA);
    cudaFuncSetAttribute(kB, cudaFuncAttributeMaxDynamicSharedMemorySize, (int)smB);
    cudaFuncSetAttribute(kC, cudaFuncAttributeMaxDynamicSharedMemorySize, (int)smC);

    kW<<<128, 256>>>(agw, apw, ogw, opw);
    kA<<<NN/128, 256, smA>>>(pair, mask, apb, agb);
    kB<<<dim3(4, 4, DDIM), 256, smB>>>();
    kC<<<NN/128, 512, smC>>>(pair, opb, ogb, out);
}

// round 8
// speedup vs baseline: 4.1309x; 1.0743x over previous
#include <cuda_runtime.h>
#include <cuda_fp16.h>
#include <cstdint>
#include <cstddef>

#define NSEQ 512
#define DDIM 128
#define NN   (NSEQ*NSEQ)

// Scratch: a,b fp16 channel-major [d][i][k]; tri fp32 [d][i][j]
static __device__ __half g_af[(size_t)DDIM * NN];
static __device__ __half g_bf[(size_t)DDIM * NN];
static __device__ float  g_t[(size_t)DDIM * NN];

// Pre-converted weights (fp16), row-major [ch][k]
static __device__ __half g_wg[256*128];
static __device__ __half g_wp[256*128];
static __device__ __half g_og[128*128];
static __device__ __half g_oph[128*128], g_opl[128*128];

__device__ __forceinline__ float sigmoidf_(float x) { return 1.0f / (1.0f + __expf(-x)); }

__device__ __forceinline__ uint32_t smem_u32(const void* p) {
    uint32_t a;
    asm("{ .reg .u64 t; cvta.to.shared.u64 t, %1; cvt.u32.u64 %0, t; }" : "=r"(a) : "l"(p));
    return a;
}
#define SW128(o) ((o) ^ (((o) >> 3) & 0x70))

#define CP_ASYNC16(dst, src) \
    asm volatile("cp.async.cg.shared.global [%0], [%1], 16;" :: "r"(dst), "l"(src) : "memory")
#define CP_COMMIT() asm volatile("cp.async.commit_group;" ::: "memory")
#define CP_WAIT(n)  asm volatile("cp.async.wait_group %0;" :: "n"(n) : "memory")

__device__ __forceinline__ void ldm4(uint32_t addr, uint32_t r[4]) {
    asm volatile("ldmatrix.sync.aligned.m8n8.x4.shared.b16 {%0,%1,%2,%3}, [%4];"
        : "=r"(r[0]), "=r"(r[1]), "=r"(r[2]), "=r"(r[3]) : "r"(addr));
}
__device__ __forceinline__ void mma16816(float c[4], const uint32_t a[4],
                                         uint32_t b0, uint32_t b1) {
    asm volatile(
        "mma.sync.aligned.m16n8k16.row.col.f32.f16.f16.f32 "
        "{%0,%1,%2,%3}, {%4,%5,%6,%7}, {%8,%9}, {%0,%1,%2,%3};"
        : "+f"(c[0]), "+f"(c[1]), "+f"(c[2]), "+f"(c[3])
        : "r"(a[0]), "r"(a[1]), "r"(a[2]), "r"(a[3]), "r"(b0), "r"(b1));
}

// ============================================================================
__global__ void __launch_bounds__(256) kW(
    const float* __restrict__ agw, const float* __restrict__ apw,
    const float* __restrict__ ogw, const float* __restrict__ opw)
{
    int i = blockIdx.x * 256 + threadIdx.x;
    if (i < 256*128) {
        g_wg[i] = __float2half_rn(agw[i]);
        g_wp[i] = __float2half_rn(apw[i]);
    }
    if (i < 128*128) {
        g_og[i] = __float2half_rn(ogw[i]);
        float p = opw[i];
        __half ph = __float2half_rn(p);
        g_oph[i] = ph;
        g_opl[i] = __float2half_rn(p - __half2float(ph));
    }
}

// ============================================================================
// Kernel A (fp16 1-term) — unchanged from R7
// ============================================================================
__global__ void __launch_bounds__(256, 2) kA(
    const float* __restrict__ pair, const float* __restrict__ mask,
    const float* __restrict__ apb, const float* __restrict__ agb)
{
    extern __shared__ char smc[];
    const uint32_t sbase = smem_u32(smc);
    const uint32_t uA  = sbase;
    const uint32_t uWg = sbase + 32768;
    const uint32_t uWp = sbase + 49152;
    __half* stgF = (__half*)(smc + 65536);
    float*  sM   = (float*)(smc + 81920);

    const int t    = threadIdx.x;
    const int lane = t & 31;
    const int wid  = t >> 5;
    const int r0   = blockIdx.x * 128;

    if (t < 128) sM[t] = mask[r0 + t];

    for (int row = wid; row < 128; row += 8) {
        const float* src = pair + (size_t)(r0 + row) * DDIM;
        float x[4] = { src[lane], src[lane+32], src[lane+64], src[lane+96] };
        float s = x[0] + x[1] + x[2] + x[3];
        #pragma unroll
        for (int o = 16; o > 0; o >>= 1) s += __shfl_xor_sync(0xffffffffu, s, o);
        float mu = s * (1.0f/128.0f);
        float d0 = x[0]-mu, d1 = x[1]-mu, d2 = x[2]-mu, d3 = x[3]-mu;
        float v = d0*d0 + d1*d1 + d2*d2 + d3*d3;
        #pragma unroll
        for (int o = 16; o > 0; o >>= 1) v += __shfl_xor_sync(0xffffffffu, v, o);
        float rstd = rsqrtf(v * (1.0f/128.0f) + 1e-5f);
        float dd[4] = { d0*rstd, d1*rstd, d2*rstd, d3*rstd };
        #pragma unroll
        for (int j = 0; j < 4; j++) {
            uint32_t off = (uint32_t)(j >= 2) * 16384u
                         + SW128((uint32_t)(row*128 + (lane + 32*(j&1))*2));
            *(__half*)(smc + off) = __float2half_rn(dd[j]);
        }
    }

    const int aRow = lane & 15;
    const int aK   = (lane >> 4) * 16;
    const int bRow = (lane & 7) + ((lane >> 4) << 3);
    const int bK   = ((lane >> 3) & 1) * 16;
    const int m0   = (wid & 1) * 64;
    const int n0   = (wid >> 1) * 16;

    for (int ct = 0; ct < 4; ct++) {
        const int ch0 = ct * 64;
        __syncthreads();
        #pragma unroll
        for (int q = 0; q < 4; q++) {
            int seg = t + 256*q;
            int ch  = seg >> 4;
            int s8  = seg & 15;
            uint32_t dst = ((s8 >= 8) ? 8192u : 0u) + SW128((uint32_t)(ch*128 + (s8 & 7)*16));
            *(uint4*)(smc + 32768 + dst) = *(const uint4*)(g_wg + (size_t)(ch0 + ch)*128 + s8*8);
            *(uint4*)(smc + 49152 + dst) = *(const uint4*)(g_wp + (size_t)(ch0 + ch)*128 + s8*8);
        }
        __syncthreads();

        float accg[4][2][4], accp[4][2][4];
        #pragma unroll
        for (int m = 0; m < 4; m++)
            #pragma unroll
            for (int n = 0; n < 2; n++)
                #pragma unroll
                for (int e = 0; e < 4; e++) { accg[m][n][e] = 0.f; accp[m][n][e] = 0.f; }

        #pragma unroll
        for (int kk = 0; kk < 8; kk++) {
            const uint32_t halfA = (uint32_t)(kk >> 2) * 16384u;
            const uint32_t halfW = (uint32_t)(kk >> 2) * 8192u;
            const uint32_t k32   = (uint32_t)(kk & 3) * 32u;

            uint32_t ah[4][4];
            #pragma unroll
            for (int f = 0; f < 4; f++) {
                uint32_t off = SW128((uint32_t)((m0 + f*16 + aRow)*128) + k32 + aK);
                ldm4(uA + halfA + off, ah[f]);
            }
            uint32_t gh[4], ph[4];
            {
                uint32_t off = SW128((uint32_t)((n0 + bRow)*128) + k32 + bK);
                ldm4(uWg + halfW + off, gh);
                ldm4(uWp + halfW + off, ph);
            }
            #pragma unroll
            for (int m = 0; m < 4; m++)
                #pragma unroll
                for (int n = 0; n < 2; n++) {
                    mma16816(accg[m][n], ah[m], gh[n*2], gh[n*2+1]);
                    mma16816(accp[m][n], ah[m], ph[n*2], ph[n*2+1]);
                }
        }

        #pragma unroll
        for (int m = 0; m < 4; m++) {
            int row0 = m0 + m*16 + (lane >> 2);
            #pragma unroll
            for (int n = 0; n < 2; n++) {
                int c0 = n0 + n*8 + (lane & 3)*2;
                float gb0 = __ldg(agb + ch0 + c0), gb1 = __ldg(agb + ch0 + c0 + 1);
                float pb0 = __ldg(apb + ch0 + c0), pb1 = __ldg(apb + ch0 + c0 + 1);
                float mv0 = sM[row0], mv1 = sM[row0 + 8];
                float vals[4];
                vals[0] = mv0 * sigmoidf_(accg[m][n][0] + gb0) * (accp[m][n][0] + pb0);
                vals[1] = mv0 * sigmoidf_(accg[m][n][1] + gb1) * (accp[m][n][1] + pb1);
                vals[2] = mv1 * sigmoidf_(accg[m][n][2] + gb0) * (accp[m][n][2] + pb0);
                vals[3] = mv1 * sigmoidf_(accg[m][n][3] + gb1) * (accp[m][n][3] + pb1);
                #pragma unroll
                for (int e = 0; e < 4; e++) {
                    int cc = c0 + (e & 1);
                    int rr = row0 + (e >> 1) * 8;
                    stgF[cc*128 + rr] = __float2half_rn(vals[e]);
                }
            }
        }
        __syncthreads();

        __half* dst = (ch0 < 128) ? (g_af + (size_t)ch0 * NN)
                                  : (g_bf + (size_t)(ch0 - 128) * NN);
        #pragma unroll
        for (int q = 0; q < 4; q++) {
            int seg = t + 256*q;
            int ch  = seg >> 4;
            int r8  = (seg & 15) * 8;
            *(uint4*)(dst + (size_t)ch * NN + r0 + r8) = *(const uint4*)(stgF + ch*128 + r8);
        }
    }
}

// ============================================================================
// Kernel B (fp16 1-term) — unchanged from R7
// ============================================================================
__global__ void __launch_bounds__(256, 2) kB()
{
    extern __shared__ char smc[];
    const uint32_t sbase = smem_u32(smc);

    const int t    = threadIdx.x;
    const int lane = t & 31;
    const int wid  = t >> 5;
    const int d    = blockIdx.z;
    const int i0   = blockIdx.x * 128;
    const int j0   = blockIdx.y * 128;

    const int m0 = (wid & 1) * 64;
    const int n0 = (wid >> 1) * 32;

    const __half* srcA = g_af + (size_t)d*NN + (size_t)i0*NSEQ;
    const __half* srcB = g_bf + (size_t)d*NN + (size_t)j0*NSEQ;

    auto issue = [&](int stage, int kc) {
        uint32_t sb = sbase + stage * 32768;
        #pragma unroll
        for (int q = 0; q < 4; q++) {
            int seg = t + 256*q;
            int row = seg >> 3;
            int s   = seg & 7;
            uint32_t off = SW128((uint32_t)(row*128 + s*16));
            CP_ASYNC16(sb + off,         srcA + (size_t)row*NSEQ + kc + s*8);
            CP_ASYNC16(sb + 16384 + off, srcB + (size_t)row*NSEQ + kc + s*8);
        }
        CP_COMMIT();
    };

    float acc[4][4][4];
    #pragma unroll
    for (int m = 0; m < 4; m++)
        #pragma unroll
        for (int n = 0; n < 4; n++)
            #pragma unroll
            for (int e = 0; e < 4; e++) acc[m][n][e] = 0.0f;

    const int aRow = lane & 15;
    const int aK   = (lane >> 4) * 16;
    const int bRow = (lane & 7) + ((lane >> 4) << 3);
    const int bK   = ((lane >> 3) & 1) * 16;

    issue(0, 0);

    for (int ch = 0; ch < 8; ch++) {
        const int stage = ch & 1;
        if (ch < 7) { issue(stage ^ 1, (ch + 1) * 64); CP_WAIT(1); }
        else        { CP_WAIT(0); }
        __syncthreads();

        const uint32_t sA = sbase + stage * 32768;
        const uint32_t sB = sA + 16384;

        #pragma unroll
        for (int kk = 0; kk < 4; kk++) {
            const uint32_t kOffA = (uint32_t)(kk*32) + aK;
            const uint32_t kOffB = (uint32_t)(kk*32) + bK;

            uint32_t bh[2][4];
            #pragma unroll
            for (int c = 0; c < 2; c++) {
                uint32_t off = (uint32_t)((n0 + c*16 + bRow) * 128) + kOffB;
                ldm4(sB + SW128(off), bh[c]);
            }
            uint32_t ah[4][4];
            #pragma unroll
            for (int f = 0; f < 4; f++) {
                uint32_t off = (uint32_t)((m0 + f*16 + aRow) * 128) + kOffA;
                ldm4(sA + SW128(off), ah[f]);
            }
            #pragma unroll
            for (int m = 0; m < 4; m++)
                #pragma unroll
                for (int n = 0; n < 4; n++)
                    mma16816(acc[m][n], ah[m], bh[n>>1][(n&1)*2], bh[n>>1][(n&1)*2+1]);
        }
        __syncthreads();
    }

    float* base = g_t + (size_t)d*NN;
    #pragma unroll
    for (int m = 0; m < 4; m++) {
        int r1 = i0 + m0 + m*16 + (lane >> 2);
        #pragma unroll
        for (int n = 0; n < 4; n++) {
            int c = j0 + n0 + n*8 + (lane & 3)*2;
            float2 lo = make_float2(acc[m][n][0], acc[m][n][1]);
            float2 hi = make_float2(acc[m][n][2], acc[m][n][3]);
            *(float2*)(base + (size_t)r1*NSEQ + c)       = lo;
            *(float2*)(base + (size_t)(r1+8)*NSEQ + c)   = hi;
        }
    }
}

// ============================================================================
// Kernel C (restructured): 64-row blocks, 256 thr, 96KB smem -> 2 CTA/SM.
// smem: A1 16K @0 | A2h 16K @16384 | A2l 16K @32768 |
//       region @49152: sTmp fp32[128][65] (33.3K) then W og/oph/opl 3x16K
// 8 warps: m0=(wid&1)*32 (2 m-groups), n0=(wid>>1)*16 (4 n-groups).
// ============================================================================
__global__ void __launch_bounds__(256, 2) kC(
    const float* __restrict__ pair,
    const float* __restrict__ opb, const float* __restrict__ ogb,
    float* __restrict__ out)
{
    extern __shared__ char smc[];
    const uint32_t sbase = smem_u32(smc);
    const uint32_t uA1  = sbase;
    const uint32_t uA2h = sbase + 16384;
    const uint32_t uA2l = sbase + 32768;
    const uint32_t uW   = sbase + 49152;
    float* sTmp = (float*)(smc + 49152);   // 128 x 65 fp32

    const int t    = threadIdx.x;
    const int lane = t & 31;
    const int wid  = t >> 5;
    const int r0   = blockIdx.x * 64;

    // pair LN -> A1 fp16 (64 rows; two 64-k halves of 8KB)
    for (int row = wid; row < 64; row += 8) {
        const float* src = pair + (size_t)(r0 + row) * DDIM;
        float x[4] = { src[lane], src[lane+32], src[lane+64], src[lane+96] };
        float s = x[0] + x[1] + x[2] + x[3];
        #pragma unroll
        for (int o = 16; o > 0; o >>= 1) s += __shfl_xor_sync(0xffffffffu, s, o);
        float mu = s * (1.0f/128.0f);
        float d0 = x[0]-mu, d1 = x[1]-mu, d2 = x[2]-mu, d3 = x[3]-mu;
        float v = d0*d0 + d1*d1 + d2*d2 + d3*d3;
        #pragma unroll
        for (int o = 16; o > 0; o >>= 1) v += __shfl_xor_sync(0xffffffffu, v, o);
        float rstd = rsqrtf(v * (1.0f/128.0f) + 1e-5f);
        float dd[4] = { d0*rstd, d1*rstd, d2*rstd, d3*rstd };
        #pragma unroll
        for (int j = 0; j < 4; j++) {
            uint32_t off = (uint32_t)(j >= 2) * 8192u
                         + SW128((uint32_t)(row*128 + (lane + 32*(j&1))*2));
            *(__half*)(smc + off) = __float2half_rn(dd[j]);
        }
    }

    // tri -> sTmp [d][65-stride], conflict-free (stride 65: lane*65 mod 32 = lane)
    #pragma unroll
    for (int q8 = 0; q8 < 8; q8++) {
        int q  = t + 256*q8;          // 0..2047
        int dd = q >> 4;              // 0..127
        int r4 = (q & 15) * 4;        // 0..60
        float4 f = *(const float4*)(g_t + (size_t)dd*NN + r0 + r4);
        float* dst = sTmp + dd*65 + r4;
        dst[0] = f.x; dst[1] = f.y; dst[2] = f.z; dst[3] = f.w;
    }
    __syncthreads();
    // LN over d for each of 64 rows (one warp per row)
    for (int row = wid; row < 64; row += 8) {
        float x0 = sTmp[(lane      )*65 + row];
        float x1 = sTmp[(lane + 32 )*65 + row];
        float x2 = sTmp[(lane + 64 )*65 + row];
        float x3 = sTmp[(lane + 96 )*65 + row];
        float sum = x0 + x1 + x2 + x3;
        #pragma unroll
        for (int o = 16; o > 0; o >>= 1) sum += __shfl_xor_sync(0xffffffffu, sum, o);
        float mu = sum * (1.0f/128.0f);
        float d0 = x0-mu, d1 = x1-mu, d2 = x2-mu, d3 = x3-mu;
        float v = d0*d0 + d1*d1 + d2*d2 + d3*d3;
        #pragma unroll
        for (int o = 16; o > 0; o >>= 1) v += __shfl_xor_sync(0xffffffffu, v, o);
        float rstd = rsqrtf(v * (1.0f/128.0f) + 1e-5f);
        float dd[4] = { d0*rstd, d1*rstd, d2*rstd, d3*rstd };
        // transpose-store directly into A2 hi/lo fp16 tiles
        #pragma unroll
        for (int j = 0; j < 4; j++) {
            float vv = dd[j];
            __half h = __float2half_rn(vv);
            __half l = __float2half_rn(vv - __half2float(h));
            uint32_t off = (uint32_t)(j >= 2) * 8192u
                         + SW128((uint32_t)(row*128 + (lane + 32*(j&1))*2));
            *(__half*)(smc + 16384 + off) = h;
            *(__half*)(smc + 32768 + off) = l;
        }
    }

    const int aRow = lane & 15;
    const int aK   = (lane >> 4) * 16;
    const int bRow = (lane & 7) + ((lane >> 4) << 3);
    const int bK   = ((lane >> 3) & 1) * 16;
    const int m0   = (wid & 1) * 32;
    const int n0   = (wid >> 1) * 16;

    for (int ot = 0; ot < 2; ot++) {
        const int o0 = ot * 64;
        __syncthreads();   // sTmp reads done (ot=0) / previous chunk done
        #pragma unroll
        for (int q = 0; q < 4; q++) {
            int seg = t + 256*q;          // 0..1023
            int ch  = seg >> 4;
            int s8  = seg & 15;
            uint32_t dst = ((s8 >= 8) ? 8192u : 0u) + SW128((uint32_t)(ch*128 + (s8 & 7)*16));
            *(uint4*)(smc + 49152 + dst) = *(const uint4*)(g_og  + (size_t)(o0 + ch)*128 + s8*8);
            *(uint4*)(smc + 65536 + dst) = *(const uint4*)(g_oph + (size_t)(o0 + ch)*128 + s8*8);
            *(uint4*)(smc + 81920 + dst) = *(const uint4*)(g_opl + (size_t)(o0 + ch)*128 + s8*8);
        }
        __syncthreads();

        float accg[2][2][4], accp[2][2][4];
        #pragma unroll
        for (int m = 0; m < 2; m++)
            #pragma unroll
            for (int n = 0; n < 2; n++)
                #pragma unroll
                for (int e = 0; e < 4; e++) { accg[m][n][e] = 0.f; accp[m][n][e] = 0.f; }

        #pragma unroll
        for (int kk = 0; kk < 8; kk++) {
            const uint32_t halfA = (uint32_t)(kk >> 2) * 8192u;
            const uint32_t halfW = (uint32_t)(kk >> 2) * 8192u;
            const uint32_t k32   = (uint32_t)(kk & 3) * 32u;

            uint32_t a1[2][4], a2h[2][4], a2l[2][4];
            #pragma unroll
            for (int f = 0; f < 2; f++) {
                uint32_t off = SW128((uint32_t)((m0 + f*16 + aRow)*128) + k32 + aK);
                ldm4(uA1  + halfA + off, a1[f]);
                ldm4(uA2h + halfA + off, a2h[f]);
                ldm4(uA2l + halfA + off, a2l[f]);
            }
            uint32_t og[4], ph[4], pl[4];
            {
                uint32_t off = SW128((uint32_t)((n0 + bRow)*128) + k32 + bK);
                ldm4(uW +     0 + halfW + off, og);
                ldm4(uW + 16384 + halfW + off, ph);
                ldm4(uW + 32768 + halfW + off, pl);
            }
            #pragma unroll
            for (int m = 0; m < 2; m++)
                #pragma unroll
                for (int n = 0; n < 2; n++) {
                    int bi = n * 2;
                    mma16816(accg[m][n], a1[m],  og[bi], og[bi+1]);
                    mma16816(accp[m][n], a2h[m], ph[bi], ph[bi+1]);
                    mma16816(accp[m][n], a2h[m], pl[bi], pl[bi+1]);
                    mma16816(accp[m][n], a2l[m], ph[bi], ph[bi+1]);
                }
        }

        #pragma unroll
        for (int m = 0; m < 2; m++) {
            int row0 = m0 + m*16 + (lane >> 2);
            #pragma unroll
            for (int n = 0; n < 2; n++) {
                int c0 = n0 + n*8 + (lane & 3)*2;
                float gb0 = __ldg(ogb + o0 + c0), gb1 = __ldg(ogb + o0 + c0 + 1);
                float pb0 = __ldg(opb + o0 + c0), pb1 = __ldg(opb + o0 + c0 + 1);
                float2 v0, v1;
                v0.x = sigmoidf_(accg[m][n][0] + gb0) * (accp[m][n][0] + pb0);
                v0.y = sigmoidf_(accg[m][n][1] + gb1) * (accp[m][n][1] + pb1);
                v1.x = sigmoidf_(accg[m][n][2] + gb0) * (accp[m][n][2] + pb0);
                v1.y = sigmoidf_(accg[m][n][3] + gb1) * (accp[m][n][3] + pb1);
                *(float2*)(out + (size_t)(r0 + row0)*DDIM + o0 + c0)     = v0;
                *(float2*)(out + (size_t)(r0 + row0 + 8)*DDIM + o0 + c0) = v1;
            }
        }
    }
}

// ============================================================================
extern "C" void kernel_launch(void* const* d_in, const int* in_sizes, int n_in,
                              void* d_out, int out_size)
{
    const float* pair = (const float*)d_in[0];
    const float* mask = (const float*)d_in[1];
    const float* apw  = (const float*)d_in[2];
    const float* apb  = (const float*)d_in[3];
    const float* agw  = (const float*)d_in[4];
    const float* agb  = (const float*)d_in[5];
    const float* opw  = (const float*)d_in[6];
    const float* opb  = (const float*)d_in[7];
    const float* ogw  = (const float*)d_in[8];
    const float* ogb  = (const float*)d_in[9];
    float* out = (float*)d_out;

    const size_t smA = 82432;    // 80.5 KB -> 2 CTA/SM
    const size_t smB = 65536;    // 64 KB   -> 2 CTA/SM
    const size_t smC = 98304;    // 96 KB   -> 2 CTA/SM
    cudaFuncSetAttribute(kA, cudaFuncAttributeMaxDynamicSharedMemorySize, (int)smA);
    cudaFuncSetAttribute(kB, cudaFuncAttributeMaxDynamicSharedMemorySize, (int)smB);
    cudaFuncSetAttribute(kC, cudaFuncAttributeMaxDynamicSharedMemorySize, (int)smC);

    kW<<<128, 256>>>(agw, apw, ogw, opw);
    kA<<<NN/128, 256, smA>>>(pair, mask, apb, agb);
    kB<<<dim3(4, 4, DDIM), 256, smB>>>();
    kC<<<NN/64, 256, smC>>>(pair, opb, ogb, out);
}

// round 9
// speedup vs baseline: 4.4603x; 1.0797x over previous
#include <cuda_runtime.h>
#include <cuda_fp16.h>
#include <cstdint>
#include <cstddef>

#define NSEQ 512
#define DDIM 128
#define NN   (NSEQ*NSEQ)

// Scratch: a,b fp16 channel-major [d][i][k]; tri fp32 [d][i][j]; gate row-major [r][ch]
static __device__ __half g_af[(size_t)DDIM * NN];
static __device__ __half g_bf[(size_t)DDIM * NN];
static __device__ float  g_t[(size_t)DDIM * NN];
static __device__ __half g_gate[(size_t)NN * DDIM];

// Pre-converted weights (fp16), row-major [ch][k]
static __device__ __half g_wg[256*128];
static __device__ __half g_wp[256*128];
static __device__ __half g_og[128*128];
static __device__ __half g_oph[128*128], g_opl[128*128];

__device__ __forceinline__ float sigmoidf_(float x) { return 1.0f / (1.0f + __expf(-x)); }

__device__ __forceinline__ uint32_t smem_u32(const void* p) {
    uint32_t a;
    asm("{ .reg .u64 t; cvta.to.shared.u64 t, %1; cvt.u32.u64 %0, t; }" : "=r"(a) : "l"(p));
    return a;
}
#define SW128(o) ((o) ^ (((o) >> 3) & 0x70))

#define CP_ASYNC16(dst, src) \
    asm volatile("cp.async.cg.shared.global [%0], [%1], 16;" :: "r"(dst), "l"(src) : "memory")
#define CP_COMMIT() asm volatile("cp.async.commit_group;" ::: "memory")
#define CP_WAIT(n)  asm volatile("cp.async.wait_group %0;" :: "n"(n) : "memory")

__device__ __forceinline__ void ldm4(uint32_t addr, uint32_t r[4]) {
    asm volatile("ldmatrix.sync.aligned.m8n8.x4.shared.b16 {%0,%1,%2,%3}, [%4];"
        : "=r"(r[0]), "=r"(r[1]), "=r"(r[2]), "=r"(r[3]) : "r"(addr));
}
__device__ __forceinline__ void mma16816(float c[4], const uint32_t a[4],
                                         uint32_t b0, uint32_t b1) {
    asm volatile(
        "mma.sync.aligned.m16n8k16.row.col.f32.f16.f16.f32 "
        "{%0,%1,%2,%3}, {%4,%5,%6,%7}, {%8,%9}, {%0,%1,%2,%3};"
        : "+f"(c[0]), "+f"(c[1]), "+f"(c[2]), "+f"(c[3])
        : "r"(a[0]), "r"(a[1]), "r"(a[2]), "r"(a[3]), "r"(b0), "r"(b1));
}

// ============================================================================
__global__ void __launch_bounds__(256) kW(
    const float* __restrict__ agw, const float* __restrict__ apw,
    const float* __restrict__ ogw, const float* __restrict__ opw)
{
    int i = blockIdx.x * 256 + threadIdx.x;
    if (i < 256*128) {
        g_wg[i] = __float2half_rn(agw[i]);
        g_wp[i] = __float2half_rn(apw[i]);
    }
    if (i < 128*128) {
        g_og[i] = __float2half_rn(ogw[i]);
        float p = opw[i];
        __half ph = __float2half_rn(p);
        g_oph[i] = ph;
        g_opl[i] = __float2half_rn(p - __half2float(ph));
    }
}

// ============================================================================
// Kernel A (fp16): LN(pair) -> ab gate/proj GEMM -> ab fp16 ch-major
//                  + out_gate GEMM -> sigmoid -> g_gate row-major fp16
// smem: A 32K | Wg 16K | Wp 16K | stage 16K | mask 512B  (~80.5KB, 2 CTA/SM)
// ============================================================================
__global__ void __launch_bounds__(256, 2) kA(
    const float* __restrict__ pair, const float* __restrict__ mask,
    const float* __restrict__ apb, const float* __restrict__ agb,
    const float* __restrict__ ogb)
{
    extern __shared__ char smc[];
    const uint32_t sbase = smem_u32(smc);
    const uint32_t uA  = sbase;
    const uint32_t uWg = sbase + 32768;
    const uint32_t uWp = sbase + 49152;
    __half* stgF = (__half*)(smc + 65536);
    float*  sM   = (float*)(smc + 81920);

    const int t    = threadIdx.x;
    const int lane = t & 31;
    const int wid  = t >> 5;
    const int r0   = blockIdx.x * 128;

    if (t < 128) sM[t] = mask[r0 + t];

    for (int row = wid; row < 128; row += 8) {
        const float* src = pair + (size_t)(r0 + row) * DDIM;
        float x[4] = { src[lane], src[lane+32], src[lane+64], src[lane+96] };
        float s = x[0] + x[1] + x[2] + x[3];
        #pragma unroll
        for (int o = 16; o > 0; o >>= 1) s += __shfl_xor_sync(0xffffffffu, s, o);
        float mu = s * (1.0f/128.0f);
        float d0 = x[0]-mu, d1 = x[1]-mu, d2 = x[2]-mu, d3 = x[3]-mu;
        float v = d0*d0 + d1*d1 + d2*d2 + d3*d3;
        #pragma unroll
        for (int o = 16; o > 0; o >>= 1) v += __shfl_xor_sync(0xffffffffu, v, o);
        float rstd = rsqrtf(v * (1.0f/128.0f) + 1e-5f);
        float dd[4] = { d0*rstd, d1*rstd, d2*rstd, d3*rstd };
        #pragma unroll
        for (int j = 0; j < 4; j++) {
            uint32_t off = (uint32_t)(j >= 2) * 16384u
                         + SW128((uint32_t)(row*128 + (lane + 32*(j&1))*2));
            *(__half*)(smc + off) = __float2half_rn(dd[j]);
        }
    }

    const int aRow = lane & 15;
    const int aK   = (lane >> 4) * 16;
    const int bRow = (lane & 7) + ((lane >> 4) << 3);
    const int bK   = ((lane >> 3) & 1) * 16;
    const int m0   = (wid & 1) * 64;
    const int n0   = (wid >> 1) * 16;

    // ---- ab gate/proj: 4 chunks of 64 ch ----
    for (int ct = 0; ct < 4; ct++) {
        const int ch0 = ct * 64;
        __syncthreads();
        #pragma unroll
        for (int q = 0; q < 4; q++) {
            int seg = t + 256*q;
            int ch  = seg >> 4;
            int s8  = seg & 15;
            uint32_t dst = ((s8 >= 8) ? 8192u : 0u) + SW128((uint32_t)(ch*128 + (s8 & 7)*16));
            *(uint4*)(smc + 32768 + dst) = *(const uint4*)(g_wg + (size_t)(ch0 + ch)*128 + s8*8);
            *(uint4*)(smc + 49152 + dst) = *(const uint4*)(g_wp + (size_t)(ch0 + ch)*128 + s8*8);
        }
        __syncthreads();

        float accg[4][2][4], accp[4][2][4];
        #pragma unroll
        for (int m = 0; m < 4; m++)
            #pragma unroll
            for (int n = 0; n < 2; n++)
                #pragma unroll
                for (int e = 0; e < 4; e++) { accg[m][n][e] = 0.f; accp[m][n][e] = 0.f; }

        #pragma unroll
        for (int kk = 0; kk < 8; kk++) {
            const uint32_t halfA = (uint32_t)(kk >> 2) * 16384u;
            const uint32_t halfW = (uint32_t)(kk >> 2) * 8192u;
            const uint32_t k32   = (uint32_t)(kk & 3) * 32u;

            uint32_t ah[4][4];
            #pragma unroll
            for (int f = 0; f < 4; f++) {
                uint32_t off = SW128((uint32_t)((m0 + f*16 + aRow)*128) + k32 + aK);
                ldm4(uA + halfA + off, ah[f]);
            }
            uint32_t gh[4], ph[4];
            {
                uint32_t off = SW128((uint32_t)((n0 + bRow)*128) + k32 + bK);
                ldm4(uWg + halfW + off, gh);
                ldm4(uWp + halfW + off, ph);
            }
            #pragma unroll
            for (int m = 0; m < 4; m++)
                #pragma unroll
                for (int n = 0; n < 2; n++) {
                    mma16816(accg[m][n], ah[m], gh[n*2], gh[n*2+1]);
                    mma16816(accp[m][n], ah[m], ph[n*2], ph[n*2+1]);
                }
        }

        #pragma unroll
        for (int m = 0; m < 4; m++) {
            int row0 = m0 + m*16 + (lane >> 2);
            #pragma unroll
            for (int n = 0; n < 2; n++) {
                int c0 = n0 + n*8 + (lane & 3)*2;
                float gb0 = __ldg(agb + ch0 + c0), gb1 = __ldg(agb + ch0 + c0 + 1);
                float pb0 = __ldg(apb + ch0 + c0), pb1 = __ldg(apb + ch0 + c0 + 1);
                float mv0 = sM[row0], mv1 = sM[row0 + 8];
                float vals[4];
                vals[0] = mv0 * sigmoidf_(accg[m][n][0] + gb0) * (accp[m][n][0] + pb0);
                vals[1] = mv0 * sigmoidf_(accg[m][n][1] + gb1) * (accp[m][n][1] + pb1);
                vals[2] = mv1 * sigmoidf_(accg[m][n][2] + gb0) * (accp[m][n][2] + pb0);
                vals[3] = mv1 * sigmoidf_(accg[m][n][3] + gb1) * (accp[m][n][3] + pb1);
                #pragma unroll
                for (int e = 0; e < 4; e++) {
                    int cc = c0 + (e & 1);
                    int rr = row0 + (e >> 1) * 8;
                    stgF[cc*128 + rr] = __float2half_rn(vals[e]);
                }
            }
        }
        __syncthreads();

        __half* dst = (ch0 < 128) ? (g_af + (size_t)ch0 * NN)
                                  : (g_bf + (size_t)(ch0 - 128) * NN);
        #pragma unroll
        for (int q = 0; q < 4; q++) {
            int seg = t + 256*q;
            int ch  = seg >> 4;
            int r8  = (seg & 15) * 8;
            *(uint4*)(dst + (size_t)ch * NN + r0 + r8) = *(const uint4*)(stgF + ch*128 + r8);
        }
    }

    // ---- out_gate: 2 chunks of 64 ch, reuses resident A tiles ----
    for (int gt = 0; gt < 2; gt++) {
        const int ch0 = gt * 64;
        __syncthreads();
        #pragma unroll
        for (int q = 0; q < 4; q++) {
            int seg = t + 256*q;
            int ch  = seg >> 4;
            int s8  = seg & 15;
            uint32_t dst = ((s8 >= 8) ? 8192u : 0u) + SW128((uint32_t)(ch*128 + (s8 & 7)*16));
            *(uint4*)(smc + 32768 + dst) = *(const uint4*)(g_og + (size_t)(ch0 + ch)*128 + s8*8);
        }
        __syncthreads();

        float accg[4][2][4];
        #pragma unroll
        for (int m = 0; m < 4; m++)
            #pragma unroll
            for (int n = 0; n < 2; n++)
                #pragma unroll
                for (int e = 0; e < 4; e++) accg[m][n][e] = 0.f;

        #pragma unroll
        for (int kk = 0; kk < 8; kk++) {
            const uint32_t halfA = (uint32_t)(kk >> 2) * 16384u;
            const uint32_t halfW = (uint32_t)(kk >> 2) * 8192u;
            const uint32_t k32   = (uint32_t)(kk & 3) * 32u;

            uint32_t ah[4][4];
            #pragma unroll
            for (int f = 0; f < 4; f++) {
                uint32_t off = SW128((uint32_t)((m0 + f*16 + aRow)*128) + k32 + aK);
                ldm4(uA + halfA + off, ah[f]);
            }
            uint32_t gh[4];
            {
                uint32_t off = SW128((uint32_t)((n0 + bRow)*128) + k32 + bK);
                ldm4(uWg + halfW + off, gh);
            }
            #pragma unroll
            for (int m = 0; m < 4; m++)
                #pragma unroll
                for (int n = 0; n < 2; n++)
                    mma16816(accg[m][n], ah[m], gh[n*2], gh[n*2+1]);
        }

        // epilogue: sigmoid -> stage row-major [row][64ch] -> g_gate
        #pragma unroll
        for (int m = 0; m < 4; m++) {
            int row0 = m0 + m*16 + (lane >> 2);
            #pragma unroll
            for (int n = 0; n < 2; n++) {
                int c0 = n0 + n*8 + (lane & 3)*2;
                float gb0 = __ldg(ogb + ch0 + c0), gb1 = __ldg(ogb + ch0 + c0 + 1);
                stgF[row0*64 + c0]         = __float2half_rn(sigmoidf_(accg[m][n][0] + gb0));
                stgF[row0*64 + c0 + 1]     = __float2half_rn(sigmoidf_(accg[m][n][1] + gb1));
                stgF[(row0+8)*64 + c0]     = __float2half_rn(sigmoidf_(accg[m][n][2] + gb0));
                stgF[(row0+8)*64 + c0 + 1] = __float2half_rn(sigmoidf_(accg[m][n][3] + gb1));
            }
        }
        __syncthreads();
        #pragma unroll
        for (int q = 0; q < 4; q++) {
            int seg = t + 256*q;          // 0..1023
            int row = seg >> 3;           // 0..127
            int c8  = (seg & 7) * 8;      // 0..56
            *(uint4*)(g_gate + (size_t)(r0 + row)*DDIM + ch0 + c8)
                = *(const uint4*)(stgF + row*64 + c8);
        }
    }
}

// ============================================================================
// Kernel B (fp16 1-term) — unchanged
// ============================================================================
__global__ void __launch_bounds__(256, 2) kB()
{
    extern __shared__ char smc[];
    const uint32_t sbase = smem_u32(smc);

    const int t    = threadIdx.x;
    const int lane = t & 31;
    const int wid  = t >> 5;
    const int d    = blockIdx.z;
    const int i0   = blockIdx.x * 128;
    const int j0   = blockIdx.y * 128;

    const int m0 = (wid & 1) * 64;
    const int n0 = (wid >> 1) * 32;

    const __half* srcA = g_af + (size_t)d*NN + (size_t)i0*NSEQ;
    const __half* srcB = g_bf + (size_t)d*NN + (size_t)j0*NSEQ;

    auto issue = [&](int stage, int kc) {
        uint32_t sb = sbase + stage * 32768;
        #pragma unroll
        for (int q = 0; q < 4; q++) {
            int seg = t + 256*q;
            int row = seg >> 3;
            int s   = seg & 7;
            uint32_t off = SW128((uint32_t)(row*128 + s*16));
            CP_ASYNC16(sb + off,         srcA + (size_t)row*NSEQ + kc + s*8);
            CP_ASYNC16(sb + 16384 + off, srcB + (size_t)row*NSEQ + kc + s*8);
        }
        CP_COMMIT();
    };

    float acc[4][4][4];
    #pragma unroll
    for (int m = 0; m < 4; m++)
        #pragma unroll
        for (int n = 0; n < 4; n++)
            #pragma unroll
            for (int e = 0; e < 4; e++) acc[m][n][e] = 0.0f;

    const int aRow = lane & 15;
    const int aK   = (lane >> 4) * 16;
    const int bRow = (lane & 7) + ((lane >> 4) << 3);
    const int bK   = ((lane >> 3) & 1) * 16;

    issue(0, 0);

    for (int ch = 0; ch < 8; ch++) {
        const int stage = ch & 1;
        if (ch < 7) { issue(stage ^ 1, (ch + 1) * 64); CP_WAIT(1); }
        else        { CP_WAIT(0); }
        __syncthreads();

        const uint32_t sA = sbase + stage * 32768;
        const uint32_t sB = sA + 16384;

        #pragma unroll
        for (int kk = 0; kk < 4; kk++) {
            const uint32_t kOffA = (uint32_t)(kk*32) + aK;
            const uint32_t kOffB = (uint32_t)(kk*32) + bK;

            uint32_t bh[2][4];
            #pragma unroll
            for (int c = 0; c < 2; c++) {
                uint32_t off = (uint32_t)((n0 + c*16 + bRow) * 128) + kOffB;
                ldm4(sB + SW128(off), bh[c]);
            }
            uint32_t ah[4][4];
            #pragma unroll
            for (int f = 0; f < 4; f++) {
                uint32_t off = (uint32_t)((m0 + f*16 + aRow) * 128) + kOffA;
                ldm4(sA + SW128(off), ah[f]);
            }
            #pragma unroll
            for (int m = 0; m < 4; m++)
                #pragma unroll
                for (int n = 0; n < 4; n++)
                    mma16816(acc[m][n], ah[m], bh[n>>1][(n&1)*2], bh[n>>1][(n&1)*2+1]);
        }
        __syncthreads();
    }

    float* base = g_t + (size_t)d*NN;
    #pragma unroll
    for (int m = 0; m < 4; m++) {
        int r1 = i0 + m0 + m*16 + (lane >> 2);
        #pragma unroll
        for (int n = 0; n < 4; n++) {
            int c = j0 + n0 + n*8 + (lane & 3)*2;
            float2 lo = make_float2(acc[m][n][0], acc[m][n][1]);
            float2 hi = make_float2(acc[m][n][2], acc[m][n][3]);
            *(float2*)(base + (size_t)r1*NSEQ + c)       = lo;
            *(float2*)(base + (size_t)(r1+8)*NSEQ + c)   = hi;
        }
    }
}

// ============================================================================
// Kernel C (proj-only): 64-row blocks, 256 thr, 96KB -> 2 CTA/SM.
// smem: A2h 16K @0 | A2l 16K @16384 |
//       @32768: sTmp fp32[128][65] (33.3K) then Wph 32K @32768, Wpl 32K @65536
// 8 warps 2m x 4n, warp tile 32 x 32; single pass over 128 ch.
// out = g_gate * (LN(tri) @ opw^T + opb)
// ============================================================================
__global__ void __launch_bounds__(256, 2) kC(
    const float* __restrict__ opb,
    float* __restrict__ out)
{
    extern __shared__ char smc[];
    const uint32_t sbase = smem_u32(smc);
    const uint32_t uA2h = sbase;
    const uint32_t uA2l = sbase + 16384;
    const uint32_t uWph = sbase + 32768;
    const uint32_t uWpl = sbase + 65536;
    float* sTmp = (float*)(smc + 32768);   // 128 x 65 fp32

    const int t    = threadIdx.x;
    const int lane = t & 31;
    const int wid  = t >> 5;
    const int r0   = blockIdx.x * 64;

    // tri -> sTmp (conflict-free stride 65)
    #pragma unroll
    for (int q8 = 0; q8 < 8; q8++) {
        int q  = t + 256*q8;
        int dd = q >> 4;
        int r4 = (q & 15) * 4;
        float4 f = *(const float4*)(g_t + (size_t)dd*NN + r0 + r4);
        float* dst = sTmp + dd*65 + r4;
        dst[0] = f.x; dst[1] = f.y; dst[2] = f.z; dst[3] = f.w;
    }
    __syncthreads();
    // LN over d per row, transpose -> A2 hi/lo tiles
    for (int row = wid; row < 64; row += 8) {
        float x0 = sTmp[(lane      )*65 + row];
        float x1 = sTmp[(lane + 32 )*65 + row];
        float x2 = sTmp[(lane + 64 )*65 + row];
        float x3 = sTmp[(lane + 96 )*65 + row];
        float sum = x0 + x1 + x2 + x3;
        #pragma unroll
        for (int o = 16; o > 0; o >>= 1) sum += __shfl_xor_sync(0xffffffffu, sum, o);
        float mu = sum * (1.0f/128.0f);
        float d0 = x0-mu, d1 = x1-mu, d2 = x2-mu, d3 = x3-mu;
        float v = d0*d0 + d1*d1 + d2*d2 + d3*d3;
        #pragma unroll
        for (int o = 16; o > 0; o >>= 1) v += __shfl_xor_sync(0xffffffffu, v, o);
        float rstd = rsqrtf(v * (1.0f/128.0f) + 1e-5f);
        float dd[4] = { d0*rstd, d1*rstd, d2*rstd, d3*rstd };
        #pragma unroll
        for (int j = 0; j < 4; j++) {
            float vv = dd[j];
            __half h = __float2half_rn(vv);
            __half l = __float2half_rn(vv - __half2float(h));
            uint32_t off = (uint32_t)(j >= 2) * 8192u
                         + SW128((uint32_t)(row*128 + (lane + 32*(j&1))*2));
            *(__half*)(smc + off)         = h;
            *(__half*)(smc + 16384 + off) = l;
        }
    }
    __syncthreads();   // sTmp reads done; W region free

    // load full W (128 ch x 128 k, hi+lo)
    #pragma unroll
    for (int q = 0; q < 8; q++) {
        int seg = t + 256*q;          // 0..2047
        int ch  = seg >> 4;           // 0..127
        int s8  = seg & 15;
        uint32_t dst = ((s8 >= 8) ? 16384u : 0u) + SW128((uint32_t)(ch*128 + (s8 & 7)*16));
        *(uint4*)(smc + 32768 + dst) = *(const uint4*)(g_oph + (size_t)ch*128 + s8*8);
        *(uint4*)(smc + 65536 + dst) = *(const uint4*)(g_opl + (size_t)ch*128 + s8*8);
    }
    __syncthreads();

    const int aRow = lane & 15;
    const int aK   = (lane >> 4) * 16;
    const int bRow = (lane & 7) + ((lane >> 4) << 3);
    const int bK   = ((lane >> 3) & 1) * 16;
    const int m0   = (wid & 1) * 32;
    const int n0   = (wid >> 1) * 32;

    float acc[2][4][4];
    #pragma unroll
    for (int m = 0; m < 2; m++)
        #pragma unroll
        for (int n = 0; n < 4; n++)
            #pragma unroll
            for (int e = 0; e < 4; e++) acc[m][n][e] = 0.f;

    #pragma unroll
    for (int kk = 0; kk < 8; kk++) {
        const uint32_t halfA = (uint32_t)(kk >> 2) * 8192u;
        const uint32_t halfW = (uint32_t)(kk >> 2) * 16384u;
        const uint32_t k32   = (uint32_t)(kk & 3) * 32u;

        uint32_t a2h[2][4], a2l[2][4];
        #pragma unroll
        for (int f = 0; f < 2; f++) {
            uint32_t off = SW128((uint32_t)((m0 + f*16 + aRow)*128) + k32 + aK);
            ldm4(uA2h + halfA + off, a2h[f]);
            ldm4(uA2l + halfA + off, a2l[f]);
        }
        uint32_t ph[2][4], pl[2][4];
        #pragma unroll
        for (int c = 0; c < 2; c++) {
            uint32_t off = SW128((uint32_t)((n0 + c*16 + bRow)*128) + k32 + bK);
            ldm4(uWph + halfW + off, ph[c]);
            ldm4(uWpl + halfW + off, pl[c]);
        }
        #pragma unroll
        for (int m = 0; m < 2; m++)
            #pragma unroll
            for (int n = 0; n < 4; n++) {
                int ci = n >> 1, bi = (n & 1) * 2;
                mma16816(acc[m][n], a2h[m], ph[ci][bi], ph[ci][bi+1]);
                mma16816(acc[m][n], a2h[m], pl[ci][bi], pl[ci][bi+1]);
                mma16816(acc[m][n], a2l[m], ph[ci][bi], ph[ci][bi+1]);
            }
    }

    // epilogue: out = gate * (acc + opb)
    #pragma unroll
    for (int m = 0; m < 2; m++) {
        int row0 = m0 + m*16 + (lane >> 2);
        #pragma unroll
        for (int n = 0; n < 4; n++) {
            int c0 = n0 + n*8 + (lane & 3)*2;
            float pb0 = __ldg(opb + c0), pb1 = __ldg(opb + c0 + 1);
            __half2 gv0 = *(const __half2*)(g_gate + (size_t)(r0 + row0)*DDIM + c0);
            __half2 gv1 = *(const __half2*)(g_gate + (size_t)(r0 + row0 + 8)*DDIM + c0);
            float2 g0 = __half22float2(gv0), g1 = __half22float2(gv1);
            float2 v0, v1;
            v0.x = g0.x * (acc[m][n][0] + pb0);
            v0.y = g0.y * (acc[m][n][1] + pb1);
            v1.x = g1.x * (acc[m][n][2] + pb0);
            v1.y = g1.y * (acc[m][n][3] + pb1);
            *(float2*)(out + (size_t)(r0 + row0)*DDIM + c0)     = v0;
            *(float2*)(out + (size_t)(r0 + row0 + 8)*DDIM + c0) = v1;
        }
    }
}

// ============================================================================
extern "C" void kernel_launch(void* const* d_in, const int* in_sizes, int n_in,
                              void* d_out, int out_size)
{
    const float* pair = (const float*)d_in[0];
    const float* mask = (const float*)d_in[1];
    const float* apw  = (const float*)d_in[2];
    const float* apb  = (const float*)d_in[3];
    const float* agw  = (const float*)d_in[4];
    const float* agb  = (const float*)d_in[5];
    const float* opw  = (const float*)d_in[6];
    const float* opb  = (const float*)d_in[7];
    const float* ogw  = (const float*)d_in[8];
    const float* ogb  = (const float*)d_in[9];
    float* out = (float*)d_out;

    const size_t smA = 82432;    // 80.5 KB -> 2 CTA/SM
    const size_t smB = 65536;    // 64 KB   -> 2 CTA/SM
    const size_t smC = 98304;    // 96 KB   -> 2 CTA/SM
    cudaFuncSetAttribute(kA, cudaFuncAttributeMaxDynamicSharedMemorySize, (int)smA);
    cudaFuncSetAttribute(kB, cudaFuncAttributeMaxDynamicSharedMemorySize, (int)smB);
    cudaFuncSetAttribute(kC, cudaFuncAttributeMaxDynamicSharedMemorySize, (int)smC);

    kW<<<128, 256>>>(agw, apw, ogw, opw);
    kA<<<NN/128, 256, smA>>>(pair, mask, apb, agb, ogb);
    kB<<<dim3(4, 4, DDIM), 256, smB>>>();
    kC<<<NN/64, 256, smC>>>(opb, out);
}

// round 10
// speedup vs baseline: 4.6084x; 1.0332x over previous
#include <cuda_runtime.h>
#include <cuda_fp16.h>
#include <cstdint>
#include <cstddef>

#define NSEQ 512
#define DDIM 128
#define NN   (NSEQ*NSEQ)

// Scratch: a,b fp16 channel-major [d][i][k]; tri fp32 [d][i][j]; gate row-major [r][ch]
static __device__ __half g_af[(size_t)DDIM * NN];
static __device__ __half g_bf[(size_t)DDIM * NN];
static __device__ float  g_t[(size_t)DDIM * NN];
static __device__ __half g_gate[(size_t)NN * DDIM];

// Pre-converted weights (fp16), row-major [ch][k]
static __device__ __half g_wg[256*128];
static __device__ __half g_wp[256*128];
static __device__ __half g_og[128*128];
static __device__ __half g_oph[128*128];

__device__ __forceinline__ float sigmoidf_(float x) { return 1.0f / (1.0f + __expf(-x)); }

__device__ __forceinline__ uint32_t smem_u32(const void* p) {
    uint32_t a;
    asm("{ .reg .u64 t; cvta.to.shared.u64 t, %1; cvt.u32.u64 %0, t; }" : "=r"(a) : "l"(p));
    return a;
}
#define SW128(o) ((o) ^ (((o) >> 3) & 0x70))

#define CP_ASYNC16(dst, src) \
    asm volatile("cp.async.cg.shared.global [%0], [%1], 16;" :: "r"(dst), "l"(src) : "memory")
#define CP_COMMIT() asm volatile("cp.async.commit_group;" ::: "memory")
#define CP_WAIT(n)  asm volatile("cp.async.wait_group %0;" :: "n"(n) : "memory")

__device__ __forceinline__ void ldm4(uint32_t addr, uint32_t r[4]) {
    asm volatile("ldmatrix.sync.aligned.m8n8.x4.shared.b16 {%0,%1,%2,%3}, [%4];"
        : "=r"(r[0]), "=r"(r[1]), "=r"(r[2]), "=r"(r[3]) : "r"(addr));
}
__device__ __forceinline__ void mma16816(float c[4], const uint32_t a[4],
                                         uint32_t b0, uint32_t b1) {
    asm volatile(
        "mma.sync.aligned.m16n8k16.row.col.f32.f16.f16.f32 "
        "{%0,%1,%2,%3}, {%4,%5,%6,%7}, {%8,%9}, {%0,%1,%2,%3};"
        : "+f"(c[0]), "+f"(c[1]), "+f"(c[2]), "+f"(c[3])
        : "r"(a[0]), "r"(a[1]), "r"(a[2]), "r"(a[3]), "r"(b0), "r"(b1));
}

// ============================================================================
__global__ void __launch_bounds__(256) kW(
    const float* __restrict__ agw, const float* __restrict__ apw,
    const float* __restrict__ ogw, const float* __restrict__ opw)
{
    int i = blockIdx.x * 256 + threadIdx.x;
    if (i < 256*128) {
        g_wg[i] = __float2half_rn(agw[i]);
        g_wp[i] = __float2half_rn(apw[i]);
    }
    if (i < 128*128) {
        g_og[i]  = __float2half_rn(ogw[i]);
        g_oph[i] = __float2half_rn(opw[i]);
    }
}

// ============================================================================
// Kernel A (fp16): LN(pair) -> ab gate/proj GEMM -> ab fp16 ch-major
//                  + out_gate GEMM -> sigmoid -> g_gate row-major fp16
// ============================================================================
__global__ void __launch_bounds__(256, 2) kA(
    const float* __restrict__ pair, const float* __restrict__ mask,
    const float* __restrict__ apb, const float* __restrict__ agb,
    const float* __restrict__ ogb)
{
    extern __shared__ char smc[];
    const uint32_t sbase = smem_u32(smc);
    const uint32_t uA  = sbase;
    const uint32_t uWg = sbase + 32768;
    const uint32_t uWp = sbase + 49152;
    __half* stgF = (__half*)(smc + 65536);
    float*  sM   = (float*)(smc + 81920);

    const int t    = threadIdx.x;
    const int lane = t & 31;
    const int wid  = t >> 5;
    const int r0   = blockIdx.x * 128;

    if (t < 128) sM[t] = mask[r0 + t];

    for (int row = wid; row < 128; row += 8) {
        const float* src = pair + (size_t)(r0 + row) * DDIM;
        float x[4] = { src[lane], src[lane+32], src[lane+64], src[lane+96] };
        float s = x[0] + x[1] + x[2] + x[3];
        #pragma unroll
        for (int o = 16; o > 0; o >>= 1) s += __shfl_xor_sync(0xffffffffu, s, o);
        float mu = s * (1.0f/128.0f);
        float d0 = x[0]-mu, d1 = x[1]-mu, d2 = x[2]-mu, d3 = x[3]-mu;
        float v = d0*d0 + d1*d1 + d2*d2 + d3*d3;
        #pragma unroll
        for (int o = 16; o > 0; o >>= 1) v += __shfl_xor_sync(0xffffffffu, v, o);
        float rstd = rsqrtf(v * (1.0f/128.0f) + 1e-5f);
        float dd[4] = { d0*rstd, d1*rstd, d2*rstd, d3*rstd };
        #pragma unroll
        for (int j = 0; j < 4; j++) {
            uint32_t off = (uint32_t)(j >= 2) * 16384u
                         + SW128((uint32_t)(row*128 + (lane + 32*(j&1))*2));
            *(__half*)(smc + off) = __float2half_rn(dd[j]);
        }
    }

    const int aRow = lane & 15;
    const int aK   = (lane >> 4) * 16;
    const int bRow = (lane & 7) + ((lane >> 4) << 3);
    const int bK   = ((lane >> 3) & 1) * 16;
    const int m0   = (wid & 1) * 64;
    const int n0   = (wid >> 1) * 16;

    // ---- ab gate/proj: 4 chunks of 64 ch ----
    for (int ct = 0; ct < 4; ct++) {
        const int ch0 = ct * 64;
        __syncthreads();
        #pragma unroll
        for (int q = 0; q < 4; q++) {
            int seg = t + 256*q;
            int ch  = seg >> 4;
            int s8  = seg & 15;
            uint32_t dst = ((s8 >= 8) ? 8192u : 0u) + SW128((uint32_t)(ch*128 + (s8 & 7)*16));
            *(uint4*)(smc + 32768 + dst) = *(const uint4*)(g_wg + (size_t)(ch0 + ch)*128 + s8*8);
            *(uint4*)(smc + 49152 + dst) = *(const uint4*)(g_wp + (size_t)(ch0 + ch)*128 + s8*8);
        }
        __syncthreads();

        float accg[4][2][4], accp[4][2][4];
        #pragma unroll
        for (int m = 0; m < 4; m++)
            #pragma unroll
            for (int n = 0; n < 2; n++)
                #pragma unroll
                for (int e = 0; e < 4; e++) { accg[m][n][e] = 0.f; accp[m][n][e] = 0.f; }

        #pragma unroll
        for (int kk = 0; kk < 8; kk++) {
            const uint32_t halfA = (uint32_t)(kk >> 2) * 16384u;
            const uint32_t halfW = (uint32_t)(kk >> 2) * 8192u;
            const uint32_t k32   = (uint32_t)(kk & 3) * 32u;

            uint32_t ah[4][4];
            #pragma unroll
            for (int f = 0; f < 4; f++) {
                uint32_t off = SW128((uint32_t)((m0 + f*16 + aRow)*128) + k32 + aK);
                ldm4(uA + halfA + off, ah[f]);
            }
            uint32_t gh[4], ph[4];
            {
                uint32_t off = SW128((uint32_t)((n0 + bRow)*128) + k32 + bK);
                ldm4(uWg + halfW + off, gh);
                ldm4(uWp + halfW + off, ph);
            }
            #pragma unroll
            for (int m = 0; m < 4; m++)
                #pragma unroll
                for (int n = 0; n < 2; n++) {
                    mma16816(accg[m][n], ah[m], gh[n*2], gh[n*2+1]);
                    mma16816(accp[m][n], ah[m], ph[n*2], ph[n*2+1]);
                }
        }

        #pragma unroll
        for (int m = 0; m < 4; m++) {
            int row0 = m0 + m*16 + (lane >> 2);
            #pragma unroll
            for (int n = 0; n < 2; n++) {
                int c0 = n0 + n*8 + (lane & 3)*2;
                float gb0 = __ldg(agb + ch0 + c0), gb1 = __ldg(agb + ch0 + c0 + 1);
                float pb0 = __ldg(apb + ch0 + c0), pb1 = __ldg(apb + ch0 + c0 + 1);
                float mv0 = sM[row0], mv1 = sM[row0 + 8];
                float vals[4];
                vals[0] = mv0 * sigmoidf_(accg[m][n][0] + gb0) * (accp[m][n][0] + pb0);
                vals[1] = mv0 * sigmoidf_(accg[m][n][1] + gb1) * (accp[m][n][1] + pb1);
                vals[2] = mv1 * sigmoidf_(accg[m][n][2] + gb0) * (accp[m][n][2] + pb0);
                vals[3] = mv1 * sigmoidf_(accg[m][n][3] + gb1) * (accp[m][n][3] + pb1);
                #pragma unroll
                for (int e = 0; e < 4; e++) {
                    int cc = c0 + (e & 1);
                    int rr = row0 + (e >> 1) * 8;
                    stgF[cc*128 + rr] = __float2half_rn(vals[e]);
                }
            }
        }
        __syncthreads();

        __half* dst = (ch0 < 128) ? (g_af + (size_t)ch0 * NN)
                                  : (g_bf + (size_t)(ch0 - 128) * NN);
        #pragma unroll
        for (int q = 0; q < 4; q++) {
            int seg = t + 256*q;
            int ch  = seg >> 4;
            int r8  = (seg & 15) * 8;
            *(uint4*)(dst + (size_t)ch * NN + r0 + r8) = *(const uint4*)(stgF + ch*128 + r8);
        }
    }

    // ---- out_gate: 2 chunks of 64 ch, reuses resident A tiles ----
    for (int gt = 0; gt < 2; gt++) {
        const int ch0 = gt * 64;
        __syncthreads();
        #pragma unroll
        for (int q = 0; q < 4; q++) {
            int seg = t + 256*q;
            int ch  = seg >> 4;
            int s8  = seg & 15;
            uint32_t dst = ((s8 >= 8) ? 8192u : 0u) + SW128((uint32_t)(ch*128 + (s8 & 7)*16));
            *(uint4*)(smc + 32768 + dst) = *(const uint4*)(g_og + (size_t)(ch0 + ch)*128 + s8*8);
        }
        __syncthreads();

        float accg[4][2][4];
        #pragma unroll
        for (int m = 0; m < 4; m++)
            #pragma unroll
            for (int n = 0; n < 2; n++)
                #pragma unroll
                for (int e = 0; e < 4; e++) accg[m][n][e] = 0.f;

        #pragma unroll
        for (int kk = 0; kk < 8; kk++) {
            const uint32_t halfA = (uint32_t)(kk >> 2) * 16384u;
            const uint32_t halfW = (uint32_t)(kk >> 2) * 8192u;
            const uint32_t k32   = (uint32_t)(kk & 3) * 32u;

            uint32_t ah[4][4];
            #pragma unroll
            for (int f = 0; f < 4; f++) {
                uint32_t off = SW128((uint32_t)((m0 + f*16 + aRow)*128) + k32 + aK);
                ldm4(uA + halfA + off, ah[f]);
            }
            uint32_t gh[4];
            {
                uint32_t off = SW128((uint32_t)((n0 + bRow)*128) + k32 + bK);
                ldm4(uWg + halfW + off, gh);
            }
            #pragma unroll
            for (int m = 0; m < 4; m++)
                #pragma unroll
                for (int n = 0; n < 2; n++)
                    mma16816(accg[m][n], ah[m], gh[n*2], gh[n*2+1]);
        }

        #pragma unroll
        for (int m = 0; m < 4; m++) {
            int row0 = m0 + m*16 + (lane >> 2);
            #pragma unroll
            for (int n = 0; n < 2; n++) {
                int c0 = n0 + n*8 + (lane & 3)*2;
                float gb0 = __ldg(ogb + ch0 + c0), gb1 = __ldg(ogb + ch0 + c0 + 1);
                stgF[row0*64 + c0]         = __float2half_rn(sigmoidf_(accg[m][n][0] + gb0));
                stgF[row0*64 + c0 + 1]     = __float2half_rn(sigmoidf_(accg[m][n][1] + gb1));
                stgF[(row0+8)*64 + c0]     = __float2half_rn(sigmoidf_(accg[m][n][2] + gb0));
                stgF[(row0+8)*64 + c0 + 1] = __float2half_rn(sigmoidf_(accg[m][n][3] + gb1));
            }
        }
        __syncthreads();
        #pragma unroll
        for (int q = 0; q < 4; q++) {
            int seg = t + 256*q;
            int row = seg >> 3;
            int c8  = (seg & 7) * 8;
            *(uint4*)(g_gate + (size_t)(r0 + row)*DDIM + ch0 + c8)
                = *(const uint4*)(stgF + row*64 + c8);
        }
    }
}

// ============================================================================
// Kernel B (fp16 1-term) — unchanged
// ============================================================================
__global__ void __launch_bounds__(256, 2) kB()
{
    extern __shared__ char smc[];
    const uint32_t sbase = smem_u32(smc);

    const int t    = threadIdx.x;
    const int lane = t & 31;
    const int wid  = t >> 5;
    const int d    = blockIdx.z;
    const int i0   = blockIdx.x * 128;
    const int j0   = blockIdx.y * 128;

    const int m0 = (wid & 1) * 64;
    const int n0 = (wid >> 1) * 32;

    const __half* srcA = g_af + (size_t)d*NN + (size_t)i0*NSEQ;
    const __half* srcB = g_bf + (size_t)d*NN + (size_t)j0*NSEQ;

    auto issue = [&](int stage, int kc) {
        uint32_t sb = sbase + stage * 32768;
        #pragma unroll
        for (int q = 0; q < 4; q++) {
            int seg = t + 256*q;
            int row = seg >> 3;
            int s   = seg & 7;
            uint32_t off = SW128((uint32_t)(row*128 + s*16));
            CP_ASYNC16(sb + off,         srcA + (size_t)row*NSEQ + kc + s*8);
            CP_ASYNC16(sb + 16384 + off, srcB + (size_t)row*NSEQ + kc + s*8);
        }
        CP_COMMIT();
    };

    float acc[4][4][4];
    #pragma unroll
    for (int m = 0; m < 4; m++)
        #pragma unroll
        for (int n = 0; n < 4; n++)
            #pragma unroll
            for (int e = 0; e < 4; e++) acc[m][n][e] = 0.0f;

    const int aRow = lane & 15;
    const int aK   = (lane >> 4) * 16;
    const int bRow = (lane & 7) + ((lane >> 4) << 3);
    const int bK   = ((lane >> 3) & 1) * 16;

    issue(0, 0);

    for (int ch = 0; ch < 8; ch++) {
        const int stage = ch & 1;
        if (ch < 7) { issue(stage ^ 1, (ch + 1) * 64); CP_WAIT(1); }
        else        { CP_WAIT(0); }
        __syncthreads();

        const uint32_t sA = sbase + stage * 32768;
        const uint32_t sB = sA + 16384;

        #pragma unroll
        for (int kk = 0; kk < 4; kk++) {
            const uint32_t kOffA = (uint32_t)(kk*32) + aK;
            const uint32_t kOffB = (uint32_t)(kk*32) + bK;

            uint32_t bh[2][4];
            #pragma unroll
            for (int c = 0; c < 2; c++) {
                uint32_t off = (uint32_t)((n0 + c*16 + bRow) * 128) + kOffB;
                ldm4(sB + SW128(off), bh[c]);
            }
            uint32_t ah[4][4];
            #pragma unroll
            for (int f = 0; f < 4; f++) {
                uint32_t off = (uint32_t)((m0 + f*16 + aRow) * 128) + kOffA;
                ldm4(sA + SW128(off), ah[f]);
            }
            #pragma unroll
            for (int m = 0; m < 4; m++)
                #pragma unroll
                for (int n = 0; n < 4; n++)
                    mma16816(acc[m][n], ah[m], bh[n>>1][(n&1)*2], bh[n>>1][(n&1)*2+1]);
        }
        __syncthreads();
    }

    float* base = g_t + (size_t)d*NN;
    #pragma unroll
    for (int m = 0; m < 4; m++) {
        int r1 = i0 + m0 + m*16 + (lane >> 2);
        #pragma unroll
        for (int n = 0; n < 4; n++) {
            int c = j0 + n0 + n*8 + (lane & 3)*2;
            float2 lo = make_float2(acc[m][n][0], acc[m][n][1]);
            float2 hi = make_float2(acc[m][n][2], acc[m][n][3]);
            *(float2*)(base + (size_t)r1*NSEQ + c)       = lo;
            *(float2*)(base + (size_t)(r1+8)*NSEQ + c)   = hi;
        }
    }
}

// ============================================================================
// Kernel C (proj 2-term): 64-row blocks, 256 thr, ~64.5KB smem.
// smem: A2h 16K @0 | A2l 16K @16384 | @32768: sTmp fp32[128][65] / Wph 32K
// out = g_gate * (LN(tri) @ opw^T + opb);  proj = a2h*ph + a2l*ph
// ============================================================================
__global__ void __launch_bounds__(256, 2) kC(
    const float* __restrict__ opb,
    float* __restrict__ out)
{
    extern __shared__ char smc[];
    const uint32_t sbase = smem_u32(smc);
    const uint32_t uA2h = sbase;
    const uint32_t uA2l = sbase + 16384;
    const uint32_t uWph = sbase + 32768;
    float* sTmp = (float*)(smc + 32768);   // 128 x 65 fp32

    const int t    = threadIdx.x;
    const int lane = t & 31;
    const int wid  = t >> 5;
    const int r0   = blockIdx.x * 64;

    // tri -> sTmp (conflict-free stride 65)
    #pragma unroll
    for (int q8 = 0; q8 < 8; q8++) {
        int q  = t + 256*q8;
        int dd = q >> 4;
        int r4 = (q & 15) * 4;
        float4 f = *(const float4*)(g_t + (size_t)dd*NN + r0 + r4);
        float* dst = sTmp + dd*65 + r4;
        dst[0] = f.x; dst[1] = f.y; dst[2] = f.z; dst[3] = f.w;
    }
    __syncthreads();
    // LN over d per row, transpose -> A2 hi/lo tiles
    for (int row = wid; row < 64; row += 8) {
        float x0 = sTmp[(lane      )*65 + row];
        float x1 = sTmp[(lane + 32 )*65 + row];
        float x2 = sTmp[(lane + 64 )*65 + row];
        float x3 = sTmp[(lane + 96 )*65 + row];
        float sum = x0 + x1 + x2 + x3;
        #pragma unroll
        for (int o = 16; o > 0; o >>= 1) sum += __shfl_xor_sync(0xffffffffu, sum, o);
        float mu = sum * (1.0f/128.0f);
        float d0 = x0-mu, d1 = x1-mu, d2 = x2-mu, d3 = x3-mu;
        float v = d0*d0 + d1*d1 + d2*d2 + d3*d3;
        #pragma unroll
        for (int o = 16; o > 0; o >>= 1) v += __shfl_xor_sync(0xffffffffu, v, o);
        float rstd = rsqrtf(v * (1.0f/128.0f) + 1e-5f);
        float dd[4] = { d0*rstd, d1*rstd, d2*rstd, d3*rstd };
        #pragma unroll
        for (int j = 0; j < 4; j++) {
            float vv = dd[j];
            __half h = __float2half_rn(vv);
            __half l = __float2half_rn(vv - __half2float(h));
            uint32_t off = (uint32_t)(j >= 2) * 8192u
                         + SW128((uint32_t)(row*128 + (lane + 32*(j&1))*2));
            *(__half*)(smc + off)         = h;
            *(__half*)(smc + 16384 + off) = l;
        }
    }
    __syncthreads();   // sTmp reads done; W region free

    // load full Wph (128 ch x 128 k)
    #pragma unroll
    for (int q = 0; q < 8; q++) {
        int seg = t + 256*q;          // 0..2047
        int ch  = seg >> 4;           // 0..127
        int s8  = seg & 15;
        uint32_t dst = ((s8 >= 8) ? 16384u : 0u) + SW128((uint32_t)(ch*128 + (s8 & 7)*16));
        *(uint4*)(smc + 32768 + dst) = *(const uint4*)(g_oph + (size_t)ch*128 + s8*8);
    }
    __syncthreads();

    const int aRow = lane & 15;
    const int aK   = (lane >> 4) * 16;
    const int bRow = (lane & 7) + ((lane >> 4) << 3);
    const int bK   = ((lane >> 3) & 1) * 16;
    const int m0   = (wid & 1) * 32;
    const int n0   = (wid >> 1) * 32;

    float acc[2][4][4];
    #pragma unroll
    for (int m = 0; m < 2; m++)
        #pragma unroll
        for (int n = 0; n < 4; n++)
            #pragma unroll
            for (int e = 0; e < 4; e++) acc[m][n][e] = 0.f;

    #pragma unroll
    for (int kk = 0; kk < 8; kk++) {
        const uint32_t halfA = (uint32_t)(kk >> 2) * 8192u;
        const uint32_t halfW = (uint32_t)(kk >> 2) * 16384u;
        const uint32_t k32   = (uint32_t)(kk & 3) * 32u;

        uint32_t a2h[2][4], a2l[2][4];
        #pragma unroll
        for (int f = 0; f < 2; f++) {
            uint32_t off = SW128((uint32_t)((m0 + f*16 + aRow)*128) + k32 + aK);
            ldm4(uA2h + halfA + off, a2h[f]);
            ldm4(uA2l + halfA + off, a2l[f]);
        }
        uint32_t ph[2][4];
        #pragma unroll
        for (int c = 0; c < 2; c++) {
            uint32_t off = SW128((uint32_t)((n0 + c*16 + bRow)*128) + k32 + bK);
            ldm4(uWph + halfW + off, ph[c]);
        }
        #pragma unroll
        for (int m = 0; m < 2; m++)
            #pragma unroll
            for (int n = 0; n < 4; n++) {
                int ci = n >> 1, bi = (n & 1) * 2;
                mma16816(acc[m][n], a2h[m], ph[ci][bi], ph[ci][bi+1]);
                mma16816(acc[m][n], a2l[m], ph[ci][bi], ph[ci][bi+1]);
            }
    }

    // epilogue: out = gate * (acc + opb)
    #pragma unroll
    for (int m = 0; m < 2; m++) {
        int row0 = m0 + m*16 + (lane >> 2);
        #pragma unroll
        for (int n = 0; n < 4; n++) {
            int c0 = n0 + n*8 + (lane & 3)*2;
            float pb0 = __ldg(opb + c0), pb1 = __ldg(opb + c0 + 1);
            __half2 gv0 = *(const __half2*)(g_gate + (size_t)(r0 + row0)*DDIM + c0);
            __half2 gv1 = *(const __half2*)(g_gate + (size_t)(r0 + row0 + 8)*DDIM + c0);
            float2 g0 = __half22float2(gv0), g1 = __half22float2(gv1);
            float2 v0, v1;
            v0.x = g0.x * (acc[m][n][0] + pb0);
            v0.y = g0.y * (acc[m][n][1] + pb1);
            v1.x = g1.x * (acc[m][n][2] + pb0);
            v1.y = g1.y * (acc[m][n][3] + pb1);
            *(float2*)(out + (size_t)(r0 + row0)*DDIM + c0)     = v0;
            *(float2*)(out + (size_t)(r0 + row0 + 8)*DDIM + c0) = v1;
        }
    }
}

// ============================================================================
extern "C" void kernel_launch(void* const* d_in, const int* in_sizes, int n_in,
                              void* d_out, int out_size)
{
    const float* pair = (const float*)d_in[0];
    const float* mask = (const float*)d_in[1];
    const float* apw  = (const float*)d_in[2];
    const float* apb  = (const float*)d_in[3];
    const float* agw  = (const float*)d_in[4];
    const float* agb  = (const float*)d_in[5];
    const float* opw  = (const float*)d_in[6];
    const float* opb  = (const float*)d_in[7];
    const float* ogw  = (const float*)d_in[8];
    const float* ogb  = (const float*)d_in[9];
    float* out = (float*)d_out;

    const size_t smA = 82432;    // 80.5 KB -> 2 CTA/SM
    const size_t smB = 65536;    // 64 KB   -> 2 CTA/SM
    const size_t smC = 66048;    // ~64.5KB -> 2 CTA/SM
    cudaFuncSetAttribute(kA, cudaFuncAttributeMaxDynamicSharedMemorySize, (int)smA);
    cudaFuncSetAttribute(kB, cudaFuncAttributeMaxDynamicSharedMemorySize, (int)smB);
    cudaFuncSetAttribute(kC, cudaFuncAttributeMaxDynamicSharedMemorySize, (int)smC);

    kW<<<128, 256>>>(agw, apw, ogw, opw);
    kA<<<NN/128, 256, smA>>>(pair, mask, apb, agb, ogb);
    kB<<<dim3(4, 4, DDIM), 256, smB>>>();
    kC<<<NN/64, 256, smC>>>(opb, out);
}

// round 11
// speedup vs baseline: 4.8193x; 1.0458x over previous
#include <cuda_runtime.h>
#include <cuda_fp16.h>
#include <cstdint>
#include <cstddef>

#define NSEQ 512
#define DDIM 128
#define NN   (NSEQ*NSEQ)

// Scratch: a,b fp16 channel-major [d][i][k]; tri fp32 [d][i][j]; gate row-major [r][ch]
static __device__ __half g_af[(size_t)DDIM * NN];
static __device__ __half g_bf[(size_t)DDIM * NN];
static __device__ float  g_t[(size_t)DDIM * NN];
static __device__ __half g_gate[(size_t)NN * DDIM];

// Pre-converted weights (fp16), row-major [ch][k]
static __device__ __half g_wg[256*128];
static __device__ __half g_wp[256*128];
static __device__ __half g_og[128*128];
static __device__ __half g_oph[128*128];
static __device__ float  g_wbar[128];     // sum_d fp16(opw[c][d])

__device__ __forceinline__ float sigmoidf_(float x) { return 1.0f / (1.0f + __expf(-x)); }

__device__ __forceinline__ uint32_t smem_u32(const void* p) {
    uint32_t a;
    asm("{ .reg .u64 t; cvta.to.shared.u64 t, %1; cvt.u32.u64 %0, t; }" : "=r"(a) : "l"(p));
    return a;
}
#define SW128(o) ((o) ^ (((o) >> 3) & 0x70))

#define CP_ASYNC16(dst, src) \
    asm volatile("cp.async.cg.shared.global [%0], [%1], 16;" :: "r"(dst), "l"(src) : "memory")
#define CP_COMMIT() asm volatile("cp.async.commit_group;" ::: "memory")
#define CP_WAIT(n)  asm volatile("cp.async.wait_group %0;" :: "n"(n) : "memory")

__device__ __forceinline__ void ldm4(uint32_t addr, uint32_t r[4]) {
    asm volatile("ldmatrix.sync.aligned.m8n8.x4.shared.b16 {%0,%1,%2,%3}, [%4];"
        : "=r"(r[0]), "=r"(r[1]), "=r"(r[2]), "=r"(r[3]) : "r"(addr));
}
__device__ __forceinline__ void ldm4t(uint32_t addr, uint32_t r[4]) {
    asm volatile("ldmatrix.sync.aligned.m8n8.x4.trans.shared.b16 {%0,%1,%2,%3}, [%4];"
        : "=r"(r[0]), "=r"(r[1]), "=r"(r[2]), "=r"(r[3]) : "r"(addr));
}
__device__ __forceinline__ void mma16816(float c[4], const uint32_t a[4],
                                         uint32_t b0, uint32_t b1) {
    asm volatile(
        "mma.sync.aligned.m16n8k16.row.col.f32.f16.f16.f32 "
        "{%0,%1,%2,%3}, {%4,%5,%6,%7}, {%8,%9}, {%0,%1,%2,%3};"
        : "+f"(c[0]), "+f"(c[1]), "+f"(c[2]), "+f"(c[3])
        : "r"(a[0]), "r"(a[1]), "r"(a[2]), "r"(a[3]), "r"(b0), "r"(b1));
}

// ============================================================================
__global__ void __launch_bounds__(256) kW(
    const float* __restrict__ agw, const float* __restrict__ apw,
    const float* __restrict__ ogw, const float* __restrict__ opw)
{
    int i = blockIdx.x * 256 + threadIdx.x;
    if (i < 256*128) {
        g_wg[i] = __float2half_rn(agw[i]);
        g_wp[i] = __float2half_rn(apw[i]);
    }
    if (i < 128*128) {
        g_og[i]  = __float2half_rn(ogw[i]);
        g_oph[i] = __float2half_rn(opw[i]);
    }
}
// column sums of fp16(out_proj_w): w̄[c] = Σ_d fp16(opw[c][d])
__global__ void kWb(const float* __restrict__ opw) {
    int c = threadIdx.x;
    float s = 0.f;
    for (int d = 0; d < 128; d++) s += __half2float(__float2half_rn(opw[c*128 + d]));
    g_wbar[c] = s;
}

// ============================================================================
// Kernel A (fp16): LN(pair) -> ab gate/proj GEMM -> ab fp16 ch-major
//                  + out_gate GEMM -> sigmoid -> g_gate row-major fp16
// (unchanged from R10)
// ============================================================================
__global__ void __launch_bounds__(256, 2) kA(
    const float* __restrict__ pair, const float* __restrict__ mask,
    const float* __restrict__ apb, const float* __restrict__ agb,
    const float* __restrict__ ogb)
{
    extern __shared__ char smc[];
    const uint32_t sbase = smem_u32(smc);
    const uint32_t uA  = sbase;
    const uint32_t uWg = sbase + 32768;
    const uint32_t uWp = sbase + 49152;
    __half* stgF = (__half*)(smc + 65536);
    float*  sM   = (float*)(smc + 81920);

    const int t    = threadIdx.x;
    const int lane = t & 31;
    const int wid  = t >> 5;
    const int r0   = blockIdx.x * 128;

    if (t < 128) sM[t] = mask[r0 + t];

    for (int row = wid; row < 128; row += 8) {
        const float* src = pair + (size_t)(r0 + row) * DDIM;
        float x[4] = { src[lane], src[lane+32], src[lane+64], src[lane+96] };
        float s = x[0] + x[1] + x[2] + x[3];
        #pragma unroll
        for (int o = 16; o > 0; o >>= 1) s += __shfl_xor_sync(0xffffffffu, s, o);
        float mu = s * (1.0f/128.0f);
        float d0 = x[0]-mu, d1 = x[1]-mu, d2 = x[2]-mu, d3 = x[3]-mu;
        float v = d0*d0 + d1*d1 + d2*d2 + d3*d3;
        #pragma unroll
        for (int o = 16; o > 0; o >>= 1) v += __shfl_xor_sync(0xffffffffu, v, o);
        float rstd = rsqrtf(v * (1.0f/128.0f) + 1e-5f);
        float dd[4] = { d0*rstd, d1*rstd, d2*rstd, d3*rstd };
        #pragma unroll
        for (int j = 0; j < 4; j++) {
            uint32_t off = (uint32_t)(j >= 2) * 16384u
                         + SW128((uint32_t)(row*128 + (lane + 32*(j&1))*2));
            *(__half*)(smc + off) = __float2half_rn(dd[j]);
        }
    }

    const int aRow = lane & 15;
    const int aK   = (lane >> 4) * 16;
    const int bRow = (lane & 7) + ((lane >> 4) << 3);
    const int bK   = ((lane >> 3) & 1) * 16;
    const int m0   = (wid & 1) * 64;
    const int n0   = (wid >> 1) * 16;

    for (int ct = 0; ct < 4; ct++) {
        const int ch0 = ct * 64;
        __syncthreads();
        #pragma unroll
        for (int q = 0; q < 4; q++) {
            int seg = t + 256*q;
            int ch  = seg >> 4;
            int s8  = seg & 15;
            uint32_t dst = ((s8 >= 8) ? 8192u : 0u) + SW128((uint32_t)(ch*128 + (s8 & 7)*16));
            *(uint4*)(smc + 32768 + dst) = *(const uint4*)(g_wg + (size_t)(ch0 + ch)*128 + s8*8);
            *(uint4*)(smc + 49152 + dst) = *(const uint4*)(g_wp + (size_t)(ch0 + ch)*128 + s8*8);
        }
        __syncthreads();

        float accg[4][2][4], accp[4][2][4];
        #pragma unroll
        for (int m = 0; m < 4; m++)
            #pragma unroll
            for (int n = 0; n < 2; n++)
                #pragma unroll
                for (int e = 0; e < 4; e++) { accg[m][n][e] = 0.f; accp[m][n][e] = 0.f; }

        #pragma unroll
        for (int kk = 0; kk < 8; kk++) {
            const uint32_t halfA = (uint32_t)(kk >> 2) * 16384u;
            const uint32_t halfW = (uint32_t)(kk >> 2) * 8192u;
            const uint32_t k32   = (uint32_t)(kk & 3) * 32u;

            uint32_t ah[4][4];
            #pragma unroll
            for (int f = 0; f < 4; f++) {
                uint32_t off = SW128((uint32_t)((m0 + f*16 + aRow)*128) + k32 + aK);
                ldm4(uA + halfA + off, ah[f]);
            }
            uint32_t gh[4], ph[4];
            {
                uint32_t off = SW128((uint32_t)((n0 + bRow)*128) + k32 + bK);
                ldm4(uWg + halfW + off, gh);
                ldm4(uWp + halfW + off, ph);
            }
            #pragma unroll
            for (int m = 0; m < 4; m++)
                #pragma unroll
                for (int n = 0; n < 2; n++) {
                    mma16816(accg[m][n], ah[m], gh[n*2], gh[n*2+1]);
                    mma16816(accp[m][n], ah[m], ph[n*2], ph[n*2+1]);
                }
        }

        #pragma unroll
        for (int m = 0; m < 4; m++) {
            int row0 = m0 + m*16 + (lane >> 2);
            #pragma unroll
            for (int n = 0; n < 2; n++) {
                int c0 = n0 + n*8 + (lane & 3)*2;
                float gb0 = __ldg(agb + ch0 + c0), gb1 = __ldg(agb + ch0 + c0 + 1);
                float pb0 = __ldg(apb + ch0 + c0), pb1 = __ldg(apb + ch0 + c0 + 1);
                float mv0 = sM[row0], mv1 = sM[row0 + 8];
                float vals[4];
                vals[0] = mv0 * sigmoidf_(accg[m][n][0] + gb0) * (accp[m][n][0] + pb0);
                vals[1] = mv0 * sigmoidf_(accg[m][n][1] + gb1) * (accp[m][n][1] + pb1);
                vals[2] = mv1 * sigmoidf_(accg[m][n][2] + gb0) * (accp[m][n][2] + pb0);
                vals[3] = mv1 * sigmoidf_(accg[m][n][3] + gb1) * (accp[m][n][3] + pb1);
                #pragma unroll
                for (int e = 0; e < 4; e++) {
                    int cc = c0 + (e & 1);
                    int rr = row0 + (e >> 1) * 8;
                    stgF[cc*128 + rr] = __float2half_rn(vals[e]);
                }
            }
        }
        __syncthreads();

        __half* dst = (ch0 < 128) ? (g_af + (size_t)ch0 * NN)
                                  : (g_bf + (size_t)(ch0 - 128) * NN);
        #pragma unroll
        for (int q = 0; q < 4; q++) {
            int seg = t + 256*q;
            int ch  = seg >> 4;
            int r8  = (seg & 15) * 8;
            *(uint4*)(dst + (size_t)ch * NN + r0 + r8) = *(const uint4*)(stgF + ch*128 + r8);
        }
    }

    for (int gt = 0; gt < 2; gt++) {
        const int ch0 = gt * 64;
        __syncthreads();
        #pragma unroll
        for (int q = 0; q < 4; q++) {
            int seg = t + 256*q;
            int ch  = seg >> 4;
            int s8  = seg & 15;
            uint32_t dst = ((s8 >= 8) ? 8192u : 0u) + SW128((uint32_t)(ch*128 + (s8 & 7)*16));
            *(uint4*)(smc + 32768 + dst) = *(const uint4*)(g_og + (size_t)(ch0 + ch)*128 + s8*8);
        }
        __syncthreads();

        float accg[4][2][4];
        #pragma unroll
        for (int m = 0; m < 4; m++)
            #pragma unroll
            for (int n = 0; n < 2; n++)
                #pragma unroll
                for (int e = 0; e < 4; e++) accg[m][n][e] = 0.f;

        #pragma unroll
        for (int kk = 0; kk < 8; kk++) {
            const uint32_t halfA = (uint32_t)(kk >> 2) * 16384u;
            const uint32_t halfW = (uint32_t)(kk >> 2) * 8192u;
            const uint32_t k32   = (uint32_t)(kk & 3) * 32u;

            uint32_t ah[4][4];
            #pragma unroll
            for (int f = 0; f < 4; f++) {
                uint32_t off = SW128((uint32_t)((m0 + f*16 + aRow)*128) + k32 + aK);
                ldm4(uA + halfA + off, ah[f]);
            }
            uint32_t gh[4];
            {
                uint32_t off = SW128((uint32_t)((n0 + bRow)*128) + k32 + bK);
                ldm4(uWg + halfW + off, gh);
            }
            #pragma unroll
            for (int m = 0; m < 4; m++)
                #pragma unroll
                for (int n = 0; n < 2; n++)
                    mma16816(accg[m][n], ah[m], gh[n*2], gh[n*2+1]);
        }

        #pragma unroll
        for (int m = 0; m < 4; m++) {
            int row0 = m0 + m*16 + (lane >> 2);
            #pragma unroll
            for (int n = 0; n < 2; n++) {
                int c0 = n0 + n*8 + (lane & 3)*2;
                float gb0 = __ldg(ogb + ch0 + c0), gb1 = __ldg(ogb + ch0 + c0 + 1);
                stgF[row0*64 + c0]         = __float2half_rn(sigmoidf_(accg[m][n][0] + gb0));
                stgF[row0*64 + c0 + 1]     = __float2half_rn(sigmoidf_(accg[m][n][1] + gb1));
                stgF[(row0+8)*64 + c0]     = __float2half_rn(sigmoidf_(accg[m][n][2] + gb0));
                stgF[(row0+8)*64 + c0 + 1] = __float2half_rn(sigmoidf_(accg[m][n][3] + gb1));
            }
        }
        __syncthreads();
        #pragma unroll
        for (int q = 0; q < 4; q++) {
            int seg = t + 256*q;
            int row = seg >> 3;
            int c8  = (seg & 7) * 8;
            *(uint4*)(g_gate + (size_t)(r0 + row)*DDIM + ch0 + c8)
                = *(const uint4*)(stgF + row*64 + c8);
        }
    }
}

// ============================================================================
// Kernel B (fp16 1-term) — unchanged
// ============================================================================
__global__ void __launch_bounds__(256, 2) kB()
{
    extern __shared__ char smc[];
    const uint32_t sbase = smem_u32(smc);

    const int t    = threadIdx.x;
    const int lane = t & 31;
    const int wid  = t >> 5;
    const int d    = blockIdx.z;
    const int i0   = blockIdx.x * 128;
    const int j0   = blockIdx.y * 128;

    const int m0 = (wid & 1) * 64;
    const int n0 = (wid >> 1) * 32;

    const __half* srcA = g_af + (size_t)d*NN + (size_t)i0*NSEQ;
    const __half* srcB = g_bf + (size_t)d*NN + (size_t)j0*NSEQ;

    auto issue = [&](int stage, int kc) {
        uint32_t sb = sbase + stage * 32768;
        #pragma unroll
        for (int q = 0; q < 4; q++) {
            int seg = t + 256*q;
            int row = seg >> 3;
            int s   = seg & 7;
            uint32_t off = SW128((uint32_t)(row*128 + s*16));
            CP_ASYNC16(sb + off,         srcA + (size_t)row*NSEQ + kc + s*8);
            CP_ASYNC16(sb + 16384 + off, srcB + (size_t)row*NSEQ + kc + s*8);
        }
        CP_COMMIT();
    };

    float acc[4][4][4];
    #pragma unroll
    for (int m = 0; m < 4; m++)
        #pragma unroll
        for (int n = 0; n < 4; n++)
            #pragma unroll
            for (int e = 0; e < 4; e++) acc[m][n][e] = 0.0f;

    const int aRow = lane & 15;
    const int aK   = (lane >> 4) * 16;
    const int bRow = (lane & 7) + ((lane >> 4) << 3);
    const int bK   = ((lane >> 3) & 1) * 16;

    issue(0, 0);

    for (int ch = 0; ch < 8; ch++) {
        const int stage = ch & 1;
        if (ch < 7) { issue(stage ^ 1, (ch + 1) * 64); CP_WAIT(1); }
        else        { CP_WAIT(0); }
        __syncthreads();

        const uint32_t sA = sbase + stage * 32768;
        const uint32_t sB = sA + 16384;

        #pragma unroll
        for (int kk = 0; kk < 4; kk++) {
            const uint32_t kOffA = (uint32_t)(kk*32) + aK;
            const uint32_t kOffB = (uint32_t)(kk*32) + bK;

            uint32_t bh[2][4];
            #pragma unroll
            for (int c = 0; c < 2; c++) {
                uint32_t off = (uint32_t)((n0 + c*16 + bRow) * 128) + kOffB;
                ldm4(sB + SW128(off), bh[c]);
            }
            uint32_t ah[4][4];
            #pragma unroll
            for (int f = 0; f < 4; f++) {
                uint32_t off = (uint32_t)((m0 + f*16 + aRow) * 128) + kOffA;
                ldm4(sA + SW128(off), ah[f]);
            }
            #pragma unroll
            for (int m = 0; m < 4; m++)
                #pragma unroll
                for (int n = 0; n < 4; n++)
                    mma16816(acc[m][n], ah[m], bh[n>>1][(n&1)*2], bh[n>>1][(n&1)*2+1]);
        }
        __syncthreads();
    }

    float* base = g_t + (size_t)d*NN;
    #pragma unroll
    for (int m = 0; m < 4; m++) {
        int r1 = i0 + m0 + m*16 + (lane >> 2);
        #pragma unroll
        for (int n = 0; n < 4; n++) {
            int c = j0 + n0 + n*8 + (lane & 3)*2;
            float2 lo = make_float2(acc[m][n][0], acc[m][n][1]);
            float2 hi = make_float2(acc[m][n][2], acc[m][n][3]);
            *(float2*)(base + (size_t)r1*NSEQ + c)       = lo;
            *(float2*)(base + (size_t)(r1+8)*NSEQ + c)   = hi;
        }
    }
}

// ============================================================================
// Kernel C (LN folded into epilogue): 64-row blocks, 256 thr, ~74KB -> 2 CTA/SM.
// A tiles stored d-major T[d][row] (fp16 hi/lo, 16KB each), read via ldmatrix.trans.
// smem: Th 16K @0 | Tl 16K @16384 | Wph 32K @32768 | pS/pQ @65536 | mu/rstd @74240
// out = gate * ( rstd*(tri@W^T - mu*wbar) + opb )
// ============================================================================
__global__ void __launch_bounds__(256, 2) kC(
    const float* __restrict__ opb,
    float* __restrict__ out)
{
    extern __shared__ char smc[];
    const uint32_t sbase = smem_u32(smc);
    const uint32_t uTh  = sbase;
    const uint32_t uTl  = sbase + 16384;
    const uint32_t uWph = sbase + 32768;
    float* pS    = (float*)(smc + 65536);            // [64][17]
    float* pQ    = (float*)(smc + 65536 + 4352);     // [64][17]
    float* sMu   = (float*)(smc + 65536 + 8704);     // [64]
    float* sRstd = (float*)(smc + 65536 + 8960);     // [64]

    const int t    = threadIdx.x;
    const int lane = t & 31;
    const int wid  = t >> 5;
    const int r0   = blockIdx.x * 64;

    // prefetch full Wph (128ch x 128k) via cp.async — overlaps everything below
    #pragma unroll
    for (int q = 0; q < 8; q++) {
        int seg = t + 256*q;
        int ch  = seg >> 4;
        int s8  = seg & 15;
        uint32_t dst = ((s8 >= 8) ? 16384u : 0u) + SW128((uint32_t)(ch*128 + (s8 & 7)*16));
        CP_ASYNC16(uWph + dst, g_oph + (size_t)ch*128 + s8*8);
    }
    CP_COMMIT();

    // load raw tri, convert to fp16 hi/lo d-major tiles, accumulate row stats
    const int r4 = (t & 15) * 4;       // 4 rows handled by this thread
    const int gg = t >> 4;             // stat group 0..15
    float s0=0.f, s1=0.f, s2=0.f, s3=0.f;
    float q0=0.f, q1=0.f, q2=0.f, q3=0.f;
    #pragma unroll
    for (int q8 = 0; q8 < 8; q8++) {
        int dd = gg + 16*q8;
        float4 f = *(const float4*)(g_t + (size_t)dd*NN + r0 + r4);
        s0 += f.x; q0 += f.x*f.x;
        s1 += f.y; q1 += f.y*f.y;
        s2 += f.z; q2 += f.z*f.z;
        s3 += f.w; q3 += f.w*f.w;
        __half h0 = __float2half_rn(f.x), h1 = __float2half_rn(f.y);
        __half h2 = __float2half_rn(f.z), h3 = __float2half_rn(f.w);
        __half l0 = __float2half_rn(f.x - __half2float(h0));
        __half l1 = __float2half_rn(f.y - __half2float(h1));
        __half l2 = __float2half_rn(f.z - __half2float(h2));
        __half l3 = __float2half_rn(f.w - __half2float(h3));
        uint32_t off = SW128((uint32_t)(dd*128 + r4*2));   // T[d][row], 8B aligned
        __half2 hA = __halves2half2(h0, h1), hB = __halves2half2(h2, h3);
        __half2 lA = __halves2half2(l0, l1), lB = __halves2half2(l2, l3);
        *(__half2*)(smc + off)             = hA;
        *(__half2*)(smc + off + 4)         = hB;
        *(__half2*)(smc + 16384 + off)     = lA;
        *(__half2*)(smc + 16384 + off + 4) = lB;
    }
    pS[(r4+0)*17 + gg] = s0;  pQ[(r4+0)*17 + gg] = q0;
    pS[(r4+1)*17 + gg] = s1;  pQ[(r4+1)*17 + gg] = q1;
    pS[(r4+2)*17 + gg] = s2;  pQ[(r4+2)*17 + gg] = q2;
    pS[(r4+3)*17 + gg] = s3;  pQ[(r4+3)*17 + gg] = q3;
    __syncthreads();

    if (t < 64) {
        float s = 0.f, q = 0.f;
        #pragma unroll
        for (int g = 0; g < 16; g++) { s += pS[t*17 + g]; q += pQ[t*17 + g]; }
        float mu  = s * (1.0f/128.0f);
        float var = q * (1.0f/128.0f) - mu*mu;
        sMu[t]   = mu;
        sRstd[t] = rsqrtf(var + 1e-5f);
    }
    CP_WAIT(0);
    __syncthreads();

    const int bRow = (lane & 7) + ((lane >> 4) << 3);
    const int bK   = ((lane >> 3) & 1) * 16;
    const int m0   = (wid & 1) * 32;
    const int n0   = (wid >> 1) * 32;
    // trans A-frag lane addressing: d-row and r-col components
    const int tD = (lane & 7) + ((lane & 16) >> 1);   // 0..15 within k16
    const int tR = ((lane >> 3) & 1) * 8;             // 0 or 8

    float acc[2][4][4];
    #pragma unroll
    for (int m = 0; m < 2; m++)
        #pragma unroll
        for (int n = 0; n < 4; n++)
            #pragma unroll
            for (int e = 0; e < 4; e++) acc[m][n][e] = 0.f;

    #pragma unroll
    for (int kk = 0; kk < 8; kk++) {
        const int d0 = kk * 16;
        const uint32_t halfW = (uint32_t)(kk >> 2) * 16384u;
        const uint32_t k32   = (uint32_t)(kk & 3) * 32u;

        uint32_t a2h[2][4], a2l[2][4];
        #pragma unroll
        for (int f = 0; f < 2; f++) {
            uint32_t off = SW128((uint32_t)((d0 + tD)*128 + (m0 + f*16 + tR)*2));
            ldm4t(uTh + off, a2h[f]);
            ldm4t(uTl + off, a2l[f]);
        }
        uint32_t ph[2][4];
        #pragma unroll
        for (int c = 0; c < 2; c++) {
            uint32_t off = SW128((uint32_t)((n0 + c*16 + bRow)*128) + k32 + bK);
            ldm4(uWph + halfW + off, ph[c]);
        }
        #pragma unroll
        for (int m = 0; m < 2; m++)
            #pragma unroll
            for (int n = 0; n < 4; n++) {
                int ci = n >> 1, bi = (n & 1) * 2;
                mma16816(acc[m][n], a2h[m], ph[ci][bi], ph[ci][bi+1]);
                mma16816(acc[m][n], a2l[m], ph[ci][bi], ph[ci][bi+1]);
            }
    }

    // epilogue: out = gate * ( rstd*(acc - mu*wbar) + opb )
    #pragma unroll
    for (int m = 0; m < 2; m++) {
        int row0 = m0 + m*16 + (lane >> 2);
        float mu0 = sMu[row0],   rs0 = sRstd[row0];
        float mu1 = sMu[row0+8], rs1 = sRstd[row0+8];
        #pragma unroll
        for (int n = 0; n < 4; n++) {
            int c0 = n0 + n*8 + (lane & 3)*2;
            float pb0 = __ldg(opb + c0),    pb1 = __ldg(opb + c0 + 1);
            float wb0 = __ldg(g_wbar + c0), wb1 = __ldg(g_wbar + c0 + 1);
            __half2 gv0 = *(const __half2*)(g_gate + (size_t)(r0 + row0)*DDIM + c0);
            __half2 gv1 = *(const __half2*)(g_gate + (size_t)(r0 + row0 + 8)*DDIM + c0);
            float2 g0 = __half22float2(gv0), g1 = __half22float2(gv1);
            float2 v0, v1;
            v0.x = g0.x * (rs0 * (acc[m][n][0] - mu0*wb0) + pb0);
            v0.y = g0.y * (rs0 * (acc[m][n][1] - mu0*wb1) + pb1);
            v1.x = g1.x * (rs1 * (acc[m][n][2] - mu1*wb0) + pb0);
            v1.y = g1.y * (rs1 * (acc[m][n][3] - mu1*wb1) + pb1);
            *(float2*)(out + (size_t)(r0 + row0)*DDIM + c0)     = v0;
            *(float2*)(out + (size_t)(r0 + row0 + 8)*DDIM + c0) = v1;
        }
    }
}

// ============================================================================
extern "C" void kernel_launch(void* const* d_in, const int* in_sizes, int n_in,
                              void* d_out, int out_size)
{
    const float* pair = (const float*)d_in[0];
    const float* mask = (const float*)d_in[1];
    const float* apw  = (const float*)d_in[2];
    const float* apb  = (const float*)d_in[3];
    const float* agw  = (const float*)d_in[4];
    const float* agb  = (const float*)d_in[5];
    const float* opw  = (const float*)d_in[6];
    const float* opb  = (const float*)d_in[7];
    const float* ogw  = (const float*)d_in[8];
    const float* ogb  = (const float*)d_in[9];
    float* out = (float*)d_out;

    const size_t smA = 82432;    // 80.5 KB -> 2 CTA/SM
    const size_t smB = 65536;    // 64 KB   -> 2 CTA/SM
    const size_t smC = 75264;    // ~73.5KB -> 2 CTA/SM
    cudaFuncSetAttribute(kA, cudaFuncAttributeMaxDynamicSharedMemorySize, (int)smA);
    cudaFuncSetAttribute(kB, cudaFuncAttributeMaxDynamicSharedMemorySize, (int)smB);
    cudaFuncSetAttribute(kC, cudaFuncAttributeMaxDynamicSharedMemorySize, (int)smC);

    kW<<<128, 256>>>(agw, apw, ogw, opw);
    kWb<<<1, 128>>>(opw);
    kA<<<NN/128, 256, smA>>>(pair, mask, apb, agb, ogb);
    kB<<<dim3(4, 4, DDIM), 256, smB>>>();
    kC<<<NN/64, 256, smC>>>(opb, out);
}

// round 12
// speedup vs baseline: 5.0944x; 1.0571x over previous
#include <cuda_runtime.h>
#include <cuda_fp16.h>
#include <cstdint>
#include <cstddef>

#define NSEQ 512
#define DDIM 128
#define NN   (NSEQ*NSEQ)

// Scratch: a,b fp16 channel-major [d][i][k]; tri fp32 [d][i][j]; gate row-major [r][ch]
static __device__ __half g_af[(size_t)DDIM * NN];
static __device__ __half g_bf[(size_t)DDIM * NN];
static __device__ float  g_t[(size_t)DDIM * NN];
static __device__ __half g_gate[(size_t)NN * DDIM];

// Pre-converted weights (fp16), row-major [ch][k]
static __device__ __half g_wg[256*128];
static __device__ __half g_wp[256*128];
static __device__ __half g_og[128*128];
static __device__ __half g_oph[128*128];
static __device__ float  g_wbar[128];

__device__ __forceinline__ float sigmoidf_(float x) { return 1.0f / (1.0f + __expf(-x)); }

__device__ __forceinline__ uint32_t smem_u32(const void* p) {
    uint32_t a;
    asm("{ .reg .u64 t; cvta.to.shared.u64 t, %1; cvt.u32.u64 %0, t; }" : "=r"(a) : "l"(p));
    return a;
}
#define SW128(o) ((o) ^ (((o) >> 3) & 0x70))

#define CP_ASYNC16(dst, src) \
    asm volatile("cp.async.cg.shared.global [%0], [%1], 16;" :: "r"(dst), "l"(src) : "memory")
#define CP_COMMIT() asm volatile("cp.async.commit_group;" ::: "memory")
#define CP_WAIT(n)  asm volatile("cp.async.wait_group %0;" :: "n"(n) : "memory")

__device__ __forceinline__ void ldm4(uint32_t addr, uint32_t r[4]) {
    asm volatile("ldmatrix.sync.aligned.m8n8.x4.shared.b16 {%0,%1,%2,%3}, [%4];"
        : "=r"(r[0]), "=r"(r[1]), "=r"(r[2]), "=r"(r[3]) : "r"(addr));
}
__device__ __forceinline__ void ldm4t(uint32_t addr, uint32_t r[4]) {
    asm volatile("ldmatrix.sync.aligned.m8n8.x4.trans.shared.b16 {%0,%1,%2,%3}, [%4];"
        : "=r"(r[0]), "=r"(r[1]), "=r"(r[2]), "=r"(r[3]) : "r"(addr));
}
__device__ __forceinline__ void mma16816(float c[4], const uint32_t a[4],
                                         uint32_t b0, uint32_t b1) {
    asm volatile(
        "mma.sync.aligned.m16n8k16.row.col.f32.f16.f16.f32 "
        "{%0,%1,%2,%3}, {%4,%5,%6,%7}, {%8,%9}, {%0,%1,%2,%3};"
        : "+f"(c[0]), "+f"(c[1]), "+f"(c[2]), "+f"(c[3])
        : "r"(a[0]), "r"(a[1]), "r"(a[2]), "r"(a[3]), "r"(b0), "r"(b1));
}

// ============================================================================
__global__ void __launch_bounds__(256) kW(
    const float* __restrict__ agw, const float* __restrict__ apw,
    const float* __restrict__ ogw, const float* __restrict__ opw)
{
    int i = blockIdx.x * 256 + threadIdx.x;
    if (i < 256*128) {
        g_wg[i] = __float2half_rn(agw[i]);
        g_wp[i] = __float2half_rn(apw[i]);
    }
    if (i < 128*128) {
        g_og[i]  = __float2half_rn(ogw[i]);
        g_oph[i] = __float2half_rn(opw[i]);
    }
}
__global__ void kWb(const float* __restrict__ opw) {
    int c = threadIdx.x;
    float s = 0.f;
    for (int d = 0; d < 128; d++) s += __half2float(__float2half_rn(opw[c*128 + d]));
    g_wbar[c] = s;
}

// ============================================================================
// Kernel A (fp16, W pipelined, direct epilogue stores)
// smem: A 32K @0 | W stage0 32K @32768 | W stage1 32K @65536 | mask @98304
// 6 chunks: 0-3 = ab (Wg+Wp), 4-5 = out_gate (og only).
// ============================================================================
__global__ void __launch_bounds__(256, 2) kA(
    const float* __restrict__ pair, const float* __restrict__ mask,
    const float* __restrict__ apb, const float* __restrict__ agb,
    const float* __restrict__ ogb)
{
    extern __shared__ char smc[];
    const uint32_t sbase = smem_u32(smc);
    const uint32_t uA = sbase;
    const uint32_t uW = sbase + 32768;
    float* sM = (float*)(smc + 98304);

    const int t    = threadIdx.x;
    const int lane = t & 31;
    const int wid  = t >> 5;
    const int r0   = blockIdx.x * 128;

    // prefetch chunk 0 weights
    auto prefetchW = [&](int stage, int c) {
        uint32_t sb = uW + stage * 32768;
        const __half* w0;
        const __half* w1 = nullptr;
        if (c < 4) { w0 = g_wg + (size_t)c*64*128; w1 = g_wp + (size_t)c*64*128; }
        else       { w0 = g_og + (size_t)(c - 4)*64*128; }
        #pragma unroll
        for (int q = 0; q < 4; q++) {
            int seg = t + 256*q;          // 0..1023
            int ch  = seg >> 4;
            int s8  = seg & 15;
            uint32_t dst = ((s8 >= 8) ? 8192u : 0u) + SW128((uint32_t)(ch*128 + (s8 & 7)*16));
            CP_ASYNC16(sb + dst, w0 + (size_t)ch*128 + s8*8);
            if (w1) CP_ASYNC16(sb + 16384 + dst, w1 + (size_t)ch*128 + s8*8);
        }
        CP_COMMIT();
    };
    prefetchW(0, 0);

    if (t < 128) sM[t] = mask[r0 + t];

    // LN(pair) -> fp16 A tiles
    for (int row = wid; row < 128; row += 8) {
        const float* src = pair + (size_t)(r0 + row) * DDIM;
        float x[4] = { src[lane], src[lane+32], src[lane+64], src[lane+96] };
        float s = x[0] + x[1] + x[2] + x[3];
        #pragma unroll
        for (int o = 16; o > 0; o >>= 1) s += __shfl_xor_sync(0xffffffffu, s, o);
        float mu = s * (1.0f/128.0f);
        float d0 = x[0]-mu, d1 = x[1]-mu, d2 = x[2]-mu, d3 = x[3]-mu;
        float v = d0*d0 + d1*d1 + d2*d2 + d3*d3;
        #pragma unroll
        for (int o = 16; o > 0; o >>= 1) v += __shfl_xor_sync(0xffffffffu, v, o);
        float rstd = rsqrtf(v * (1.0f/128.0f) + 1e-5f);
        float dd[4] = { d0*rstd, d1*rstd, d2*rstd, d3*rstd };
        #pragma unroll
        for (int j = 0; j < 4; j++) {
            uint32_t off = (uint32_t)(j >= 2) * 16384u
                         + SW128((uint32_t)(row*128 + (lane + 32*(j&1))*2));
            *(__half*)(smc + off) = __float2half_rn(dd[j]);
        }
    }

    const int aRow = lane & 15;
    const int aK   = (lane >> 4) * 16;
    const int bRow = (lane & 7) + ((lane >> 4) << 3);
    const int bK   = ((lane >> 3) & 1) * 16;
    const int m0   = (wid & 1) * 64;
    const int n0   = (wid >> 1) * 16;

    for (int c = 0; c < 6; c++) {
        const int stage = c & 1;
        if (c < 5) { prefetchW(stage ^ 1, c + 1); CP_WAIT(1); }
        else       { CP_WAIT(0); }
        __syncthreads();   // W(stage) visible; also guards stage reuse from prev iter

        const uint32_t sW0 = uW + stage * 32768;          // Wg or og
        const uint32_t sW1 = sW0 + 16384;                 // Wp (ab chunks)
        const bool isAB = (c < 4);
        const int ch0   = isAB ? c * 64 : (c - 4) * 64;

        if (isAB) {
            float accg[4][2][4], accp[4][2][4];
            #pragma unroll
            for (int m = 0; m < 4; m++)
                #pragma unroll
                for (int n = 0; n < 2; n++)
                    #pragma unroll
                    for (int e = 0; e < 4; e++) { accg[m][n][e] = 0.f; accp[m][n][e] = 0.f; }

            #pragma unroll
            for (int kk = 0; kk < 8; kk++) {
                const uint32_t halfA = (uint32_t)(kk >> 2) * 16384u;
                const uint32_t halfW = (uint32_t)(kk >> 2) * 8192u;
                const uint32_t k32   = (uint32_t)(kk & 3) * 32u;

                uint32_t ah[4][4];
                #pragma unroll
                for (int f = 0; f < 4; f++) {
                    uint32_t off = SW128((uint32_t)((m0 + f*16 + aRow)*128) + k32 + aK);
                    ldm4(uA + halfA + off, ah[f]);
                }
                uint32_t gh[4], ph[4];
                {
                    uint32_t off = SW128((uint32_t)((n0 + bRow)*128) + k32 + bK);
                    ldm4(sW0 + halfW + off, gh);
                    ldm4(sW1 + halfW + off, ph);
                }
                #pragma unroll
                for (int m = 0; m < 4; m++)
                    #pragma unroll
                    for (int n = 0; n < 2; n++) {
                        mma16816(accg[m][n], ah[m], gh[n*2], gh[n*2+1]);
                        mma16816(accp[m][n], ah[m], ph[n*2], ph[n*2+1]);
                    }
            }

            __half* dst = (ch0 < 128) ? (g_af + (size_t)ch0 * NN)
                                      : (g_bf + (size_t)(ch0 - 128) * NN);
            #pragma unroll
            for (int m = 0; m < 4; m++) {
                int row0 = m0 + m*16 + (lane >> 2);
                #pragma unroll
                for (int n = 0; n < 2; n++) {
                    int c0 = n0 + n*8 + (lane & 3)*2;
                    float gb0 = __ldg(agb + ch0 + c0), gb1 = __ldg(agb + ch0 + c0 + 1);
                    float pb0 = __ldg(apb + ch0 + c0), pb1 = __ldg(apb + ch0 + c0 + 1);
                    float mv0 = sM[row0], mv1 = sM[row0 + 8];
                    float v00 = mv0 * sigmoidf_(accg[m][n][0] + gb0) * (accp[m][n][0] + pb0);
                    float v01 = mv0 * sigmoidf_(accg[m][n][1] + gb1) * (accp[m][n][1] + pb1);
                    float v10 = mv1 * sigmoidf_(accg[m][n][2] + gb0) * (accp[m][n][2] + pb0);
                    float v11 = mv1 * sigmoidf_(accg[m][n][3] + gb1) * (accp[m][n][3] + pb1);
                    __half* p0 = dst + (size_t)c0 * NN + r0 + row0;
                    __half* p1 = dst + (size_t)(c0 + 1) * NN + r0 + row0;
                    p0[0] = __float2half_rn(v00);
                    p1[0] = __float2half_rn(v01);
                    p0[8] = __float2half_rn(v10);
                    p1[8] = __float2half_rn(v11);
                }
            }
        } else {
            float accg[4][2][4];
            #pragma unroll
            for (int m = 0; m < 4; m++)
                #pragma unroll
                for (int n = 0; n < 2; n++)
                    #pragma unroll
                    for (int e = 0; e < 4; e++) accg[m][n][e] = 0.f;

            #pragma unroll
            for (int kk = 0; kk < 8; kk++) {
                const uint32_t halfA = (uint32_t)(kk >> 2) * 16384u;
                const uint32_t halfW = (uint32_t)(kk >> 2) * 8192u;
                const uint32_t k32   = (uint32_t)(kk & 3) * 32u;

                uint32_t ah[4][4];
                #pragma unroll
                for (int f = 0; f < 4; f++) {
                    uint32_t off = SW128((uint32_t)((m0 + f*16 + aRow)*128) + k32 + aK);
                    ldm4(uA + halfA + off, ah[f]);
                }
                uint32_t gh[4];
                {
                    uint32_t off = SW128((uint32_t)((n0 + bRow)*128) + k32 + bK);
                    ldm4(sW0 + halfW + off, gh);
                }
                #pragma unroll
                for (int m = 0; m < 4; m++)
                    #pragma unroll
                    for (int n = 0; n < 2; n++)
                        mma16816(accg[m][n], ah[m], gh[n*2], gh[n*2+1]);
            }

            #pragma unroll
            for (int m = 0; m < 4; m++) {
                int row0 = m0 + m*16 + (lane >> 2);
                #pragma unroll
                for (int n = 0; n < 2; n++) {
                    int c0 = n0 + n*8 + (lane & 3)*2;
                    float gb0 = __ldg(ogb + ch0 + c0), gb1 = __ldg(ogb + ch0 + c0 + 1);
                    __half2 h0 = __halves2half2(
                        __float2half_rn(sigmoidf_(accg[m][n][0] + gb0)),
                        __float2half_rn(sigmoidf_(accg[m][n][1] + gb1)));
                    __half2 h1 = __halves2half2(
                        __float2half_rn(sigmoidf_(accg[m][n][2] + gb0)),
                        __float2half_rn(sigmoidf_(accg[m][n][3] + gb1)));
                    *(__half2*)(g_gate + (size_t)(r0 + row0)*DDIM + ch0 + c0)     = h0;
                    *(__half2*)(g_gate + (size_t)(r0 + row0 + 8)*DDIM + ch0 + c0) = h1;
                }
            }
        }
        __syncthreads();   // all warps done with W(stage) before it is re-prefetched
    }
}

// ============================================================================
// Kernel B (fp16 1-term) — unchanged
// ============================================================================
__global__ void __launch_bounds__(256, 2) kB()
{
    extern __shared__ char smc[];
    const uint32_t sbase = smem_u32(smc);

    const int t    = threadIdx.x;
    const int lane = t & 31;
    const int wid  = t >> 5;
    const int d    = blockIdx.z;
    const int i0   = blockIdx.x * 128;
    const int j0   = blockIdx.y * 128;

    const int m0 = (wid & 1) * 64;
    const int n0 = (wid >> 1) * 32;

    const __half* srcA = g_af + (size_t)d*NN + (size_t)i0*NSEQ;
    const __half* srcB = g_bf + (size_t)d*NN + (size_t)j0*NSEQ;

    auto issue = [&](int stage, int kc) {
        uint32_t sb = sbase + stage * 32768;
        #pragma unroll
        for (int q = 0; q < 4; q++) {
            int seg = t + 256*q;
            int row = seg >> 3;
            int s   = seg & 7;
            uint32_t off = SW128((uint32_t)(row*128 + s*16));
            CP_ASYNC16(sb + off,         srcA + (size_t)row*NSEQ + kc + s*8);
            CP_ASYNC16(sb + 16384 + off, srcB + (size_t)row*NSEQ + kc + s*8);
        }
        CP_COMMIT();
    };

    float acc[4][4][4];
    #pragma unroll
    for (int m = 0; m < 4; m++)
        #pragma unroll
        for (int n = 0; n < 4; n++)
            #pragma unroll
            for (int e = 0; e < 4; e++) acc[m][n][e] = 0.0f;

    const int aRow = lane & 15;
    const int aK   = (lane >> 4) * 16;
    const int bRow = (lane & 7) + ((lane >> 4) << 3);
    const int bK   = ((lane >> 3) & 1) * 16;

    issue(0, 0);

    for (int ch = 0; ch < 8; ch++) {
        const int stage = ch & 1;
        if (ch < 7) { issue(stage ^ 1, (ch + 1) * 64); CP_WAIT(1); }
        else        { CP_WAIT(0); }
        __syncthreads();

        const uint32_t sA = sbase + stage * 32768;
        const uint32_t sB = sA + 16384;

        #pragma unroll
        for (int kk = 0; kk < 4; kk++) {
            const uint32_t kOffA = (uint32_t)(kk*32) + aK;
            const uint32_t kOffB = (uint32_t)(kk*32) + bK;

            uint32_t bh[2][4];
            #pragma unroll
            for (int c = 0; c < 2; c++) {
                uint32_t off = (uint32_t)((n0 + c*16 + bRow) * 128) + kOffB;
                ldm4(sB + SW128(off), bh[c]);
            }
            uint32_t ah[4][4];
            #pragma unroll
            for (int f = 0; f < 4; f++) {
                uint32_t off = (uint32_t)((m0 + f*16 + aRow) * 128) + kOffA;
                ldm4(sA + SW128(off), ah[f]);
            }
            #pragma unroll
            for (int m = 0; m < 4; m++)
                #pragma unroll
                for (int n = 0; n < 4; n++)
                    mma16816(acc[m][n], ah[m], bh[n>>1][(n&1)*2], bh[n>>1][(n&1)*2+1]);
        }
        __syncthreads();
    }

    float* base = g_t + (size_t)d*NN;
    #pragma unroll
    for (int m = 0; m < 4; m++) {
        int r1 = i0 + m0 + m*16 + (lane >> 2);
        #pragma unroll
        for (int n = 0; n < 4; n++) {
            int c = j0 + n0 + n*8 + (lane & 3)*2;
            float2 lo = make_float2(acc[m][n][0], acc[m][n][1]);
            float2 hi = make_float2(acc[m][n][2], acc[m][n][3]);
            *(float2*)(base + (size_t)r1*NSEQ + c)       = lo;
            *(float2*)(base + (size_t)(r1+8)*NSEQ + c)   = hi;
        }
    }
}

// ============================================================================
// Kernel C (LN folded into epilogue) — unchanged from R11
// ============================================================================
__global__ void __launch_bounds__(256, 2) kC(
    const float* __restrict__ opb,
    float* __restrict__ out)
{
    extern __shared__ char smc[];
    const uint32_t sbase = smem_u32(smc);
    const uint32_t uTh  = sbase;
    const uint32_t uTl  = sbase + 16384;
    const uint32_t uWph = sbase + 32768;
    float* pS    = (float*)(smc + 65536);
    float* pQ    = (float*)(smc + 65536 + 4352);
    float* sMu   = (float*)(smc + 65536 + 8704);
    float* sRstd = (float*)(smc + 65536 + 8960);

    const int t    = threadIdx.x;
    const int lane = t & 31;
    const int wid  = t >> 5;
    const int r0   = blockIdx.x * 64;

    #pragma unroll
    for (int q = 0; q < 8; q++) {
        int seg = t + 256*q;
        int ch  = seg >> 4;
        int s8  = seg & 15;
        uint32_t dst = ((s8 >= 8) ? 16384u : 0u) + SW128((uint32_t)(ch*128 + (s8 & 7)*16));
        CP_ASYNC16(uWph + dst, g_oph + (size_t)ch*128 + s8*8);
    }
    CP_COMMIT();

    const int r4 = (t & 15) * 4;
    const int gg = t >> 4;
    float s0=0.f, s1=0.f, s2=0.f, s3=0.f;
    float q0=0.f, q1=0.f, q2=0.f, q3=0.f;
    #pragma unroll
    for (int q8 = 0; q8 < 8; q8++) {
        int dd = gg + 16*q8;
        float4 f = *(const float4*)(g_t + (size_t)dd*NN + r0 + r4);
        s0 += f.x; q0 += f.x*f.x;
        s1 += f.y; q1 += f.y*f.y;
        s2 += f.z; q2 += f.z*f.z;
        s3 += f.w; q3 += f.w*f.w;
        __half h0 = __float2half_rn(f.x), h1 = __float2half_rn(f.y);
        __half h2 = __float2half_rn(f.z), h3 = __float2half_rn(f.w);
        __half l0 = __float2half_rn(f.x - __half2float(h0));
        __half l1 = __float2half_rn(f.y - __half2float(h1));
        __half l2 = __float2half_rn(f.z - __half2float(h2));
        __half l3 = __float2half_rn(f.w - __half2float(h3));
        uint32_t off = SW128((uint32_t)(dd*128 + r4*2));
        __half2 hA = __halves2half2(h0, h1), hB = __halves2half2(h2, h3);
        __half2 lA = __halves2half2(l0, l1), lB = __halves2half2(l2, l3);
        *(__half2*)(smc + off)             = hA;
        *(__half2*)(smc + off + 4)         = hB;
        *(__half2*)(smc + 16384 + off)     = lA;
        *(__half2*)(smc + 16384 + off + 4) = lB;
    }
    pS[(r4+0)*17 + gg] = s0;  pQ[(r4+0)*17 + gg] = q0;
    pS[(r4+1)*17 + gg] = s1;  pQ[(r4+1)*17 + gg] = q1;
    pS[(r4+2)*17 + gg] = s2;  pQ[(r4+2)*17 + gg] = q2;
    pS[(r4+3)*17 + gg] = s3;  pQ[(r4+3)*17 + gg] = q3;
    __syncthreads();

    if (t < 64) {
        float s = 0.f, q = 0.f;
        #pragma unroll
        for (int g = 0; g < 16; g++) { s += pS[t*17 + g]; q += pQ[t*17 + g]; }
        float mu  = s * (1.0f/128.0f);
        float var = q * (1.0f/128.0f) - mu*mu;
        sMu[t]   = mu;
        sRstd[t] = rsqrtf(var + 1e-5f);
    }
    CP_WAIT(0);
    __syncthreads();

    const int bRow = (lane & 7) + ((lane >> 4) << 3);
    const int bK   = ((lane >> 3) & 1) * 16;
    const int m0   = (wid & 1) * 32;
    const int n0   = (wid >> 1) * 32;
    const int tD = (lane & 7) + ((lane & 16) >> 1);
    const int tR = ((lane >> 3) & 1) * 8;

    float acc[2][4][4];
    #pragma unroll
    for (int m = 0; m < 2; m++)
        #pragma unroll
        for (int n = 0; n < 4; n++)
            #pragma unroll
            for (int e = 0; e < 4; e++) acc[m][n][e] = 0.f;

    #pragma unroll
    for (int kk = 0; kk < 8; kk++) {
        const int d0 = kk * 16;
        const uint32_t halfW = (uint32_t)(kk >> 2) * 16384u;
        const uint32_t k32   = (uint32_t)(kk & 3) * 32u;

        uint32_t a2h[2][4], a2l[2][4];
        #pragma unroll
        for (int f = 0; f < 2; f++) {
            uint32_t off = SW128((uint32_t)((d0 + tD)*128 + (m0 + f*16 + tR)*2));
            ldm4t(uTh + off, a2h[f]);
            ldm4t(uTl + off, a2l[f]);
        }
        uint32_t ph[2][4];
        #pragma unroll
        for (int c = 0; c < 2; c++) {
            uint32_t off = SW128((uint32_t)((n0 + c*16 + bRow)*128) + k32 + bK);
            ldm4(uWph + halfW + off, ph[c]);
        }
        #pragma unroll
        for (int m = 0; m < 2; m++)
            #pragma unroll
            for (int n = 0; n < 4; n++) {
                int ci = n >> 1, bi = (n & 1) * 2;
                mma16816(acc[m][n], a2h[m], ph[ci][bi], ph[ci][bi+1]);
                mma16816(acc[m][n], a2l[m], ph[ci][bi], ph[ci][bi+1]);
            }
    }

    #pragma unroll
    for (int m = 0; m < 2; m++) {
        int row0 = m0 + m*16 + (lane >> 2);
        float mu0 = sMu[row0],   rs0 = sRstd[row0];
        float mu1 = sMu[row0+8], rs1 = sRstd[row0+8];
        #pragma unroll
        for (int n = 0; n < 4; n++) {
            int c0 = n0 + n*8 + (lane & 3)*2;
            float pb0 = __ldg(opb + c0),    pb1 = __ldg(opb + c0 + 1);
            float wb0 = __ldg(g_wbar + c0), wb1 = __ldg(g_wbar + c0 + 1);
            __half2 gv0 = *(const __half2*)(g_gate + (size_t)(r0 + row0)*DDIM + c0);
            __half2 gv1 = *(const __half2*)(g_gate + (size_t)(r0 + row0 + 8)*DDIM + c0);
            float2 g0 = __half22float2(gv0), g1 = __half22float2(gv1);
            float2 v0, v1;
            v0.x = g0.x * (rs0 * (acc[m][n][0] - mu0*wb0) + pb0);
            v0.y = g0.y * (rs0 * (acc[m][n][1] - mu0*wb1) + pb1);
            v1.x = g1.x * (rs1 * (acc[m][n][2] - mu1*wb0) + pb0);
            v1.y = g1.y * (rs1 * (acc[m][n][3] - mu1*wb1) + pb1);
            *(float2*)(out + (size_t)(r0 + row0)*DDIM + c0)     = v0;
            *(float2*)(out + (size_t)(r0 + row0 + 8)*DDIM + c0) = v1;
        }
    }
}

// ============================================================================
extern "C" void kernel_launch(void* const* d_in, const int* in_sizes, int n_in,
                              void* d_out, int out_size)
{
    const float* pair = (const float*)d_in[0];
    const float* mask = (const float*)d_in[1];
    const float* apw  = (const float*)d_in[2];
    const float* apb  = (const float*)d_in[3];
    const float* agw  = (const float*)d_in[4];
    const float* agb  = (const float*)d_in[5];
    const float* opw  = (const float*)d_in[6];
    const float* opb  = (const float*)d_in[7];
    const float* ogw  = (const float*)d_in[8];
    const float* ogb  = (const float*)d_in[9];
    float* out = (float*)d_out;

    const size_t smA = 98816;    // 96.5 KB -> 2 CTA/SM
    const size_t smB = 65536;    // 64 KB   -> 2 CTA/SM
    const size_t smC = 75264;    // ~73.5KB -> 2 CTA/SM
    cudaFuncSetAttribute(kA, cudaFuncAttributeMaxDynamicSharedMemorySize, (int)smA);
    cudaFuncSetAttribute(kB, cudaFuncAttributeMaxDynamicSharedMemorySize, (int)smB);
    cudaFuncSetAttribute(kC, cudaFuncAttributeMaxDynamicSharedMemorySize, (int)smC);

    kW<<<128, 256>>>(agw, apw, ogw, opw);
    kWb<<<1, 128>>>(opw);
    kA<<<NN/128, 256, smA>>>(pair, mask, apb, agb, ogb);
    kB<<<dim3(4, 4, DDIM), 256, smB>>>();
    kC<<<NN/64, 256, smC>>>(opb, out);
}